// round 2
// baseline (speedup 1.0000x reference)
#include <cuda_runtime.h>

// ---------------- problem constants ----------------
namespace {
constexpr int kD    = 1024;
constexpr int kHD   = 128;
constexpr int kEA   = 8;
constexpr int kEF   = 16;
constexpr int kFH   = 512;
constexpr int kMAXP = 64;
constexpr int kR    = 2 * kMAXP + 1;   // 129
constexpr int kB    = 4;
constexpr int kS    = 1024;
constexpr int kBS   = kB * kS;         // 4096
constexpr float kEPS = 1e-5f;
constexpr float kQScale = 0.08838834764831845f;   // 128^-0.5
}

// ---------------- device scratch (allocation-free) ----------------
__device__ float g_xn1 [kBS * kD];
__device__ float g_xn2 [kBS * kD];
__device__ float g_xcur[kBS * kD];
__device__ float g_kbuf[kBS * kHD];
__device__ float g_vbuf[kBS * kHD];
__device__ int   g_cntA [kB * kEA];
__device__ int   g_listA[kB * kEA * kS];
__device__ float g_gateA[kB * kEA * kS];
__device__ float g_qg  [(size_t)kB * kEA * kS * kHD];
__device__ float g_ctxg[(size_t)kB * kEA * kS * kHD];
__device__ int   g_cntF [kEF];
__device__ int   g_listF[kEF * kBS];
__device__ float g_gateF[kEF * kBS];
__device__ float g_hbuf[(size_t)kEF * kBS * kFH];   // routed FFN hidden

// ---------------- small utility kernels ----------------
__global__ void zero_cnts_kernel() {
    int i = threadIdx.x;
    if (i < kB * kEA) g_cntA[i] = 0;
    if (i < kEF)      g_cntF[i] = 0;
}

__global__ void copy_kernel(const float* __restrict__ in, float* __restrict__ out, int n) {
    int n4 = n >> 2;
    for (int i = blockIdx.x * blockDim.x + threadIdx.x; i < n4; i += gridDim.x * blockDim.x)
        ((float4*)out)[i] = ((const float4*)in)[i];
}

// ---------------- fused LayerNorm + top-2 router ----------------
// one block per token, 256 threads
template <int E>
__global__ __launch_bounds__(256)
void ln_gate_kernel(const float* __restrict__ x,
                    const float* __restrict__ w,
                    const float* __restrict__ bvec,
                    const float* __restrict__ gw,   // [D, E] row-major
                    float* __restrict__ xn,
                    int* __restrict__ cnt,
                    int* __restrict__ list,
                    float* __restrict__ gates,
                    int cap, int perBatch)
{
    __shared__ __align__(16) float xs[kD];
    __shared__ float red1[8], red2[8];
    __shared__ float logits[E];
    __shared__ float s_mu, s_rstd;

    int t    = blockIdx.x;
    int tid  = threadIdx.x;
    int lane = tid & 31, wid = tid >> 5;

    const float4* xin = (const float4*)(x + (size_t)t * kD);
    float4* xs4 = (float4*)xs;
    float s = 0.f, ss = 0.f;
    for (int i = tid; i < kD / 4; i += 256) {
        float4 v = xin[i];
        xs4[i] = v;
        s  += v.x + v.y + v.z + v.w;
        ss += v.x * v.x + v.y * v.y + v.z * v.z + v.w * v.w;
    }
    #pragma unroll
    for (int o = 16; o; o >>= 1) {
        s  += __shfl_xor_sync(~0u, s, o);
        ss += __shfl_xor_sync(~0u, ss, o);
    }
    if (lane == 0) { red1[wid] = s; red2[wid] = ss; }
    __syncthreads();
    if (tid == 0) {
        float S1 = 0.f, S2 = 0.f;
        #pragma unroll
        for (int i = 0; i < 8; i++) { S1 += red1[i]; S2 += red2[i]; }
        float mu  = S1 / kD;
        float var = S2 / kD - mu * mu;
        s_mu = mu; s_rstd = rsqrtf(var + kEPS);
    }
    __syncthreads();
    float mu = s_mu, rstd = s_rstd;
    for (int i = tid; i < kD; i += 256) {
        float v = (xs[i] - mu) * rstd * w[i] + bvec[i];
        xs[i] = v;
        xn[(size_t)t * kD + i] = v;
    }
    __syncthreads();

    // router logits (warp per expert)
    for (int e = wid; e < E; e += 8) {
        float acc = 0.f;
        for (int d = lane; d < kD; d += 32) acc += xs[d] * gw[d * E + e];
        #pragma unroll
        for (int o = 16; o; o >>= 1) acc += __shfl_xor_sync(~0u, acc, o);
        if (lane == 0) logits[e] = acc;
    }
    __syncthreads();

    if (tid == 0) {
        int e0 = 0; float v0 = logits[0];
        #pragma unroll
        for (int e = 1; e < E; e++) if (logits[e] > v0) { v0 = logits[e]; e0 = e; }
        int e1 = -1; float v1 = -3.4e38f;
        #pragma unroll
        for (int e = 0; e < E; e++) {
            if (e == e0) continue;
            if (logits[e] > v1) { v1 = logits[e]; e1 = e; }
        }
        float a1  = __expf(v1 - v0);
        float inv = 1.f / (1.f + a1);
        float g0 = inv, g1 = a1 * inv;     // softmax over [v0, v1]
        int bb = perBatch ? (t / kS) : 0;
        int grp0 = bb * E + e0;
        int p0 = atomicAdd(&cnt[grp0], 1);
        list[grp0 * cap + p0] = t; gates[grp0 * cap + p0] = g0;
        int grp1 = bb * E + e1;
        int p1 = atomicAdd(&cnt[grp1], 1);
        list[grp1 * cap + p1] = t; gates[grp1 * cap + p1] = g1;
    }
}

// ---------------- generic grouped GEMM ----------------
// out[row, col0:col0+64] = act( (A_row @ W_e[:, cols]) + bias_e ) * alpha
// GATHER_A : A row index comes from list (token id); else grouped rows g*cap+r (or dense)
// SCATTER  : atomicAdd into out[token, :] scaled by per-row gate
// BM=128, BN=64, BK=16, 256 threads, 8x4 microtile
template <bool GATHER_A, bool SCATTER, bool RELU>
__global__ __launch_bounds__(256)
void gemm_kernel(const float* __restrict__ A,
                 const float* __restrict__ W,      // per-expert stride K*N
                 const float* __restrict__ bias,   // per-expert stride N
                 float* __restrict__ out,
                 const int* __restrict__ list,
                 const float* __restrict__ gates,
                 const int* __restrict__ cnt,      // null -> dense (Mfixed)
                 int Mfixed, int N, int K, int cap, int wMod, float alpha)
{
    constexpr int BM = 128, BN = 64, BK = 16;
    int g = blockIdx.z;
    int M = cnt ? cnt[g] : Mfixed;
    int row0 = blockIdx.x * BM;
    if (row0 >= M) return;
    int col0 = blockIdx.y * BN;
    int e = g % wMod;
    const float* Wg = W    + (size_t)e * K * N;
    const float* bg = bias + (size_t)e * N;
    bool grouped = (cnt != nullptr);

    __shared__ __align__(16) float As[BK][BM];
    __shared__ __align__(16) float Bs[BK][BN];
    __shared__ int   rowTok[BM];
    __shared__ float rowG[BM];

    int tid = threadIdx.x;
    if (tid < BM) {
        int r = row0 + tid;
        int tok = 0; float gt = 0.f;
        if (r < M && list) { tok = list[g * cap + r]; gt = gates ? gates[g * cap + r] : 0.f; }
        rowTok[tid] = tok;
        rowG[tid]   = gt;
    }
    __syncthreads();

    float c[8][4];
    #pragma unroll
    for (int i = 0; i < 8; i++)
        #pragma unroll
        for (int j = 0; j < 4; j++) c[i][j] = 0.f;

    int ty = tid >> 4, tx = tid & 15;

    for (int k0 = 0; k0 < K; k0 += BK) {
        // A tile: 128 rows x 16 k  (512 float4 loads)
        #pragma unroll
        for (int i = 0; i < 2; i++) {
            int idx = tid + i * 256;
            int r = idx >> 2, kq = idx & 3;
            int gr = row0 + r;
            long ar;
            if (GATHER_A) ar = rowTok[r];
            else          ar = grouped ? (long)g * cap + gr : gr;
            float4 v = make_float4(0.f, 0.f, 0.f, 0.f);
            if (gr < M) v = *(const float4*)&A[(size_t)ar * K + k0 + kq * 4];
            As[kq * 4 + 0][r] = v.x;
            As[kq * 4 + 1][r] = v.y;
            As[kq * 4 + 2][r] = v.z;
            As[kq * 4 + 3][r] = v.w;
        }
        // B tile: 16 k x 64 n
        {
            int kk = tid >> 4, nq = tid & 15;
            float4 v = *(const float4*)&Wg[(size_t)(k0 + kk) * N + col0 + nq * 4];
            *(float4*)&Bs[kk][nq * 4] = v;
        }
        __syncthreads();
        #pragma unroll
        for (int kk = 0; kk < BK; kk++) {
            float4 a0 = *(const float4*)&As[kk][ty * 8];
            float4 a1 = *(const float4*)&As[kk][ty * 8 + 4];
            float4 b  = *(const float4*)&Bs[kk][tx * 4];
            float av[8] = {a0.x, a0.y, a0.z, a0.w, a1.x, a1.y, a1.z, a1.w};
            float bv[4] = {b.x, b.y, b.z, b.w};
            #pragma unroll
            for (int i = 0; i < 8; i++)
                #pragma unroll
                for (int j = 0; j < 4; j++) c[i][j] += av[i] * bv[j];
        }
        __syncthreads();
    }

    #pragma unroll
    for (int i = 0; i < 8; i++) {
        int r = ty * 8 + i;
        int gr = row0 + r;
        if (gr >= M) continue;
        #pragma unroll
        for (int j = 0; j < 4; j++) {
            int n = col0 + tx * 4 + j;
            float val = (c[i][j] + bg[n]) * alpha;
            if (RELU) val = fmaxf(val, 0.f);
            if (SCATTER) {
                atomicAdd(&out[(size_t)rowTok[r] * N + n], rowG[r] * val);
            } else {
                size_t orow = grouped ? (size_t)g * cap + gr : (size_t)gr;
                out[orow * N + n] = val;
            }
        }
    }
}

// ---------------- routed attention core ----------------
// grid: (B*EA, S/16), 256 threads; 16 queries/block, 16 threads/query owning 8 h-dims
__global__ __launch_bounds__(256)
void attn_kernel(const float* __restrict__ rel_table)
{
    constexpr int QT = 16, KT = 16, KPAD = 132;
    int g  = blockIdx.x;          // b*EA + e
    int b  = g / kEA;
    int qt = blockIdx.y;
    int cnt  = g_cntA[g];
    int base = qt * QT;
    if (base >= cnt) return;

    __shared__ __align__(16) float qs  [QT][kHD];
    __shared__ __align__(16) float relq[QT][KPAD];
    __shared__ __align__(16) float ks  [KT][KPAD];
    __shared__ __align__(16) float vs  [KT][KPAD];
    __shared__ float ps[QT][KT];
    __shared__ int   qpos[QT];

    int tid = threadIdx.x;

    // load Q tile (zero-padded past count)
    for (int i = tid; i < QT * kHD / 4; i += 256) {
        int qi = i / (kHD / 4), h4 = i % (kHD / 4);
        float4 v = make_float4(0.f, 0.f, 0.f, 0.f);
        if (base + qi < cnt)
            v = ((const float4*)&g_qg[((size_t)g * kS + base + qi) * kHD])[h4];
        ((float4*)&qs[qi][0])[h4] = v;
    }
    if (tid < QT) {
        int t = (base + tid < cnt) ? g_listA[g * kS + base + tid] : 0;
        qpos[tid] = t & (kS - 1);
    }
    __syncthreads();

    // rel bias table per query: relq[qi][r] = q_qi . rel_table[r]
    for (int idx = tid; idx < QT * kR; idx += 256) {
        int qi = idx / kR, r = idx % kR;
        const float4* q4 = (const float4*)&qs[qi][0];
        const float4* t4 = (const float4*)&rel_table[(size_t)r * kHD];
        float s = 0.f;
        #pragma unroll
        for (int h = 0; h < kHD / 4; h++) {
            float4 a = q4[h], c = t4[h];
            s += a.x * c.x + a.y * c.y + a.z * c.z + a.w * c.w;
        }
        relq[qi][r] = s;
    }
    __syncthreads();

    int qi = tid >> 4;
    int li = tid & 15;
    float m = -1e30f, l = 0.f;
    float acc[8];
    #pragma unroll
    for (int t = 0; t < 8; t++) acc[t] = 0.f;
    int myq = qpos[qi];
    const float4* q4 = (const float4*)&qs[qi][0];

    for (int c0 = 0; c0 < kS; c0 += KT) {
        for (int i = tid; i < KT * kHD / 4; i += 256) {
            int kk = i / (kHD / 4), h4 = i % (kHD / 4);
            size_t srcrow = ((size_t)b * kS + c0 + kk) * kHD;
            ((float4*)&ks[kk][0])[h4] = ((const float4*)&g_kbuf[srcrow])[h4];
            ((float4*)&vs[kk][0])[h4] = ((const float4*)&g_vbuf[srcrow])[h4];
        }
        __syncthreads();

        // score for key li
        const float4* k4 = (const float4*)&ks[li][0];
        float s = 0.f;
        #pragma unroll
        for (int h = 0; h < kHD / 4; h++) {
            float4 a = q4[h], kv = k4[h];
            s += a.x * kv.x + a.y * kv.y + a.z * kv.z + a.w * kv.w;
        }
        int rel = c0 + li - myq;
        rel = min(max(rel, -kMAXP), kMAXP) + kMAXP;
        s += relq[qi][rel];

        // online softmax within 16-lane group
        float cm = s;
        #pragma unroll
        for (int o = 8; o; o >>= 1) cm = fmaxf(cm, __shfl_xor_sync(~0u, cm, o));
        float mn = fmaxf(m, cm);
        float scale = __expf(m - mn);
        float p = __expf(s - mn);
        float psum = p;
        #pragma unroll
        for (int o = 8; o; o >>= 1) psum += __shfl_xor_sync(~0u, psum, o);
        l = l * scale + psum;
        m = mn;
        ps[qi][li] = p;
        __syncwarp();

        #pragma unroll
        for (int t = 0; t < 8; t++) acc[t] *= scale;
        #pragma unroll
        for (int kk = 0; kk < KT; kk++) {
            float pv = ps[qi][kk];
            const float4* v4 = (const float4*)&vs[kk][li * 8];
            float4 va = v4[0], vb = v4[1];
            acc[0] += pv * va.x; acc[1] += pv * va.y;
            acc[2] += pv * va.z; acc[3] += pv * va.w;
            acc[4] += pv * vb.x; acc[5] += pv * vb.y;
            acc[6] += pv * vb.z; acc[7] += pv * vb.w;
        }
        __syncthreads();
    }

    if (base + qi < cnt) {
        float inv = 1.f / l;
        float* dst = &g_ctxg[((size_t)g * kS + base + qi) * kHD + li * 8];
        #pragma unroll
        for (int t = 0; t < 8; t++) dst[t] = acc[t] * inv;
    }
}

// ---------------- launch ----------------
extern "C" void kernel_launch(void* const* d_in, const int* in_sizes, int n_in,
                              void* d_out, int out_size)
{
    const float* src   = (const float*)d_in[0];
    const float* ln1_w = (const float*)d_in[1];
    const float* ln1_b = (const float*)d_in[2];
    const float* ln2_w = (const float*)d_in[3];
    const float* ln2_b = (const float*)d_in[4];
    const float* agw   = (const float*)d_in[5];
    const float* q_w   = (const float*)d_in[6];
    const float* q_b   = (const float*)d_in[7];
    const float* k_w   = (const float*)d_in[8];
    const float* k_b   = (const float*)d_in[9];
    const float* v_w   = (const float*)d_in[10];
    const float* v_b   = (const float*)d_in[11];
    const float* o_w   = (const float*)d_in[12];
    const float* o_b   = (const float*)d_in[13];
    const float* rel   = (const float*)d_in[14];
    const float* fgw   = (const float*)d_in[15];
    const float* w1    = (const float*)d_in[16];
    const float* b1    = (const float*)d_in[17];
    const float* w2    = (const float*)d_in[18];
    const float* b2    = (const float*)d_in[19];
    float* out = (float*)d_out;

    float *xn1, *xn2, *xcur, *kb, *vb, *qg, *ctxg, *hb, *gateA, *gateF;
    int *cntA, *listA, *cntF, *listF;
    cudaGetSymbolAddress((void**)&xn1,   g_xn1);
    cudaGetSymbolAddress((void**)&xn2,   g_xn2);
    cudaGetSymbolAddress((void**)&xcur,  g_xcur);
    cudaGetSymbolAddress((void**)&kb,    g_kbuf);
    cudaGetSymbolAddress((void**)&vb,    g_vbuf);
    cudaGetSymbolAddress((void**)&qg,    g_qg);
    cudaGetSymbolAddress((void**)&ctxg,  g_ctxg);
    cudaGetSymbolAddress((void**)&hb,    g_hbuf);
    cudaGetSymbolAddress((void**)&gateA, g_gateA);
    cudaGetSymbolAddress((void**)&gateF, g_gateF);
    cudaGetSymbolAddress((void**)&cntA,  g_cntA);
    cudaGetSymbolAddress((void**)&listA, g_listA);
    cudaGetSymbolAddress((void**)&cntF,  g_cntF);
    cudaGetSymbolAddress((void**)&listF, g_listF);

    zero_cnts_kernel<<<1, 64>>>();

    // LN1 + attention router (per-batch, per-expert lists)
    ln_gate_kernel<kEA><<<kBS, 256>>>(src, ln1_w, ln1_b, agw, xn1,
                                      cntA, listA, gateA, kS, 1);

    // shared k / v projections (dense GEMMs)
    dim3 gkv(kBS / 128, kHD / 64, 1);
    gemm_kernel<false, false, false><<<gkv, 256>>>(xn1, k_w, k_b, kb,
        nullptr, nullptr, nullptr, kBS, kHD, kD, 0, 1, 1.f);
    gemm_kernel<false, false, false><<<gkv, 256>>>(xn1, v_w, v_b, vb,
        nullptr, nullptr, nullptr, kBS, kHD, kD, 0, 1, 1.f);

    // routed q projection (gather tokens per (b,e) group)
    dim3 gq(kS / 128, kHD / 64, kB * kEA);
    gemm_kernel<true, false, false><<<gq, 256>>>(xn1, q_w, q_b, qg,
        listA, gateA, cntA, 0, kHD, kD, kS, kEA, kQScale);

    // attention core (flash-style, rel-pos bias)
    attn_kernel<<<dim3(kB * kEA, kS / 16), 256>>>(rel);

    // residual base x = src
    copy_kernel<<<512, 256>>>(src, xcur, kBS * kD);

    // routed output projection, gated atomic accumulate into x
    dim3 go(kS / 128, kD / 64, kB * kEA);
    gemm_kernel<false, true, false><<<go, 256>>>(ctxg, o_w, o_b, xcur,
        listA, gateA, cntA, 0, kD, kHD, kS, kEA, 1.f);

    // LN2 + FFN router (global per-expert lists)
    ln_gate_kernel<kEF><<<kBS, 256>>>(xcur, ln2_w, ln2_b, fgw, xn2,
                                      cntF, listF, gateF, kBS, 0);

    // routed FFN up-proj + relu
    dim3 gf1(kBS / 128, kFH / 64, kEF);
    gemm_kernel<true, false, true><<<gf1, 256>>>(xn2, w1, b1, hb,
        listF, gateF, cntF, 0, kFH, kD, kBS, kEF, 1.f);

    // residual base for output
    copy_kernel<<<512, 256>>>(xcur, out, kBS * kD);

    // routed FFN down-proj, gated atomic accumulate into out
    dim3 gf2(kBS / 128, kD / 64, kEF);
    gemm_kernel<false, true, false><<<gf2, 256>>>(hb, w2, b2, out,
        listF, gateF, cntF, 0, kD, kFH, kBS, kEF, 1.f);
}

// round 4
// speedup vs baseline: 1.1451x; 1.1451x over previous
#include <cuda_runtime.h>

// ---------------- problem constants ----------------
namespace {
constexpr int kD    = 1024;
constexpr int kHD   = 128;
constexpr int kEA   = 8;
constexpr int kEF   = 16;
constexpr int kFH   = 512;
constexpr int kMAXP = 64;
constexpr int kR    = 2 * kMAXP + 1;   // 129
constexpr int kB    = 4;
constexpr int kS    = 1024;
constexpr int kBS   = kB * kS;         // 4096
constexpr float kEPS = 1e-5f;
constexpr float kQScale = 0.08838834764831845f;   // 128^-0.5
}

typedef unsigned long long ull;

// ---------------- device scratch (allocation-free) ----------------
__device__ float g_xn1 [kBS * kD];
__device__ float g_xn2 [kBS * kD];
__device__ float g_xcur[kBS * kD];
__device__ float g_kbuf[kBS * kHD];
__device__ float g_vbuf[kBS * kHD];
__device__ int   g_cntA [kB * kEA];
__device__ int   g_listA[kB * kEA * kS];
__device__ float g_gateA[kB * kEA * kS];
__device__ float g_qg  [(size_t)kB * kEA * kS * kHD];
__device__ float g_ctxg[(size_t)kB * kEA * kS * kHD];
__device__ int   g_cntF [kEF];
__device__ int   g_listF[kEF * kBS];
__device__ float g_gateF[kEF * kBS];
__device__ float g_hbuf[(size_t)kEF * kBS * kFH];   // routed FFN hidden

// ---------------- small utility kernels ----------------
__global__ void zero_cnts_kernel() {
    int i = threadIdx.x;
    if (i < kB * kEA) g_cntA[i] = 0;
    if (i < kEF)      g_cntF[i] = 0;
}

__global__ void copy_kernel(const float* __restrict__ in, float* __restrict__ out, int n) {
    int n4 = n >> 2;
    for (int i = blockIdx.x * blockDim.x + threadIdx.x; i < n4; i += gridDim.x * blockDim.x)
        ((float4*)out)[i] = ((const float4*)in)[i];
}

// ---------------- fused LayerNorm + top-2 router ----------------
template <int E>
__global__ __launch_bounds__(256)
void ln_gate_kernel(const float* __restrict__ x,
                    const float* __restrict__ w,
                    const float* __restrict__ bvec,
                    const float* __restrict__ gw,   // [D, E] row-major
                    float* __restrict__ xn,
                    int* __restrict__ cnt,
                    int* __restrict__ list,
                    float* __restrict__ gates,
                    int cap, int perBatch)
{
    __shared__ __align__(16) float xs[kD];
    __shared__ float red1[8], red2[8];
    __shared__ float logits[E];
    __shared__ float s_mu, s_rstd;

    int t    = blockIdx.x;
    int tid  = threadIdx.x;
    int lane = tid & 31, wid = tid >> 5;

    const float4* xin = (const float4*)(x + (size_t)t * kD);
    float4* xs4 = (float4*)xs;
    float s = 0.f, ss = 0.f;
    for (int i = tid; i < kD / 4; i += 256) {
        float4 v = xin[i];
        xs4[i] = v;
        s  += v.x + v.y + v.z + v.w;
        ss += v.x * v.x + v.y * v.y + v.z * v.z + v.w * v.w;
    }
    #pragma unroll
    for (int o = 16; o; o >>= 1) {
        s  += __shfl_xor_sync(~0u, s, o);
        ss += __shfl_xor_sync(~0u, ss, o);
    }
    if (lane == 0) { red1[wid] = s; red2[wid] = ss; }
    __syncthreads();
    if (tid == 0) {
        float S1 = 0.f, S2 = 0.f;
        #pragma unroll
        for (int i = 0; i < 8; i++) { S1 += red1[i]; S2 += red2[i]; }
        float mu  = S1 / kD;
        float var = S2 / kD - mu * mu;
        s_mu = mu; s_rstd = rsqrtf(var + kEPS);
    }
    __syncthreads();
    float mu = s_mu, rstd = s_rstd;
    for (int i = tid; i < kD; i += 256) {
        float v = (xs[i] - mu) * rstd * w[i] + bvec[i];
        xs[i] = v;
        xn[(size_t)t * kD + i] = v;
    }
    __syncthreads();

    for (int e = wid; e < E; e += 8) {
        float acc = 0.f;
        for (int d = lane; d < kD; d += 32) acc += xs[d] * gw[d * E + e];
        #pragma unroll
        for (int o = 16; o; o >>= 1) acc += __shfl_xor_sync(~0u, acc, o);
        if (lane == 0) logits[e] = acc;
    }
    __syncthreads();

    if (tid == 0) {
        int e0 = 0; float v0 = logits[0];
        #pragma unroll
        for (int e = 1; e < E; e++) if (logits[e] > v0) { v0 = logits[e]; e0 = e; }
        int e1 = -1; float v1 = -3.4e38f;
        #pragma unroll
        for (int e = 0; e < E; e++) {
            if (e == e0) continue;
            if (logits[e] > v1) { v1 = logits[e]; e1 = e; }
        }
        float a1  = __expf(v1 - v0);
        float inv = 1.f / (1.f + a1);
        float g0 = inv, g1 = a1 * inv;
        int bb = perBatch ? (t / kS) : 0;
        int grp0 = bb * E + e0;
        int p0 = atomicAdd(&cnt[grp0], 1);
        list[grp0 * cap + p0] = t; gates[grp0 * cap + p0] = g0;
        int grp1 = bb * E + e1;
        int p1 = atomicAdd(&cnt[grp1], 1);
        list[grp1 * cap + p1] = t; gates[grp1 * cap + p1] = g1;
    }
}

// ---------------- packed f32x2 helpers ----------------
__device__ __forceinline__ void fma2(ull& d, ull a, ull b) {
    asm("fma.rn.f32x2 %0, %1, %2, %0;" : "+l"(d) : "l"(a), "l"(b));
}
__device__ __forceinline__ ull pack_dup(float a) {
    ull r;
    asm("mov.b64 %0, {%1, %1};" : "=l"(r) : "f"(a));
    return r;
}
__device__ __forceinline__ float2 unpack2(ull v) {
    float2 r;
    asm("mov.b64 {%0, %1}, %2;" : "=f"(r.x), "=f"(r.y) : "l"(v));
    return r;
}

// ---------------- grouped GEMM, f32x2 double-buffered ----------------
// BN = 128 fixed, BK = 16, 256 threads as 16(ty) x 16(tx).
// Thread owns rows {2ty + 32s + h} and col-pairs {2tx + 32j} (conflict-free LDS).
// GATHER_A : A row index = list token; grouped else rows g*cap+r; dense rows r.
// SCATTER  : atomicAdd into out[token,:] scaled by per-row gate.
// Dual dense mode: when cnt==null and W2!=null, blockIdx.z==1 uses W2/b2/out2.
template <int BM, bool GATHER_A, bool SCATTER, bool RELU>
__global__ __launch_bounds__(256)
void gemm2_kernel(const float* __restrict__ A,
                  const float* __restrict__ W,
                  const float* __restrict__ bias,
                  float* __restrict__ out,
                  const float* __restrict__ W2,
                  const float* __restrict__ bias2,
                  float* __restrict__ out2,
                  const int* __restrict__ list,
                  const float* __restrict__ gates,
                  const int* __restrict__ cnt,
                  int Mfixed, int N, int K, int cap, int wMod, float alpha)
{
    constexpr int BN = 128, BK = 16;
    constexpr int MR = BM / 16;      // rows per thread (8 or 4)
    constexpr int PR = MR / 2;       // row pairs per thread
    constexpr int AITER = BM * BK / (4 * 256);   // float4 A loads per thread

    int g = blockIdx.z;
    int M;
    const float* Wg; const float* bg; float* og;
    bool grouped = (cnt != nullptr);
    if (grouped) {
        M = cnt[g];
        int e = g % wMod;
        Wg = W    + (size_t)e * K * N;
        bg = bias + (size_t)e * N;
        og = out;
    } else {
        M = Mfixed;
        if (W2 != nullptr && g == 1) { Wg = W2; bg = bias2; og = out2; }
        else                         { Wg = W;  bg = bias;  og = out;  }
    }
    int row0 = blockIdx.x * BM;
    if (row0 >= M) return;
    int col0 = blockIdx.y * BN;

    __shared__ __align__(16) float As[2][BK][BM];
    __shared__ __align__(16) float Bs[2][BK][BN];
    __shared__ int   rowTok[BM];
    __shared__ float rowG[BM];

    int tid = threadIdx.x;
    int tx = tid & 15, ty = tid >> 4;

    if (tid < BM) {
        int r = row0 + tid;
        int tok = 0; float gt = 0.f;
        if (r < M && list) { tok = list[(size_t)g * cap + r]; gt = gates[(size_t)g * cap + r]; }
        rowTok[tid] = tok;
        rowG[tid]   = gt;
    }
    __syncthreads();

    ull acc[MR][4];
    #pragma unroll
    for (int i = 0; i < MR; i++)
        #pragma unroll
        for (int j = 0; j < 4; j++) acc[i][j] = 0ull;

    float4 aR[AITER], bR[2];
    int T = K / BK;

    // ---- tile loaders (gmem -> regs) ----
    auto loadTile = [&](int t) {
        int k0 = t * BK;
        #pragma unroll
        for (int i = 0; i < AITER; i++) {
            int idx = tid + 256 * i;
            int r   = idx & (BM - 1);
            int kq  = idx / BM;          // 0..3
            int gr  = row0 + r;
            float4 v = make_float4(0.f, 0.f, 0.f, 0.f);
            if (gr < M) {
                size_t ar;
                if (GATHER_A)     ar = (size_t)rowTok[r];
                else if (grouped) ar = (size_t)g * cap + gr;
                else              ar = (size_t)gr;
                v = *(const float4*)&A[ar * K + k0 + kq * 4];
            }
            aR[i] = v;
        }
        #pragma unroll
        for (int i = 0; i < 2; i++) {
            int idx = tid + 256 * i;
            int kk  = idx >> 5;
            int c4  = idx & 31;
            bR[i] = *(const float4*)&Wg[(size_t)(k0 + kk) * N + col0 + c4 * 4];
        }
    };
    auto stsTile = [&](int buf) {
        #pragma unroll
        for (int i = 0; i < AITER; i++) {
            int idx = tid + 256 * i;
            int r   = idx & (BM - 1);
            int kq  = idx / BM;
            As[buf][kq * 4 + 0][r] = aR[i].x;
            As[buf][kq * 4 + 1][r] = aR[i].y;
            As[buf][kq * 4 + 2][r] = aR[i].z;
            As[buf][kq * 4 + 3][r] = aR[i].w;
        }
        #pragma unroll
        for (int i = 0; i < 2; i++) {
            int idx = tid + 256 * i;
            int kk  = idx >> 5;
            int c4  = idx & 31;
            *(float4*)&Bs[buf][kk][c4 * 4] = bR[i];
        }
    };

    loadTile(0);
    stsTile(0);
    __syncthreads();

    for (int t = 0; t < T; t++) {
        if (t + 1 < T) loadTile(t + 1);
        int buf = t & 1;
        #pragma unroll
        for (int kk = 0; kk < BK; kk++) {
            float2 av[PR];
            #pragma unroll
            for (int s = 0; s < PR; s++)
                av[s] = *(const float2*)&As[buf][kk][ty * 2 + 32 * s];
            ull bv[4];
            #pragma unroll
            for (int j = 0; j < 4; j++)
                bv[j] = *(const ull*)&Bs[buf][kk][tx * 2 + 32 * j];
            #pragma unroll
            for (int s = 0; s < PR; s++) {
                ull ap0 = pack_dup(av[s].x);
                ull ap1 = pack_dup(av[s].y);
                #pragma unroll
                for (int j = 0; j < 4; j++) fma2(acc[s * 2 + 0][j], ap0, bv[j]);
                #pragma unroll
                for (int j = 0; j < 4; j++) fma2(acc[s * 2 + 1][j], ap1, bv[j]);
            }
        }
        if (t + 1 < T) stsTile((t + 1) & 1);
        __syncthreads();
    }

    // ---- epilogue ----
    #pragma unroll
    for (int s = 0; s < PR; s++) {
        #pragma unroll
        for (int h = 0; h < 2; h++) {
            int r  = ty * 2 + 32 * s + h;
            int gr = row0 + r;
            if (gr >= M) continue;
            #pragma unroll
            for (int j = 0; j < 4; j++) {
                int n0 = col0 + tx * 2 + 32 * j;
                float2 v = unpack2(acc[s * 2 + h][j]);
                v.x = (v.x + bg[n0])     * alpha;
                v.y = (v.y + bg[n0 + 1]) * alpha;
                if (RELU) { v.x = fmaxf(v.x, 0.f); v.y = fmaxf(v.y, 0.f); }
                if (SCATTER) {
                    float gt = rowG[r];
                    float* dst = &og[(size_t)rowTok[r] * N + n0];
                    atomicAdd(dst,     gt * v.x);
                    atomicAdd(dst + 1, gt * v.y);
                } else {
                    size_t orow = grouped ? (size_t)g * cap + gr : (size_t)gr;
                    *(float2*)&og[orow * N + n0] = v;
                }
            }
        }
    }
}

// ---------------- routed attention core ----------------
__global__ __launch_bounds__(256)
void attn_kernel(const float* __restrict__ rel_table)
{
    constexpr int QT = 16, KT = 16, KPAD = 132;
    int g  = blockIdx.x;          // b*EA + e
    int b  = g / kEA;
    int qt = blockIdx.y;
    int cnt  = g_cntA[g];
    int base = qt * QT;
    if (base >= cnt) return;

    __shared__ __align__(16) float qs  [QT][kHD];
    __shared__ __align__(16) float relq[QT][KPAD];
    __shared__ __align__(16) float ks  [KT][KPAD];
    __shared__ __align__(16) float vs  [KT][KPAD];
    __shared__ float ps[QT][KT];
    __shared__ int   qpos[QT];

    int tid = threadIdx.x;

    for (int i = tid; i < QT * kHD / 4; i += 256) {
        int qi = i / (kHD / 4), h4 = i % (kHD / 4);
        float4 v = make_float4(0.f, 0.f, 0.f, 0.f);
        if (base + qi < cnt)
            v = ((const float4*)&g_qg[((size_t)g * kS + base + qi) * kHD])[h4];
        ((float4*)&qs[qi][0])[h4] = v;
    }
    if (tid < QT) {
        int t = (base + tid < cnt) ? g_listA[g * kS + base + tid] : 0;
        qpos[tid] = t & (kS - 1);
    }
    __syncthreads();

    for (int idx = tid; idx < QT * kR; idx += 256) {
        int qi = idx / kR, r = idx % kR;
        const float4* q4 = (const float4*)&qs[qi][0];
        const float4* t4 = (const float4*)&rel_table[(size_t)r * kHD];
        float s = 0.f;
        #pragma unroll
        for (int h = 0; h < kHD / 4; h++) {
            float4 a = q4[h], c = t4[h];
            s += a.x * c.x + a.y * c.y + a.z * c.z + a.w * c.w;
        }
        relq[qi][r] = s;
    }
    __syncthreads();

    int qi = tid >> 4;
    int li = tid & 15;
    float m = -1e30f, l = 0.f;
    float acc[8];
    #pragma unroll
    for (int t = 0; t < 8; t++) acc[t] = 0.f;
    int myq = qpos[qi];
    const float4* q4 = (const float4*)&qs[qi][0];

    for (int c0 = 0; c0 < kS; c0 += KT) {
        for (int i = tid; i < KT * kHD / 4; i += 256) {
            int kk = i / (kHD / 4), h4 = i % (kHD / 4);
            size_t srcrow = ((size_t)b * kS + c0 + kk) * kHD;
            ((float4*)&ks[kk][0])[h4] = ((const float4*)&g_kbuf[srcrow])[h4];
            ((float4*)&vs[kk][0])[h4] = ((const float4*)&g_vbuf[srcrow])[h4];
        }
        __syncthreads();

        const float4* k4 = (const float4*)&ks[li][0];
        float s = 0.f;
        #pragma unroll
        for (int h = 0; h < kHD / 4; h++) {
            float4 a = q4[h], kv = k4[h];
            s += a.x * kv.x + a.y * kv.y + a.z * kv.z + a.w * kv.w;
        }
        int rel = c0 + li - myq;
        rel = min(max(rel, -kMAXP), kMAXP) + kMAXP;
        s += relq[qi][rel];

        float cm = s;
        #pragma unroll
        for (int o = 8; o; o >>= 1) cm = fmaxf(cm, __shfl_xor_sync(~0u, cm, o));
        float mn = fmaxf(m, cm);
        float scale = __expf(m - mn);
        float p = __expf(s - mn);
        float psum = p;
        #pragma unroll
        for (int o = 8; o; o >>= 1) psum += __shfl_xor_sync(~0u, psum, o);
        l = l * scale + psum;
        m = mn;
        ps[qi][li] = p;
        __syncwarp();

        #pragma unroll
        for (int t = 0; t < 8; t++) acc[t] *= scale;
        #pragma unroll
        for (int kk = 0; kk < KT; kk++) {
            float pv = ps[qi][kk];
            const float4* v4 = (const float4*)&vs[kk][li * 8];
            float4 va = v4[0], vb = v4[1];
            acc[0] += pv * va.x; acc[1] += pv * va.y;
            acc[2] += pv * va.z; acc[3] += pv * va.w;
            acc[4] += pv * vb.x; acc[5] += pv * vb.y;
            acc[6] += pv * vb.z; acc[7] += pv * vb.w;
        }
        __syncthreads();
    }

    if (base + qi < cnt) {
        float inv = 1.f / l;
        float* dst = &g_ctxg[((size_t)g * kS + base + qi) * kHD + li * 8];
        #pragma unroll
        for (int t = 0; t < 8; t++) dst[t] = acc[t] * inv;
    }
}

// ---------------- launch ----------------
extern "C" void kernel_launch(void* const* d_in, const int* in_sizes, int n_in,
                              void* d_out, int out_size)
{
    const float* src   = (const float*)d_in[0];
    const float* ln1_w = (const float*)d_in[1];
    const float* ln1_b = (const float*)d_in[2];
    const float* ln2_w = (const float*)d_in[3];
    const float* ln2_b = (const float*)d_in[4];
    const float* agw   = (const float*)d_in[5];
    const float* q_w   = (const float*)d_in[6];
    const float* q_b   = (const float*)d_in[7];
    const float* k_w   = (const float*)d_in[8];
    const float* k_b   = (const float*)d_in[9];
    const float* v_w   = (const float*)d_in[10];
    const float* v_b   = (const float*)d_in[11];
    const float* o_w   = (const float*)d_in[12];
    const float* o_b   = (const float*)d_in[13];
    const float* rel   = (const float*)d_in[14];
    const float* fgw   = (const float*)d_in[15];
    const float* w1    = (const float*)d_in[16];
    const float* b1    = (const float*)d_in[17];
    const float* w2    = (const float*)d_in[18];
    const float* b2    = (const float*)d_in[19];
    float* out = (float*)d_out;

    float *xn1, *xn2, *xcur, *kb, *vb, *qg, *ctxg, *hb, *gateA, *gateF;
    int *cntA, *listA, *cntF, *listF;
    cudaGetSymbolAddress((void**)&xn1,   g_xn1);
    cudaGetSymbolAddress((void**)&xn2,   g_xn2);
    cudaGetSymbolAddress((void**)&xcur,  g_xcur);
    cudaGetSymbolAddress((void**)&kb,    g_kbuf);
    cudaGetSymbolAddress((void**)&vb,    g_vbuf);
    cudaGetSymbolAddress((void**)&qg,    g_qg);
    cudaGetSymbolAddress((void**)&ctxg,  g_ctxg);
    cudaGetSymbolAddress((void**)&hb,    g_hbuf);
    cudaGetSymbolAddress((void**)&gateA, g_gateA);
    cudaGetSymbolAddress((void**)&gateF, g_gateF);
    cudaGetSymbolAddress((void**)&cntA,  g_cntA);
    cudaGetSymbolAddress((void**)&listA, g_listA);
    cudaGetSymbolAddress((void**)&cntF,  g_cntF);
    cudaGetSymbolAddress((void**)&listF, g_listF);

    zero_cnts_kernel<<<1, 64>>>();

    // LN1 + attention router
    ln_gate_kernel<kEA><<<kBS, 256>>>(src, ln1_w, ln1_b, agw, xn1,
                                      cntA, listA, gateA, kS, 1);

    // shared k + v projections fused (dual dense, BM=64 -> 128 CTAs)
    gemm2_kernel<64, false, false, false><<<dim3(kBS / 64, 1, 2), 256>>>(
        xn1, k_w, k_b, kb, v_w, v_b, vb,
        nullptr, nullptr, nullptr, kBS, kHD, kD, 0, 1, 1.f);

    // routed q projection (gather per (b,e) group)
    gemm2_kernel<128, true, false, false><<<dim3(kS / 128, 1, kB * kEA), 256>>>(
        xn1, q_w, q_b, qg, nullptr, nullptr, nullptr,
        listA, gateA, cntA, 0, kHD, kD, kS, kEA, kQScale);

    // attention core
    attn_kernel<<<dim3(kB * kEA, kS / 16), 256>>>(rel);

    // residual base x = src
    copy_kernel<<<512, 256>>>(src, xcur, kBS * kD);

    // routed output projection, gated atomic accumulate into x
    gemm2_kernel<128, false, true, false><<<dim3(kS / 128, kD / 128, kB * kEA), 256>>>(
        ctxg, o_w, o_b, xcur, nullptr, nullptr, nullptr,
        listA, gateA, cntA, 0, kD, kHD, kS, kEA, 1.f);

    // LN2 + FFN router
    ln_gate_kernel<kEF><<<kBS, 256>>>(xcur, ln2_w, ln2_b, fgw, xn2,
                                      cntF, listF, gateF, kBS, 0);

    // routed FFN up-proj + relu
    gemm2_kernel<128, true, false, true><<<dim3(kBS / 128, kFH / 128, kEF), 256>>>(
        xn2, w1, b1, hb, nullptr, nullptr, nullptr,
        listF, gateF, cntF, 0, kFH, kD, kBS, kEF, 1.f);

    // residual base for output
    copy_kernel<<<512, 256>>>(xcur, out, kBS * kD);

    // routed FFN down-proj, gated atomic accumulate into out
    gemm2_kernel<128, false, true, false><<<dim3(kBS / 128, kD / 128, kEF), 256>>>(
        hb, w2, b2, out, nullptr, nullptr, nullptr,
        listF, gateF, cntF, 0, kD, kFH, kBS, kEF, 1.f);
}

// round 7
// speedup vs baseline: 1.2545x; 1.0956x over previous
#include <cuda_runtime.h>

// ---------------- problem constants ----------------
namespace {
constexpr int kD    = 1024;
constexpr int kHD   = 128;
constexpr int kEA   = 8;
constexpr int kEF   = 16;
constexpr int kFH   = 512;
constexpr int kMAXP = 64;
constexpr int kR    = 2 * kMAXP + 1;   // 129
constexpr int kB    = 4;
constexpr int kS    = 1024;
constexpr int kBS   = kB * kS;         // 4096
constexpr float kEPS = 1e-5f;
constexpr float kQScale = 0.08838834764831845f;   // 128^-0.5
}

typedef unsigned long long ull;

// ---------------- device scratch (allocation-free) ----------------
__device__ float g_xn1 [kBS * kD];
__device__ float g_xn2 [kBS * kD];
__device__ float g_xcur[kBS * kD];
__device__ float g_kbuf[kBS * kHD];
__device__ float g_vbuf[kBS * kHD];
__device__ int   g_cntA [kB * kEA];
__device__ int   g_listA[kB * kEA * kS];
__device__ float g_gateA[kB * kEA * kS];
__device__ float g_qg  [(size_t)kB * kEA * kS * kHD];
__device__ float g_ctxg[(size_t)kB * kEA * kS * kHD];
__device__ int   g_cntF [kEF];
__device__ int   g_listF[kEF * kBS];
__device__ float g_gateF[kEF * kBS];
__device__ float g_hbuf[(size_t)kEF * kBS * kFH];   // routed FFN hidden

// ---------------- small utility kernels ----------------
__global__ void zero_cnts_kernel() {
    int i = threadIdx.x;
    if (i < kB * kEA) g_cntA[i] = 0;
    if (i < kEF)      g_cntF[i] = 0;
}

__global__ void zero_f_kernel(float* __restrict__ p, int n) {
    int n4 = n >> 2;
    float4 z = make_float4(0.f, 0.f, 0.f, 0.f);
    for (int i = blockIdx.x * blockDim.x + threadIdx.x; i < n4; i += gridDim.x * blockDim.x)
        ((float4*)p)[i] = z;
}

__global__ void copy_kernel(const float* __restrict__ in, float* __restrict__ out, int n) {
    int n4 = n >> 2;
    for (int i = blockIdx.x * blockDim.x + threadIdx.x; i < n4; i += gridDim.x * blockDim.x)
        ((float4*)out)[i] = ((const float4*)in)[i];
}

// ---------------- fused LayerNorm + top-2 router ----------------
template <int E>
__global__ __launch_bounds__(256)
void ln_gate_kernel(const float* __restrict__ x,
                    const float* __restrict__ w,
                    const float* __restrict__ bvec,
                    const float* __restrict__ gw,   // [D, E] row-major
                    float* __restrict__ xn,
                    int* __restrict__ cnt,
                    int* __restrict__ list,
                    float* __restrict__ gates,
                    int cap, int perBatch)
{
    __shared__ __align__(16) float xs[kD];
    __shared__ float red1[8], red2[8];
    __shared__ float logits[E];
    __shared__ float s_mu, s_rstd;

    int t    = blockIdx.x;
    int tid  = threadIdx.x;
    int lane = tid & 31, wid = tid >> 5;

    const float4* xin = (const float4*)(x + (size_t)t * kD);
    float4* xs4 = (float4*)xs;
    float s = 0.f, ss = 0.f;
    for (int i = tid; i < kD / 4; i += 256) {
        float4 v = xin[i];
        xs4[i] = v;
        s  += v.x + v.y + v.z + v.w;
        ss += v.x * v.x + v.y * v.y + v.z * v.z + v.w * v.w;
    }
    #pragma unroll
    for (int o = 16; o; o >>= 1) {
        s  += __shfl_xor_sync(~0u, s, o);
        ss += __shfl_xor_sync(~0u, ss, o);
    }
    if (lane == 0) { red1[wid] = s; red2[wid] = ss; }
    __syncthreads();
    if (tid == 0) {
        float S1 = 0.f, S2 = 0.f;
        #pragma unroll
        for (int i = 0; i < 8; i++) { S1 += red1[i]; S2 += red2[i]; }
        float mu  = S1 / kD;
        float var = S2 / kD - mu * mu;
        s_mu = mu; s_rstd = rsqrtf(var + kEPS);
    }
    __syncthreads();
    float mu = s_mu, rstd = s_rstd;
    for (int i = tid; i < kD; i += 256) {
        float v = (xs[i] - mu) * rstd * w[i] + bvec[i];
        xs[i] = v;
        xn[(size_t)t * kD + i] = v;
    }
    __syncthreads();

    for (int e = wid; e < E; e += 8) {
        float acc = 0.f;
        for (int d = lane; d < kD; d += 32) acc += xs[d] * gw[d * E + e];
        #pragma unroll
        for (int o = 16; o; o >>= 1) acc += __shfl_xor_sync(~0u, acc, o);
        if (lane == 0) logits[e] = acc;
    }
    __syncthreads();

    if (tid == 0) {
        int e0 = 0; float v0 = logits[0];
        #pragma unroll
        for (int e = 1; e < E; e++) if (logits[e] > v0) { v0 = logits[e]; e0 = e; }
        int e1 = -1; float v1 = -3.4e38f;
        #pragma unroll
        for (int e = 0; e < E; e++) {
            if (e == e0) continue;
            if (logits[e] > v1) { v1 = logits[e]; e1 = e; }
        }
        float a1  = __expf(v1 - v0);
        float inv = 1.f / (1.f + a1);
        float g0 = inv, g1 = a1 * inv;
        int bb = perBatch ? (t / kS) : 0;
        int grp0 = bb * E + e0;
        int p0 = atomicAdd(&cnt[grp0], 1);
        list[grp0 * cap + p0] = t; gates[grp0 * cap + p0] = g0;
        int grp1 = bb * E + e1;
        int p1 = atomicAdd(&cnt[grp1], 1);
        list[grp1 * cap + p1] = t; gates[grp1 * cap + p1] = g1;
    }
}

// ---------------- packed f32x2 helpers ----------------
__device__ __forceinline__ void fma2(ull& d, ull a, ull b) {
    asm("fma.rn.f32x2 %0, %1, %2, %0;" : "+l"(d) : "l"(a), "l"(b));
}
__device__ __forceinline__ ull pack_dup(float a) {
    ull r;
    asm("mov.b64 %0, {%1, %1};" : "=l"(r) : "f"(a));
    return r;
}
__device__ __forceinline__ float2 unpack2(ull v) {
    float2 r;
    asm("mov.b64 {%0, %1}, %2;" : "=f"(r.x), "=f"(r.y) : "l"(v));
    return r;
}

// ---------------- grouped GEMM, f32x2, LDS.128 microtile, split-K ----------------
// BN = 128, BK = 16, 256 threads as 16(ty) x 16(tx).
// Thread owns rows {4ty..4ty+3} (+64 for BM=128), cols col0 + {4tx..4tx+3, +64}.
// GATHER_A : A row index = list token; grouped else rows g*cap+r; dense rows r.
// SCATTER  : atomicAdd into out[token,:] scaled by per-row gate (splitK must be 1).
// splitK>1 : out must be pre-zeroed; partials accumulated with atomicAdd,
//            bias contributed only by chunk 0.
// Dual dense mode: when cnt==null and W2!=null, group 1 uses W2/bias2/out2.
template <int BM, bool GATHER_A, bool SCATTER, bool RELU>
__global__ __launch_bounds__(256, 2)
void gemm3_kernel(const float* __restrict__ A,
                  const float* __restrict__ W,
                  const float* __restrict__ bias,
                  float* __restrict__ out,
                  const float* __restrict__ W2,
                  const float* __restrict__ bias2,
                  float* __restrict__ out2,
                  const int* __restrict__ list,
                  const float* __restrict__ gates,
                  const int* __restrict__ cnt,
                  int Mfixed, int N, int K, int cap, int wMod,
                  float alpha, int splitK)
{
    constexpr int BN = 128, BK = 16;
    constexpr int S  = BM / 64;                  // row groups per thread (1 or 2)
    constexpr int MR = 4 * S;                    // rows per thread
    constexpr int AITER = BM * BK / (4 * 256);   // float4 A loads per thread

    int gz = blockIdx.z;
    int g  = gz / splitK;
    int kc = gz % splitK;

    int M;
    const float* Wg; const float* bg; float* og;
    bool grouped = (cnt != nullptr);
    if (grouped) {
        M = cnt[g];
        int e = g % wMod;
        Wg = W    + (size_t)e * K * N;
        bg = bias + (size_t)e * N;
        og = out;
    } else {
        M = Mfixed;
        if (W2 != nullptr && g == 1) { Wg = W2; bg = bias2; og = out2; }
        else                         { Wg = W;  bg = bias;  og = out;  }
    }
    int row0 = blockIdx.x * BM;
    if (row0 >= M) return;
    int col0 = blockIdx.y * BN;

    int Kc     = K / splitK;
    int kcBase = kc * Kc;

    __shared__ __align__(16) float As[2][BK][BM];
    __shared__ __align__(16) float Bs[2][BK][BN];
    __shared__ int   rowTok[BM];
    __shared__ float rowG[BM];

    int tid = threadIdx.x;
    int tx = tid & 15, ty = tid >> 4;

    if (tid < BM) {
        int r = row0 + tid;
        int tok = 0; float gt = 0.f;
        if (r < M && list) { tok = list[(size_t)g * cap + r]; gt = gates[(size_t)g * cap + r]; }
        rowTok[tid] = tok;
        rowG[tid]   = gt;
    }
    __syncthreads();

    ull acc[MR][4];
    #pragma unroll
    for (int i = 0; i < MR; i++)
        #pragma unroll
        for (int j = 0; j < 4; j++) acc[i][j] = 0ull;

    float4 aR[AITER], bR[2];
    int T = Kc / BK;

    auto loadTile = [&](int t) {
        int k0 = kcBase + t * BK;
        #pragma unroll
        for (int i = 0; i < AITER; i++) {
            int idx = tid + 256 * i;
            int r   = idx & (BM - 1);
            int kq  = idx / BM;          // 0..3
            int gr  = row0 + r;
            float4 v = make_float4(0.f, 0.f, 0.f, 0.f);
            if (gr < M) {
                size_t ar;
                if (GATHER_A)     ar = (size_t)rowTok[r];
                else if (grouped) ar = (size_t)g * cap + gr;
                else              ar = (size_t)gr;
                v = *(const float4*)&A[ar * K + k0 + kq * 4];
            }
            aR[i] = v;
        }
        #pragma unroll
        for (int i = 0; i < 2; i++) {
            int idx = tid + 256 * i;
            int kk  = idx >> 5;
            int c4  = idx & 31;
            bR[i] = *(const float4*)&Wg[(size_t)(k0 + kk) * N + col0 + c4 * 4];
        }
    };
    auto stsTile = [&](int buf) {
        #pragma unroll
        for (int i = 0; i < AITER; i++) {
            int idx = tid + 256 * i;
            int r   = idx & (BM - 1);
            int kq  = idx / BM;
            As[buf][kq * 4 + 0][r] = aR[i].x;
            As[buf][kq * 4 + 1][r] = aR[i].y;
            As[buf][kq * 4 + 2][r] = aR[i].z;
            As[buf][kq * 4 + 3][r] = aR[i].w;
        }
        #pragma unroll
        for (int i = 0; i < 2; i++) {
            int idx = tid + 256 * i;
            int kk  = idx >> 5;
            int c4  = idx & 31;
            *(float4*)&Bs[buf][kk][c4 * 4] = bR[i];
        }
    };

    loadTile(0);
    stsTile(0);
    __syncthreads();

    for (int t = 0; t < T; t++) {
        if (t + 1 < T) loadTile(t + 1);
        int buf = t & 1;
        #pragma unroll
        for (int kk = 0; kk < BK; kk++) {
            float4 af[S];
            #pragma unroll
            for (int s = 0; s < S; s++)
                af[s] = *(const float4*)&As[buf][kk][ty * 4 + 64 * s];
            float4 b0 = *(const float4*)&Bs[buf][kk][tx * 4];
            float4 b1 = *(const float4*)&Bs[buf][kk][tx * 4 + 64];
            ull bv[4];
            bv[0] = ((const ull*)&b0)[0];
            bv[1] = ((const ull*)&b0)[1];
            bv[2] = ((const ull*)&b1)[0];
            bv[3] = ((const ull*)&b1)[1];
            #pragma unroll
            for (int s = 0; s < S; s++) {
                const float* av = (const float*)&af[s];
                #pragma unroll
                for (int rr = 0; rr < 4; rr++) {
                    ull ad = pack_dup(av[rr]);
                    fma2(acc[s * 4 + rr][0], ad, bv[0]);
                    fma2(acc[s * 4 + rr][1], ad, bv[1]);
                    fma2(acc[s * 4 + rr][2], ad, bv[2]);
                    fma2(acc[s * 4 + rr][3], ad, bv[3]);
                }
            }
        }
        if (t + 1 < T) stsTile((t + 1) & 1);
        __syncthreads();
    }

    // ---- epilogue ----
    bool partial = (splitK > 1);
    #pragma unroll
    for (int s = 0; s < S; s++) {
        #pragma unroll
        for (int rr = 0; rr < 4; rr++) {
            int r  = 4 * ty + 64 * s + rr;
            int gr = row0 + r;
            if (gr >= M) continue;
            #pragma unroll
            for (int j = 0; j < 4; j++) {
                int n0 = col0 + 4 * tx + 64 * (j >> 1) + 2 * (j & 1);
                float2 v = unpack2(acc[s * 4 + rr][j]);
                float bx = (!partial || kc == 0) ? bg[n0]     : 0.f;
                float by = (!partial || kc == 0) ? bg[n0 + 1] : 0.f;
                v.x = (v.x + bx) * alpha;
                v.y = (v.y + by) * alpha;
                if (RELU) { v.x = fmaxf(v.x, 0.f); v.y = fmaxf(v.y, 0.f); }
                if (SCATTER) {
                    float gt = rowG[r];
                    float* dst = &og[(size_t)rowTok[r] * N + n0];
                    atomicAdd(dst,     gt * v.x);
                    atomicAdd(dst + 1, gt * v.y);
                } else {
                    size_t orow = grouped ? (size_t)g * cap + gr : (size_t)gr;
                    float* dst = &og[orow * N + n0];
                    if (partial) {
                        atomicAdd(dst,     v.x);
                        atomicAdd(dst + 1, v.y);
                    } else {
                        *(float2*)dst = v;
                    }
                }
            }
        }
    }
}

// ---------------- routed attention core ----------------
__global__ __launch_bounds__(256)
void attn_kernel(const float* __restrict__ rel_table)
{
    constexpr int QT = 16, KT = 16, KPAD = 132;
    int g  = blockIdx.x;          // b*EA + e
    int b  = g / kEA;
    int qt = blockIdx.y;
    int cnt  = g_cntA[g];
    int base = qt * QT;
    if (base >= cnt) return;

    __shared__ __align__(16) float qs  [QT][kHD];
    __shared__ __align__(16) float relq[QT][KPAD];
    __shared__ __align__(16) float ks  [KT][KPAD];
    __shared__ __align__(16) float vs  [KT][KPAD];
    __shared__ float ps[QT][KT];
    __shared__ int   qpos[QT];

    int tid = threadIdx.x;

    for (int i = tid; i < QT * kHD / 4; i += 256) {
        int qi = i / (kHD / 4), h4 = i % (kHD / 4);
        float4 v = make_float4(0.f, 0.f, 0.f, 0.f);
        if (base + qi < cnt)
            v = ((const float4*)&g_qg[((size_t)g * kS + base + qi) * kHD])[h4];
        ((float4*)&qs[qi][0])[h4] = v;
    }
    if (tid < QT) {
        int t = (base + tid < cnt) ? g_listA[g * kS + base + tid] : 0;
        qpos[tid] = t & (kS - 1);
    }
    __syncthreads();

    for (int idx = tid; idx < QT * kR; idx += 256) {
        int qi = idx / kR, r = idx % kR;
        const float4* q4 = (const float4*)&qs[qi][0];
        const float4* t4 = (const float4*)&rel_table[(size_t)r * kHD];
        float s = 0.f;
        #pragma unroll
        for (int h = 0; h < kHD / 4; h++) {
            float4 a = q4[h], c = t4[h];
            s += a.x * c.x + a.y * c.y + a.z * c.z + a.w * c.w;
        }
        relq[qi][r] = s;
    }
    __syncthreads();

    int qi = tid >> 4;
    int li = tid & 15;
    float m = -1e30f, l = 0.f;
    float acc[8];
    #pragma unroll
    for (int t = 0; t < 8; t++) acc[t] = 0.f;
    int myq = qpos[qi];
    const float4* q4 = (const float4*)&qs[qi][0];

    for (int c0 = 0; c0 < kS; c0 += KT) {
        for (int i = tid; i < KT * kHD / 4; i += 256) {
            int kk = i / (kHD / 4), h4 = i % (kHD / 4);
            size_t srcrow = ((size_t)b * kS + c0 + kk) * kHD;
            ((float4*)&ks[kk][0])[h4] = ((const float4*)&g_kbuf[srcrow])[h4];
            ((float4*)&vs[kk][0])[h4] = ((const float4*)&g_vbuf[srcrow])[h4];
        }
        __syncthreads();

        const float4* k4 = (const float4*)&ks[li][0];
        float s = 0.f;
        #pragma unroll
        for (int h = 0; h < kHD / 4; h++) {
            float4 a = q4[h], kv = k4[h];
            s += a.x * kv.x + a.y * kv.y + a.z * kv.z + a.w * kv.w;
        }
        int rel = c0 + li - myq;
        rel = min(max(rel, -kMAXP), kMAXP) + kMAXP;
        s += relq[qi][rel];

        float cm = s;
        #pragma unroll
        for (int o = 8; o; o >>= 1) cm = fmaxf(cm, __shfl_xor_sync(~0u, cm, o));
        float mn = fmaxf(m, cm);
        float scale = __expf(m - mn);
        float p = __expf(s - mn);
        float psum = p;
        #pragma unroll
        for (int o = 8; o; o >>= 1) psum += __shfl_xor_sync(~0u, psum, o);
        l = l * scale + psum;
        m = mn;
        ps[qi][li] = p;
        __syncwarp();

        #pragma unroll
        for (int t = 0; t < 8; t++) acc[t] *= scale;
        #pragma unroll
        for (int kk = 0; kk < KT; kk++) {
            float pv = ps[qi][kk];
            const float4* v4 = (const float4*)&vs[kk][li * 8];
            float4 va = v4[0], vb = v4[1];
            acc[0] += pv * va.x; acc[1] += pv * va.y;
            acc[2] += pv * va.z; acc[3] += pv * va.w;
            acc[4] += pv * vb.x; acc[5] += pv * vb.y;
            acc[6] += pv * vb.z; acc[7] += pv * vb.w;
        }
        __syncthreads();
    }

    if (base + qi < cnt) {
        float inv = 1.f / l;
        float* dst = &g_ctxg[((size_t)g * kS + base + qi) * kHD + li * 8];
        #pragma unroll
        for (int t = 0; t < 8; t++) dst[t] = acc[t] * inv;
    }
}

// ---------------- launch ----------------
extern "C" void kernel_launch(void* const* d_in, const int* in_sizes, int n_in,
                              void* d_out, int out_size)
{
    const float* src   = (const float*)d_in[0];
    const float* ln1_w = (const float*)d_in[1];
    const float* ln1_b = (const float*)d_in[2];
    const float* ln2_w = (const float*)d_in[3];
    const float* ln2_b = (const float*)d_in[4];
    const float* agw   = (const float*)d_in[5];
    const float* q_w   = (const float*)d_in[6];
    const float* q_b   = (const float*)d_in[7];
    const float* k_w   = (const float*)d_in[8];
    const float* k_b   = (const float*)d_in[9];
    const float* v_w   = (const float*)d_in[10];
    const float* v_b   = (const float*)d_in[11];
    const float* o_w   = (const float*)d_in[12];
    const float* o_b   = (const float*)d_in[13];
    const float* rel   = (const float*)d_in[14];
    const float* fgw   = (const float*)d_in[15];
    const float* w1    = (const float*)d_in[16];
    const float* b1    = (const float*)d_in[17];
    const float* w2    = (const float*)d_in[18];
    const float* b2    = (const float*)d_in[19];
    float* out = (float*)d_out;

    float *xn1, *xn2, *xcur, *kb, *vb, *qg, *ctxg, *hb, *gateA, *gateF;
    int *cntA, *listA, *cntF, *listF;
    cudaGetSymbolAddress((void**)&xn1,   g_xn1);
    cudaGetSymbolAddress((void**)&xn2,   g_xn2);
    cudaGetSymbolAddress((void**)&xcur,  g_xcur);
    cudaGetSymbolAddress((void**)&kb,    g_kbuf);
    cudaGetSymbolAddress((void**)&vb,    g_vbuf);
    cudaGetSymbolAddress((void**)&qg,    g_qg);
    cudaGetSymbolAddress((void**)&ctxg,  g_ctxg);
    cudaGetSymbolAddress((void**)&hb,    g_hbuf);
    cudaGetSymbolAddress((void**)&gateA, g_gateA);
    cudaGetSymbolAddress((void**)&gateF, g_gateF);
    cudaGetSymbolAddress((void**)&cntA,  g_cntA);
    cudaGetSymbolAddress((void**)&listA, g_listA);
    cudaGetSymbolAddress((void**)&cntF,  g_cntF);
    cudaGetSymbolAddress((void**)&listF, g_listF);

    zero_cnts_kernel<<<1, 64>>>();

    // pre-zero split-K accumulation targets
    zero_f_kernel<<<256, 256>>>(qg, kB * kEA * kS * kHD);
    zero_f_kernel<<<128, 256>>>(kb, kBS * kHD);
    zero_f_kernel<<<128, 256>>>(vb, kBS * kHD);

    // LN1 + attention router
    ln_gate_kernel<kEA><<<kBS, 256>>>(src, ln1_w, ln1_b, agw, xn1,
                                      cntA, listA, gateA, kS, 1);

    // shared k + v projections fused (dual dense, BM=64, splitK=2 -> 256 CTAs)
    gemm3_kernel<64, false, false, false><<<dim3(kBS / 64, 1, 2 * 2), 256>>>(
        xn1, k_w, k_b, kb, v_w, v_b, vb,
        nullptr, nullptr, nullptr, kBS, kHD, kD, 0, 1, 1.f, 2);

    // routed q projection (gather per (b,e) group, splitK=4 -> ~256 active CTAs)
    gemm3_kernel<128, true, false, false><<<dim3(kS / 128, 1, kB * kEA * 4), 256>>>(
        xn1, q_w, q_b, qg, nullptr, nullptr, nullptr,
        listA, gateA, cntA, 0, kHD, kD, kS, kEA, kQScale, 4);

    // attention core
    attn_kernel<<<dim3(kB * kEA, kS / 16), 256>>>(rel);

    // residual base x = src
    copy_kernel<<<512, 256>>>(src, xcur, kBS * kD);

    // routed output projection, gated atomic accumulate into x
    gemm3_kernel<128, false, true, false><<<dim3(kS / 128, kD / 128, kB * kEA), 256>>>(
        ctxg, o_w, o_b, xcur, nullptr, nullptr, nullptr,
        listA, gateA, cntA, 0, kD, kHD, kS, kEA, 1.f, 1);

    // LN2 + FFN router
    ln_gate_kernel<kEF><<<kBS, 256>>>(xcur, ln2_w, ln2_b, fgw, xn2,
                                      cntF, listF, gateF, kBS, 0);

    // routed FFN up-proj + relu
    gemm3_kernel<128, true, false, true><<<dim3(kBS / 128, kFH / 128, kEF), 256>>>(
        xn2, w1, b1, hb, nullptr, nullptr, nullptr,
        listF, gateF, cntF, 0, kFH, kD, kBS, kEF, 1.f, 1);

    // residual base for output
    copy_kernel<<<512, 256>>>(xcur, out, kBS * kD);

    // routed FFN down-proj, gated atomic accumulate into out
    gemm3_kernel<128, false, true, false><<<dim3(kBS / 128, kD / 128, kEF), 256>>>(
        hb, w2, b2, out, nullptr, nullptr, nullptr,
        listF, gateF, cntF, 0, kD, kFH, kBS, kEF, 1.f, 1);
}

// round 9
// speedup vs baseline: 1.3696x; 1.0918x over previous
#include <cuda_runtime.h>
#include <cuda_bf16.h>

// ---------------- problem constants ----------------
namespace {
constexpr int kD    = 1024;
constexpr int kHD   = 128;
constexpr int kEA   = 8;
constexpr int kEF   = 16;
constexpr int kFH   = 512;
constexpr int kMAXP = 64;
constexpr int kR    = 2 * kMAXP + 1;   // 129
constexpr int kB    = 4;
constexpr int kS    = 1024;
constexpr int kBS   = kB * kS;         // 4096
constexpr float kEPS = 1e-5f;
constexpr float kQScale = 0.08838834764831845f;   // 128^-0.5
constexpr int kPAD = 40;               // smem row pitch in bf16 (conflict-free frag loads)
}

typedef unsigned long long ull;

// ---------------- device scratch (allocation-free) ----------------
__device__ float g_xn1 [kBS * kD];
__device__ float g_xn2 [kBS * kD];
__device__ float g_xcur[kBS * kD];
__device__ float g_kbuf[kBS * kHD];
__device__ float g_vbuf[kBS * kHD];
__device__ int   g_cntA [kB * kEA];
__device__ int   g_listA[kB * kEA * kS];
__device__ float g_gateA[kB * kEA * kS];
__device__ float g_qg  [(size_t)kB * kEA * kS * kHD];
__device__ float g_ctxg[(size_t)kB * kEA * kS * kHD];
__device__ int   g_cntF [kEF];
__device__ int   g_listF[kEF * kBS];
__device__ float g_gateF[kEF * kBS];
// bf16 hi/lo split buffers for tensor-core FFN
__device__ __nv_bfloat16 g_xn2h[(size_t)kBS * kD];
__device__ __nv_bfloat16 g_xn2l[(size_t)kBS * kD];
__device__ __nv_bfloat16 g_w1th[(size_t)kEF * kFH * kD];  // [e][n=512][k=1024]
__device__ __nv_bfloat16 g_w1tl[(size_t)kEF * kFH * kD];
__device__ __nv_bfloat16 g_w2th[(size_t)kEF * kD * kFH];  // [e][n=1024][k=512]
__device__ __nv_bfloat16 g_w2tl[(size_t)kEF * kD * kFH];
__device__ __nv_bfloat16 g_hh [(size_t)kEF * kBS * kFH];  // routed hidden hi
__device__ __nv_bfloat16 g_hl [(size_t)kEF * kBS * kFH];  // routed hidden lo

// ---------------- small utility kernels ----------------
__global__ void zero_cnts_kernel() {
    int i = threadIdx.x;
    if (i < kB * kEA) g_cntA[i] = 0;
    if (i < kEF)      g_cntF[i] = 0;
}

__global__ void zero_f_kernel(float* __restrict__ p, int n) {
    int n4 = n >> 2;
    float4 z = make_float4(0.f, 0.f, 0.f, 0.f);
    for (int i = blockIdx.x * blockDim.x + threadIdx.x; i < n4; i += gridDim.x * blockDim.x)
        ((float4*)p)[i] = z;
}

__global__ void copy_kernel(const float* __restrict__ in, float* __restrict__ out, int n) {
    int n4 = n >> 2;
    for (int i = blockIdx.x * blockDim.x + threadIdx.x; i < n4; i += gridDim.x * blockDim.x)
        ((float4*)out)[i] = ((const float4*)in)[i];
}

// f32 row buffer -> bf16 hi/lo split (same layout)
__global__ void split_rows_kernel(const float* __restrict__ in,
                                  __nv_bfloat16* __restrict__ hi,
                                  __nv_bfloat16* __restrict__ lo, int n)
{
    int n4 = n >> 2;
    for (int i = blockIdx.x * blockDim.x + threadIdx.x; i < n4; i += gridDim.x * blockDim.x) {
        float4 v = ((const float4*)in)[i];
        __nv_bfloat16 h0 = __float2bfloat16(v.x), h1 = __float2bfloat16(v.y);
        __nv_bfloat16 h2 = __float2bfloat16(v.z), h3 = __float2bfloat16(v.w);
        __nv_bfloat162 H0; H0.x = h0; H0.y = h1;
        __nv_bfloat162 H1; H1.x = h2; H1.y = h3;
        __nv_bfloat162 L0, L1;
        L0.x = __float2bfloat16(v.x - __bfloat162float(h0));
        L0.y = __float2bfloat16(v.y - __bfloat162float(h1));
        L1.x = __float2bfloat16(v.z - __bfloat162float(h2));
        L1.y = __float2bfloat16(v.w - __bfloat162float(h3));
        ((__nv_bfloat162*)hi)[2 * i]     = H0;
        ((__nv_bfloat162*)hi)[2 * i + 1] = H1;
        ((__nv_bfloat162*)lo)[2 * i]     = L0;
        ((__nv_bfloat162*)lo)[2 * i + 1] = L1;
    }
}

// [E][K][N] f32 -> [E][N][K] bf16 hi/lo (transpose + split)
__global__ void transp_split_kernel(const float* __restrict__ in,
                                    __nv_bfloat16* __restrict__ oh,
                                    __nv_bfloat16* __restrict__ ol,
                                    int K, int N)
{
    __shared__ float t[32][33];
    int e  = blockIdx.z;
    int nb = blockIdx.x * 32, kb = blockIdx.y * 32;
    int tx = threadIdx.x, ty = threadIdx.y;
    const float* ie = in + (size_t)e * K * N;
    for (int i = ty; i < 32; i += 8)
        t[i][tx] = ie[(size_t)(kb + i) * N + nb + tx];
    __syncthreads();
    size_t ob = (size_t)e * N * K;
    for (int j = ty; j < 32; j += 8) {
        float v = t[tx][j];
        __nv_bfloat16 h = __float2bfloat16(v);
        size_t o = ob + (size_t)(nb + j) * K + kb + tx;
        oh[o] = h;
        ol[o] = __float2bfloat16(v - __bfloat162float(h));
    }
}

// ---------------- fused LayerNorm + top-2 router ----------------
template <int E>
__global__ __launch_bounds__(256)
void ln_gate_kernel(const float* __restrict__ x,
                    const float* __restrict__ w,
                    const float* __restrict__ bvec,
                    const float* __restrict__ gw,   // [D, E] row-major
                    float* __restrict__ xn,
                    int* __restrict__ cnt,
                    int* __restrict__ list,
                    float* __restrict__ gates,
                    int cap, int perBatch)
{
    __shared__ __align__(16) float xs[kD];
    __shared__ float red1[8], red2[8];
    __shared__ float logits[E];
    __shared__ float s_mu, s_rstd;

    int t    = blockIdx.x;
    int tid  = threadIdx.x;
    int lane = tid & 31, wid = tid >> 5;

    const float4* xin = (const float4*)(x + (size_t)t * kD);
    float4* xs4 = (float4*)xs;
    float s = 0.f, ss = 0.f;
    for (int i = tid; i < kD / 4; i += 256) {
        float4 v = xin[i];
        xs4[i] = v;
        s  += v.x + v.y + v.z + v.w;
        ss += v.x * v.x + v.y * v.y + v.z * v.z + v.w * v.w;
    }
    #pragma unroll
    for (int o = 16; o; o >>= 1) {
        s  += __shfl_xor_sync(~0u, s, o);
        ss += __shfl_xor_sync(~0u, ss, o);
    }
    if (lane == 0) { red1[wid] = s; red2[wid] = ss; }
    __syncthreads();
    if (tid == 0) {
        float S1 = 0.f, S2 = 0.f;
        #pragma unroll
        for (int i = 0; i < 8; i++) { S1 += red1[i]; S2 += red2[i]; }
        float mu  = S1 / kD;
        float var = S2 / kD - mu * mu;
        s_mu = mu; s_rstd = rsqrtf(var + kEPS);
    }
    __syncthreads();
    float mu = s_mu, rstd = s_rstd;
    for (int i = tid; i < kD; i += 256) {
        float v = (xs[i] - mu) * rstd * w[i] + bvec[i];
        xs[i] = v;
        xn[(size_t)t * kD + i] = v;
    }
    __syncthreads();

    for (int e = wid; e < E; e += 8) {
        float acc = 0.f;
        for (int d = lane; d < kD; d += 32) acc += xs[d] * gw[d * E + e];
        #pragma unroll
        for (int o = 16; o; o >>= 1) acc += __shfl_xor_sync(~0u, acc, o);
        if (lane == 0) logits[e] = acc;
    }
    __syncthreads();

    if (tid == 0) {
        int e0 = 0; float v0 = logits[0];
        #pragma unroll
        for (int e = 1; e < E; e++) if (logits[e] > v0) { v0 = logits[e]; e0 = e; }
        int e1 = -1; float v1 = -3.4e38f;
        #pragma unroll
        for (int e = 0; e < E; e++) {
            if (e == e0) continue;
            if (logits[e] > v1) { v1 = logits[e]; e1 = e; }
        }
        float a1  = __expf(v1 - v0);
        float inv = 1.f / (1.f + a1);
        float g0 = inv, g1 = a1 * inv;
        int bb = perBatch ? (t / kS) : 0;
        int grp0 = bb * E + e0;
        int p0 = atomicAdd(&cnt[grp0], 1);
        list[grp0 * cap + p0] = t; gates[grp0 * cap + p0] = g0;
        int grp1 = bb * E + e1;
        int p1 = atomicAdd(&cnt[grp1], 1);
        list[grp1 * cap + p1] = t; gates[grp1 * cap + p1] = g1;
    }
}

// ---------------- packed f32x2 helpers ----------------
__device__ __forceinline__ void fma2(ull& d, ull a, ull b) {
    asm("fma.rn.f32x2 %0, %1, %2, %0;" : "+l"(d) : "l"(a), "l"(b));
}
__device__ __forceinline__ ull pack_dup(float a) {
    ull r;
    asm("mov.b64 %0, {%1, %1};" : "=l"(r) : "f"(a));
    return r;
}
__device__ __forceinline__ float2 unpack2(ull v) {
    float2 r;
    asm("mov.b64 {%0, %1}, %2;" : "=f"(r.x), "=f"(r.y) : "l"(v));
    return r;
}

// ---------------- warp-MMA (HMMA bf16) helpers ----------------
__device__ __forceinline__ void mma16816(float* c, const unsigned* a, const unsigned* b) {
    asm volatile(
        "mma.sync.aligned.m16n8k16.row.col.f32.bf16.bf16.f32 "
        "{%0,%1,%2,%3}, {%4,%5,%6,%7}, {%8,%9}, {%0,%1,%2,%3};"
        : "+f"(c[0]), "+f"(c[1]), "+f"(c[2]), "+f"(c[3])
        : "r"(a[0]), "r"(a[1]), "r"(a[2]), "r"(a[3]), "r"(b[0]), "r"(b[1]));
}

// ---------------- warp-MMA grouped FFN GEMM ----------------
// CTA tile 128x128, BK=32, 8 warps as 2(m) x 4(n) -> 64x32 warp tiles.
// bf16 hi/lo split: acc += Ah*Bh + Ah*Bl + Al*Bh (fp32 accum).
// A: [rows][K] hi/lo (gathered rows via list when GATHER_A; else grouped e*cap+r)
// B: [E][N][K] hi/lo (K contiguous per n-row == mma row.col B operand)
// FFN1MODE: relu(acc+bias) -> bf16 hi/lo stores to outH/outL at grouped rows
// else:     atomicAdd(outF[token], gate*(acc+bias))
template <bool GATHER_A, bool FFN1MODE>
__global__ __launch_bounds__(256)
void wmma_ffn_kernel(const __nv_bfloat16* __restrict__ Ah,
                     const __nv_bfloat16* __restrict__ Al,
                     const __nv_bfloat16* __restrict__ Bh,
                     const __nv_bfloat16* __restrict__ Bl,
                     const float* __restrict__ bias,         // [E][N]
                     float* __restrict__ outF,
                     __nv_bfloat16* __restrict__ outH,
                     __nv_bfloat16* __restrict__ outL,
                     const int* __restrict__ list,
                     const float* __restrict__ gates,
                     const int* __restrict__ cnt,
                     int N, int K, int cap)
{
    int e = blockIdx.z;
    int M = cnt[e];
    int row0 = blockIdx.x * 128;
    if (row0 >= M) return;
    int col0 = blockIdx.y * 128;

    extern __shared__ __align__(16) __nv_bfloat16 sm[];   // 2 bufs x 4 tiles x 128*kPAD
    __shared__ int   rowTok[128];
    __shared__ float rowG[128];

    int tid  = threadIdx.x;
    int wid  = tid >> 5;
    int lane = tid & 31;
    int gq   = lane >> 2;        // fragment group row
    int tq   = lane & 3;         // fragment pair col

    if (tid < 128) {
        int r = row0 + tid;
        rowTok[tid] = (r < M) ? list[(size_t)e * cap + r] : 0;
        rowG[tid]   = (r < M) ? gates[(size_t)e * cap + r] : 0.f;
    }
    __syncthreads();

    auto tilep = [&](int buf, int t) -> __nv_bfloat16* {
        return sm + ((size_t)(buf * 4 + t)) * (128 * kPAD);
    };

    // chunk loader: 128 rows x 32 k per tile, uint4 (8 bf16) granularity
    auto loadChunk = [&](int c, int buf) {
        int k0 = c * 32;
        #pragma unroll
        for (int i = 0; i < 2; i++) {
            int idx = tid + 256 * i;
            int r   = idx >> 2;          // 0..127
            int u   = idx & 3;           // 4 x uint4 per 32-k row
            // A hi/lo
            uint4 vh = make_uint4(0, 0, 0, 0), vl = make_uint4(0, 0, 0, 0);
            int gr = row0 + r;
            if (gr < M) {
                size_t ar = GATHER_A ? (size_t)rowTok[r] : (size_t)e * cap + gr;
                vh = *(const uint4*)(Ah + ar * K + k0 + u * 8);
                vl = *(const uint4*)(Al + ar * K + k0 + u * 8);
            }
            *(uint4*)(tilep(buf, 0) + r * kPAD + u * 8) = vh;
            *(uint4*)(tilep(buf, 1) + r * kPAD + u * 8) = vl;
            // B hi/lo
            size_t br = (size_t)e * N + col0 + r;
            uint4 bh = *(const uint4*)(Bh + br * K + k0 + u * 8);
            uint4 bl = *(const uint4*)(Bl + br * K + k0 + u * 8);
            *(uint4*)(tilep(buf, 2) + r * kPAD + u * 8) = bh;
            *(uint4*)(tilep(buf, 3) + r * kPAD + u * 8) = bl;
        }
    };

    float acc[4][4][4];
    #pragma unroll
    for (int mf = 0; mf < 4; mf++)
        #pragma unroll
        for (int nf = 0; nf < 4; nf++)
            #pragma unroll
            for (int q = 0; q < 4; q++) acc[mf][nf][q] = 0.f;

    int warpM = (wid & 1) * 64;
    int warpN = (wid >> 1) * 32;
    int T = K >> 5;

    loadChunk(0, 0);
    __syncthreads();

    for (int c = 0; c < T; c++) {
        int buf = c & 1;
        if (c + 1 < T) loadChunk(c + 1, buf ^ 1);

        const __nv_bfloat16* sAh = tilep(buf, 0);
        const __nv_bfloat16* sAl = tilep(buf, 1);
        const __nv_bfloat16* sBh = tilep(buf, 2);
        const __nv_bfloat16* sBl = tilep(buf, 3);

        #pragma unroll
        for (int ks = 0; ks < 2; ks++) {
            int k0 = ks * 16;
            unsigned ah[4][4], al[4][4], bh[4][2], bl[4][2];
            #pragma unroll
            for (int mf = 0; mf < 4; mf++) {
                int rb = warpM + mf * 16 + gq;
                ah[mf][0] = *(const unsigned*)(sAh + rb * kPAD + k0 + 2 * tq);
                ah[mf][1] = *(const unsigned*)(sAh + (rb + 8) * kPAD + k0 + 2 * tq);
                ah[mf][2] = *(const unsigned*)(sAh + rb * kPAD + k0 + 2 * tq + 8);
                ah[mf][3] = *(const unsigned*)(sAh + (rb + 8) * kPAD + k0 + 2 * tq + 8);
                al[mf][0] = *(const unsigned*)(sAl + rb * kPAD + k0 + 2 * tq);
                al[mf][1] = *(const unsigned*)(sAl + (rb + 8) * kPAD + k0 + 2 * tq);
                al[mf][2] = *(const unsigned*)(sAl + rb * kPAD + k0 + 2 * tq + 8);
                al[mf][3] = *(const unsigned*)(sAl + (rb + 8) * kPAD + k0 + 2 * tq + 8);
            }
            #pragma unroll
            for (int nf = 0; nf < 4; nf++) {
                int nb = warpN + nf * 8 + gq;
                bh[nf][0] = *(const unsigned*)(sBh + nb * kPAD + k0 + 2 * tq);
                bh[nf][1] = *(const unsigned*)(sBh + nb * kPAD + k0 + 2 * tq + 8);
                bl[nf][0] = *(const unsigned*)(sBl + nb * kPAD + k0 + 2 * tq);
                bl[nf][1] = *(const unsigned*)(sBl + nb * kPAD + k0 + 2 * tq + 8);
            }
            #pragma unroll
            for (int mf = 0; mf < 4; mf++)
                #pragma unroll
                for (int nf = 0; nf < 4; nf++) {
                    mma16816(acc[mf][nf], ah[mf], bh[nf]);
                    mma16816(acc[mf][nf], ah[mf], bl[nf]);
                    mma16816(acc[mf][nf], al[mf], bh[nf]);
                }
        }
        __syncthreads();
    }

    // ---- epilogue ----
    const float* bg = bias + (size_t)e * N;
    #pragma unroll
    for (int mf = 0; mf < 4; mf++) {
        #pragma unroll
        for (int half = 0; half < 2; half++) {
            int rloc = warpM + mf * 16 + gq + half * 8;
            int gr   = row0 + rloc;
            if (gr >= M) continue;
            #pragma unroll
            for (int nf = 0; nf < 4; nf++) {
                int ncol = col0 + warpN + nf * 8 + 2 * tq;
                float v0 = acc[mf][nf][half * 2 + 0] + bg[ncol];
                float v1 = acc[mf][nf][half * 2 + 1] + bg[ncol + 1];
                if (FFN1MODE) {
                    v0 = fmaxf(v0, 0.f);
                    v1 = fmaxf(v1, 0.f);
                    __nv_bfloat16 h0 = __float2bfloat16(v0);
                    __nv_bfloat16 h1 = __float2bfloat16(v1);
                    __nv_bfloat162 H; H.x = h0; H.y = h1;
                    __nv_bfloat162 L;
                    L.x = __float2bfloat16(v0 - __bfloat162float(h0));
                    L.y = __float2bfloat16(v1 - __bfloat162float(h1));
                    size_t off = ((size_t)e * cap + gr) * N + ncol;
                    *(__nv_bfloat162*)(outH + off) = H;
                    *(__nv_bfloat162*)(outL + off) = L;
                } else {
                    int tok = rowTok[rloc];
                    float gt = rowG[rloc];
                    float* dst = outF + (size_t)tok * N + ncol;
                    atomicAdd(dst,     gt * v0);
                    atomicAdd(dst + 1, gt * v1);
                }
            }
        }
    }
}

// ---------------- grouped GEMM, f32x2, LDS.128 microtile, split-K ----------------
template <int BM, bool GATHER_A, bool SCATTER, bool RELU>
__global__ __launch_bounds__(256, 2)
void gemm3_kernel(const float* __restrict__ A,
                  const float* __restrict__ W,
                  const float* __restrict__ bias,
                  float* __restrict__ out,
                  const float* __restrict__ W2,
                  const float* __restrict__ bias2,
                  float* __restrict__ out2,
                  const int* __restrict__ list,
                  const float* __restrict__ gates,
                  const int* __restrict__ cnt,
                  int Mfixed, int N, int K, int cap, int wMod,
                  float alpha, int splitK)
{
    constexpr int BN = 128, BK = 16;
    constexpr int S  = BM / 64;
    constexpr int MR = 4 * S;
    constexpr int AITER = BM * BK / (4 * 256);

    int gz = blockIdx.z;
    int g  = gz / splitK;
    int kc = gz % splitK;

    int M;
    const float* Wg; const float* bg; float* og;
    bool grouped = (cnt != nullptr);
    if (grouped) {
        M = cnt[g];
        int e = g % wMod;
        Wg = W    + (size_t)e * K * N;
        bg = bias + (size_t)e * N;
        og = out;
    } else {
        M = Mfixed;
        if (W2 != nullptr && g == 1) { Wg = W2; bg = bias2; og = out2; }
        else                         { Wg = W;  bg = bias;  og = out;  }
    }
    int row0 = blockIdx.x * BM;
    if (row0 >= M) return;
    int col0 = blockIdx.y * BN;

    int Kc     = K / splitK;
    int kcBase = kc * Kc;

    __shared__ __align__(16) float As[2][BK][BM];
    __shared__ __align__(16) float Bs[2][BK][BN];
    __shared__ int   rowTok[BM];
    __shared__ float rowG[BM];

    int tid = threadIdx.x;
    int tx = tid & 15, ty = tid >> 4;

    if (tid < BM) {
        int r = row0 + tid;
        int tok = 0; float gt = 0.f;
        if (r < M && list) { tok = list[(size_t)g * cap + r]; gt = gates[(size_t)g * cap + r]; }
        rowTok[tid] = tok;
        rowG[tid]   = gt;
    }
    __syncthreads();

    ull acc[MR][4];
    #pragma unroll
    for (int i = 0; i < MR; i++)
        #pragma unroll
        for (int j = 0; j < 4; j++) acc[i][j] = 0ull;

    float4 aR[AITER], bR[2];
    int T = Kc / BK;

    auto loadTile = [&](int t) {
        int k0 = kcBase + t * BK;
        #pragma unroll
        for (int i = 0; i < AITER; i++) {
            int idx = tid + 256 * i;
            int r   = idx & (BM - 1);
            int kq  = idx / BM;
            int gr  = row0 + r;
            float4 v = make_float4(0.f, 0.f, 0.f, 0.f);
            if (gr < M) {
                size_t ar;
                if (GATHER_A)     ar = (size_t)rowTok[r];
                else if (grouped) ar = (size_t)g * cap + gr;
                else              ar = (size_t)gr;
                v = *(const float4*)&A[ar * K + k0 + kq * 4];
            }
            aR[i] = v;
        }
        #pragma unroll
        for (int i = 0; i < 2; i++) {
            int idx = tid + 256 * i;
            int kk  = idx >> 5;
            int c4  = idx & 31;
            bR[i] = *(const float4*)&Wg[(size_t)(k0 + kk) * N + col0 + c4 * 4];
        }
    };
    auto stsTile = [&](int buf) {
        #pragma unroll
        for (int i = 0; i < AITER; i++) {
            int idx = tid + 256 * i;
            int r   = idx & (BM - 1);
            int kq  = idx / BM;
            As[buf][kq * 4 + 0][r] = aR[i].x;
            As[buf][kq * 4 + 1][r] = aR[i].y;
            As[buf][kq * 4 + 2][r] = aR[i].z;
            As[buf][kq * 4 + 3][r] = aR[i].w;
        }
        #pragma unroll
        for (int i = 0; i < 2; i++) {
            int idx = tid + 256 * i;
            int kk  = idx >> 5;
            int c4  = idx & 31;
            *(float4*)&Bs[buf][kk][c4 * 4] = bR[i];
        }
    };

    loadTile(0);
    stsTile(0);
    __syncthreads();

    for (int t = 0; t < T; t++) {
        if (t + 1 < T) loadTile(t + 1);
        int buf = t & 1;
        #pragma unroll
        for (int kk = 0; kk < BK; kk++) {
            float4 af[S];
            #pragma unroll
            for (int s = 0; s < S; s++)
                af[s] = *(const float4*)&As[buf][kk][ty * 4 + 64 * s];
            float4 b0 = *(const float4*)&Bs[buf][kk][tx * 4];
            float4 b1 = *(const float4*)&Bs[buf][kk][tx * 4 + 64];
            ull bv[4];
            bv[0] = ((const ull*)&b0)[0];
            bv[1] = ((const ull*)&b0)[1];
            bv[2] = ((const ull*)&b1)[0];
            bv[3] = ((const ull*)&b1)[1];
            #pragma unroll
            for (int s = 0; s < S; s++) {
                const float* av = (const float*)&af[s];
                #pragma unroll
                for (int rr = 0; rr < 4; rr++) {
                    ull ad = pack_dup(av[rr]);
                    fma2(acc[s * 4 + rr][0], ad, bv[0]);
                    fma2(acc[s * 4 + rr][1], ad, bv[1]);
                    fma2(acc[s * 4 + rr][2], ad, bv[2]);
                    fma2(acc[s * 4 + rr][3], ad, bv[3]);
                }
            }
        }
        if (t + 1 < T) stsTile((t + 1) & 1);
        __syncthreads();
    }

    bool partial = (splitK > 1);
    #pragma unroll
    for (int s = 0; s < S; s++) {
        #pragma unroll
        for (int rr = 0; rr < 4; rr++) {
            int r  = 4 * ty + 64 * s + rr;
            int gr = row0 + r;
            if (gr >= M) continue;
            #pragma unroll
            for (int j = 0; j < 4; j++) {
                int n0 = col0 + 4 * tx + 64 * (j >> 1) + 2 * (j & 1);
                float2 v = unpack2(acc[s * 4 + rr][j]);
                float bx = (!partial || kc == 0) ? bg[n0]     : 0.f;
                float by = (!partial || kc == 0) ? bg[n0 + 1] : 0.f;
                v.x = (v.x + bx) * alpha;
                v.y = (v.y + by) * alpha;
                if (RELU) { v.x = fmaxf(v.x, 0.f); v.y = fmaxf(v.y, 0.f); }
                if (SCATTER) {
                    float gt = rowG[r];
                    float* dst = &og[(size_t)rowTok[r] * N + n0];
                    atomicAdd(dst,     gt * v.x);
                    atomicAdd(dst + 1, gt * v.y);
                } else {
                    size_t orow = grouped ? (size_t)g * cap + gr : (size_t)gr;
                    float* dst = &og[orow * N + n0];
                    if (partial) {
                        atomicAdd(dst,     v.x);
                        atomicAdd(dst + 1, v.y);
                    } else {
                        *(float2*)dst = v;
                    }
                }
            }
        }
    }
}

// ---------------- routed attention core ----------------
__global__ __launch_bounds__(256)
void attn_kernel(const float* __restrict__ rel_table)
{
    constexpr int QT = 16, KT = 16, KPAD = 132;
    int g  = blockIdx.x;          // b*EA + e
    int b  = g / kEA;
    int qt = blockIdx.y;
    int cnt  = g_cntA[g];
    int base = qt * QT;
    if (base >= cnt) return;

    __shared__ __align__(16) float qs  [QT][kHD];
    __shared__ __align__(16) float relq[QT][KPAD];
    __shared__ __align__(16) float ks  [KT][KPAD];
    __shared__ __align__(16) float vs  [KT][KPAD];
    __shared__ float ps[QT][KT];
    __shared__ int   qpos[QT];

    int tid = threadIdx.x;

    for (int i = tid; i < QT * kHD / 4; i += 256) {
        int qi = i / (kHD / 4), h4 = i % (kHD / 4);
        float4 v = make_float4(0.f, 0.f, 0.f, 0.f);
        if (base + qi < cnt)
            v = ((const float4*)&g_qg[((size_t)g * kS + base + qi) * kHD])[h4];
        ((float4*)&qs[qi][0])[h4] = v;
    }
    if (tid < QT) {
        int t = (base + tid < cnt) ? g_listA[g * kS + base + tid] : 0;
        qpos[tid] = t & (kS - 1);
    }
    __syncthreads();

    for (int idx = tid; idx < QT * kR; idx += 256) {
        int qi = idx / kR, r = idx % kR;
        const float4* q4 = (const float4*)&qs[qi][0];
        const float4* t4 = (const float4*)&rel_table[(size_t)r * kHD];
        float s = 0.f;
        #pragma unroll
        for (int h = 0; h < kHD / 4; h++) {
            float4 a = q4[h], c = t4[h];
            s += a.x * c.x + a.y * c.y + a.z * c.z + a.w * c.w;
        }
        relq[qi][r] = s;
    }
    __syncthreads();

    int qi = tid >> 4;
    int li = tid & 15;
    float m = -1e30f, l = 0.f;
    float acc[8];
    #pragma unroll
    for (int t = 0; t < 8; t++) acc[t] = 0.f;
    int myq = qpos[qi];
    const float4* q4 = (const float4*)&qs[qi][0];

    for (int c0 = 0; c0 < kS; c0 += KT) {
        for (int i = tid; i < KT * kHD / 4; i += 256) {
            int kk = i / (kHD / 4), h4 = i % (kHD / 4);
            size_t srcrow = ((size_t)b * kS + c0 + kk) * kHD;
            ((float4*)&ks[kk][0])[h4] = ((const float4*)&g_kbuf[srcrow])[h4];
            ((float4*)&vs[kk][0])[h4] = ((const float4*)&g_vbuf[srcrow])[h4];
        }
        __syncthreads();

        const float4* k4 = (const float4*)&ks[li][0];
        float s = 0.f;
        #pragma unroll
        for (int h = 0; h < kHD / 4; h++) {
            float4 a = q4[h], kv = k4[h];
            s += a.x * kv.x + a.y * kv.y + a.z * kv.z + a.w * kv.w;
        }
        int rel = c0 + li - myq;
        rel = min(max(rel, -kMAXP), kMAXP) + kMAXP;
        s += relq[qi][rel];

        float cm = s;
        #pragma unroll
        for (int o = 8; o; o >>= 1) cm = fmaxf(cm, __shfl_xor_sync(~0u, cm, o));
        float mn = fmaxf(m, cm);
        float scale = __expf(m - mn);
        float p = __expf(s - mn);
        float psum = p;
        #pragma unroll
        for (int o = 8; o; o >>= 1) psum += __shfl_xor_sync(~0u, psum, o);
        l = l * scale + psum;
        m = mn;
        ps[qi][li] = p;
        __syncwarp();

        #pragma unroll
        for (int t = 0; t < 8; t++) acc[t] *= scale;
        #pragma unroll
        for (int kk = 0; kk < KT; kk++) {
            float pv = ps[qi][kk];
            const float4* v4 = (const float4*)&vs[kk][li * 8];
            float4 va = v4[0], vb = v4[1];
            acc[0] += pv * va.x; acc[1] += pv * va.y;
            acc[2] += pv * va.z; acc[3] += pv * va.w;
            acc[4] += pv * vb.x; acc[5] += pv * vb.y;
            acc[6] += pv * vb.z; acc[7] += pv * vb.w;
        }
        __syncthreads();
    }

    if (base + qi < cnt) {
        float inv = 1.f / l;
        float* dst = &g_ctxg[((size_t)g * kS + base + qi) * kHD + li * 8];
        #pragma unroll
        for (int t = 0; t < 8; t++) dst[t] = acc[t] * inv;
    }
}

// ---------------- launch ----------------
extern "C" void kernel_launch(void* const* d_in, const int* in_sizes, int n_in,
                              void* d_out, int out_size)
{
    const float* src   = (const float*)d_in[0];
    const float* ln1_w = (const float*)d_in[1];
    const float* ln1_b = (const float*)d_in[2];
    const float* ln2_w = (const float*)d_in[3];
    const float* ln2_b = (const float*)d_in[4];
    const float* agw   = (const float*)d_in[5];
    const float* q_w   = (const float*)d_in[6];
    const float* q_b   = (const float*)d_in[7];
    const float* k_w   = (const float*)d_in[8];
    const float* k_b   = (const float*)d_in[9];
    const float* v_w   = (const float*)d_in[10];
    const float* v_b   = (const float*)d_in[11];
    const float* o_w   = (const float*)d_in[12];
    const float* o_b   = (const float*)d_in[13];
    const float* rel   = (const float*)d_in[14];
    const float* fgw   = (const float*)d_in[15];
    const float* w1    = (const float*)d_in[16];
    const float* b1    = (const float*)d_in[17];
    const float* w2    = (const float*)d_in[18];
    const float* b2    = (const float*)d_in[19];
    float* out = (float*)d_out;

    float *xn1, *xn2, *xcur, *kb, *vb, *qg, *ctxg, *gateA, *gateF;
    int *cntA, *listA, *cntF, *listF;
    __nv_bfloat16 *xn2h, *xn2l, *w1th, *w1tl, *w2th, *w2tl, *hh, *hl;
    cudaGetSymbolAddress((void**)&xn1,   g_xn1);
    cudaGetSymbolAddress((void**)&xn2,   g_xn2);
    cudaGetSymbolAddress((void**)&xcur,  g_xcur);
    cudaGetSymbolAddress((void**)&kb,    g_kbuf);
    cudaGetSymbolAddress((void**)&vb,    g_vbuf);
    cudaGetSymbolAddress((void**)&qg,    g_qg);
    cudaGetSymbolAddress((void**)&ctxg,  g_ctxg);
    cudaGetSymbolAddress((void**)&gateA, g_gateA);
    cudaGetSymbolAddress((void**)&gateF, g_gateF);
    cudaGetSymbolAddress((void**)&cntA,  g_cntA);
    cudaGetSymbolAddress((void**)&listA, g_listA);
    cudaGetSymbolAddress((void**)&cntF,  g_cntF);
    cudaGetSymbolAddress((void**)&listF, g_listF);
    cudaGetSymbolAddress((void**)&xn2h,  g_xn2h);
    cudaGetSymbolAddress((void**)&xn2l,  g_xn2l);
    cudaGetSymbolAddress((void**)&w1th,  g_w1th);
    cudaGetSymbolAddress((void**)&w1tl,  g_w1tl);
    cudaGetSymbolAddress((void**)&w2th,  g_w2th);
    cudaGetSymbolAddress((void**)&w2tl,  g_w2tl);
    cudaGetSymbolAddress((void**)&hh,    g_hh);
    cudaGetSymbolAddress((void**)&hl,    g_hl);

    constexpr int kWmmaSmem = 2 * 4 * 128 * kPAD * 2;   // 81920 bytes
    cudaFuncSetAttribute(wmma_ffn_kernel<true,  true>,
                         cudaFuncAttributeMaxDynamicSharedMemorySize, kWmmaSmem);
    cudaFuncSetAttribute(wmma_ffn_kernel<false, false>,
                         cudaFuncAttributeMaxDynamicSharedMemorySize, kWmmaSmem);

    zero_cnts_kernel<<<1, 64>>>();

    // weight transpose+split (independent of activations — run early)
    transp_split_kernel<<<dim3(kFH / 32, kD / 32, kEF), dim3(32, 8)>>>(w1, w1th, w1tl, kD, kFH);
    transp_split_kernel<<<dim3(kD / 32, kFH / 32, kEF), dim3(32, 8)>>>(w2, w2th, w2tl, kFH, kD);

    // pre-zero split-K accumulation targets
    zero_f_kernel<<<256, 256>>>(qg, kB * kEA * kS * kHD);
    zero_f_kernel<<<128, 256>>>(kb, kBS * kHD);
    zero_f_kernel<<<128, 256>>>(vb, kBS * kHD);

    // LN1 + attention router
    ln_gate_kernel<kEA><<<kBS, 256>>>(src, ln1_w, ln1_b, agw, xn1,
                                      cntA, listA, gateA, kS, 1);

    // shared k + v projections fused (dual dense, BM=64, splitK=2)
    gemm3_kernel<64, false, false, false><<<dim3(kBS / 64, 1, 2 * 2), 256>>>(
        xn1, k_w, k_b, kb, v_w, v_b, vb,
        nullptr, nullptr, nullptr, kBS, kHD, kD, 0, 1, 1.f, 2);

    // routed q projection (gather per (b,e) group, splitK=4)
    gemm3_kernel<128, true, false, false><<<dim3(kS / 128, 1, kB * kEA * 4), 256>>>(
        xn1, q_w, q_b, qg, nullptr, nullptr, nullptr,
        listA, gateA, cntA, 0, kHD, kD, kS, kEA, kQScale, 4);

    // attention core
    attn_kernel<<<dim3(kB * kEA, kS / 16), 256>>>(rel);

    // residual base x = src
    copy_kernel<<<512, 256>>>(src, xcur, kBS * kD);

    // routed output projection, gated atomic accumulate into x
    gemm3_kernel<128, false, true, false><<<dim3(kS / 128, kD / 128, kB * kEA), 256>>>(
        ctxg, o_w, o_b, xcur, nullptr, nullptr, nullptr,
        listA, gateA, cntA, 0, kD, kHD, kS, kEA, 1.f, 1);

    // LN2 + FFN router
    ln_gate_kernel<kEF><<<kBS, 256>>>(xcur, ln2_w, ln2_b, fgw, xn2,
                                      cntF, listF, gateF, kBS, 0);

    // split xn2 into bf16 hi/lo
    split_rows_kernel<<<512, 256>>>(xn2, xn2h, xn2l, kBS * kD);

    // routed FFN up-proj + relu (HMMA bf16 split)
    wmma_ffn_kernel<true, true><<<dim3(kBS / 128, kFH / 128, kEF), 256, kWmmaSmem>>>(
        xn2h, xn2l, w1th, w1tl, b1,
        nullptr, hh, hl, listF, gateF, cntF, kFH, kD, kBS);

    // residual base for output
    copy_kernel<<<512, 256>>>(xcur, out, kBS * kD);

    // routed FFN down-proj, gated atomic accumulate into out (HMMA bf16 split)
    wmma_ffn_kernel<false, false><<<dim3(kBS / 128, kD / 128, kEF), 256, kWmmaSmem>>>(
        hh, hl, w2th, w2tl, b2,
        out, nullptr, nullptr, listF, gateF, cntF, kD, kFH, kBS);
}

// round 10
// speedup vs baseline: 1.4888x; 1.0870x over previous
#include <cuda_runtime.h>
#include <cuda_bf16.h>

// ---------------- problem constants ----------------
namespace {
constexpr int kD    = 1024;
constexpr int kHD   = 128;
constexpr int kEA   = 8;
constexpr int kEF   = 16;
constexpr int kFH   = 512;
constexpr int kMAXP = 64;
constexpr int kR    = 2 * kMAXP + 1;   // 129
constexpr int kB    = 4;
constexpr int kS    = 1024;
constexpr int kBS   = kB * kS;         // 4096
constexpr float kEPS = 1e-5f;
constexpr float kQScale = 0.08838834764831845f;   // 128^-0.5
constexpr int kPAD = 40;               // smem row pitch in bf16 for wmma tiles
}

typedef unsigned long long ull;

// ---------------- device scratch (allocation-free) ----------------
__device__ float g_xn1 [kBS * kD];
__device__ float g_xn2 [kBS * kD];
__device__ float g_xcur[kBS * kD];
__device__ float g_kvbuf[(size_t)kBS * 256];              // packed [token][k(128)|v(128)]
__device__ float g_kvbias[256];
__device__ int   g_cntA [kB * kEA];
__device__ int   g_listA[kB * kEA * kS];
__device__ float g_gateA[kB * kEA * kS];
__device__ float g_qg  [(size_t)kB * kEA * kS * kHD];
__device__ float g_ctxg[(size_t)kB * kEA * kS * kHD];
__device__ int   g_cntF [kEF];
__device__ int   g_listF[kEF * kBS];
__device__ float g_gateF[kEF * kBS];
// bf16 hi/lo split activation buffers
__device__ __nv_bfloat16 g_xn1h[(size_t)kBS * kD];
__device__ __nv_bfloat16 g_xn1l[(size_t)kBS * kD];
__device__ __nv_bfloat16 g_xn2h[(size_t)kBS * kD];
__device__ __nv_bfloat16 g_xn2l[(size_t)kBS * kD];
__device__ __nv_bfloat16 g_ctxh[(size_t)kB * kEA * kS * kHD];
__device__ __nv_bfloat16 g_ctxl[(size_t)kB * kEA * kS * kHD];
__device__ __nv_bfloat16 g_hh [(size_t)kEF * kBS * kFH];
__device__ __nv_bfloat16 g_hl [(size_t)kEF * kBS * kFH];
// bf16 hi/lo transposed weights
__device__ __nv_bfloat16 g_w1th[(size_t)kEF * kFH * kD];  // [e][512][1024]
__device__ __nv_bfloat16 g_w1tl[(size_t)kEF * kFH * kD];
__device__ __nv_bfloat16 g_w2th[(size_t)kEF * kD * kFH];  // [e][1024][512]
__device__ __nv_bfloat16 g_w2tl[(size_t)kEF * kD * kFH];
__device__ __nv_bfloat16 g_qwth[(size_t)kEA * kHD * kD];  // [e][128][1024]
__device__ __nv_bfloat16 g_qwtl[(size_t)kEA * kHD * kD];
__device__ __nv_bfloat16 g_owth[(size_t)kEA * kD * kHD];  // [e][1024][128]
__device__ __nv_bfloat16 g_owtl[(size_t)kEA * kD * kHD];
__device__ __nv_bfloat16 g_kvth[(size_t)256 * kD];        // [256][1024] (k rows, then v rows)
__device__ __nv_bfloat16 g_kvtl[(size_t)256 * kD];

// ---------------- small utility kernels ----------------
__global__ void zero_cnts_kernel() {
    int i = threadIdx.x;
    if (i < kB * kEA) g_cntA[i] = 0;
    if (i < kEF)      g_cntF[i] = 0;
}

__global__ void pack_kvbias_kernel(const float* __restrict__ kb, const float* __restrict__ vb) {
    int i = threadIdx.x;
    g_kvbias[i] = (i < 128) ? kb[i] : vb[i - 128];
}

__global__ void copy_kernel(const float* __restrict__ in, float* __restrict__ out, int n) {
    int n4 = n >> 2;
    for (int i = blockIdx.x * blockDim.x + threadIdx.x; i < n4; i += gridDim.x * blockDim.x)
        ((float4*)out)[i] = ((const float4*)in)[i];
}

// f32 -> bf16 hi/lo split (same layout)
__global__ void split_rows_kernel(const float* __restrict__ in,
                                  __nv_bfloat16* __restrict__ hi,
                                  __nv_bfloat16* __restrict__ lo, int n)
{
    int n4 = n >> 2;
    for (int i = blockIdx.x * blockDim.x + threadIdx.x; i < n4; i += gridDim.x * blockDim.x) {
        float4 v = ((const float4*)in)[i];
        __nv_bfloat16 h0 = __float2bfloat16(v.x), h1 = __float2bfloat16(v.y);
        __nv_bfloat16 h2 = __float2bfloat16(v.z), h3 = __float2bfloat16(v.w);
        __nv_bfloat162 H0; H0.x = h0; H0.y = h1;
        __nv_bfloat162 H1; H1.x = h2; H1.y = h3;
        __nv_bfloat162 L0, L1;
        L0.x = __float2bfloat16(v.x - __bfloat162float(h0));
        L0.y = __float2bfloat16(v.y - __bfloat162float(h1));
        L1.x = __float2bfloat16(v.z - __bfloat162float(h2));
        L1.y = __float2bfloat16(v.w - __bfloat162float(h3));
        ((__nv_bfloat162*)hi)[2 * i]     = H0;
        ((__nv_bfloat162*)hi)[2 * i + 1] = H1;
        ((__nv_bfloat162*)lo)[2 * i]     = L0;
        ((__nv_bfloat162*)lo)[2 * i + 1] = L1;
    }
}

// [E][K][N] f32 -> [E][N][K] bf16 hi/lo (transpose + split); E via blockIdx.z
__global__ void transp_split_kernel(const float* __restrict__ in,
                                    __nv_bfloat16* __restrict__ oh,
                                    __nv_bfloat16* __restrict__ ol,
                                    int K, int N)
{
    __shared__ float t[32][33];
    int e  = blockIdx.z;
    int nb = blockIdx.x * 32, kb = blockIdx.y * 32;
    int tx = threadIdx.x, ty = threadIdx.y;
    const float* ie = in + (size_t)e * K * N;
    for (int i = ty; i < 32; i += 8)
        t[i][tx] = ie[(size_t)(kb + i) * N + nb + tx];
    __syncthreads();
    size_t ob = (size_t)e * N * K;
    for (int j = ty; j < 32; j += 8) {
        float v = t[tx][j];
        __nv_bfloat16 h = __float2bfloat16(v);
        size_t o = ob + (size_t)(nb + j) * K + kb + tx;
        oh[o] = h;
        ol[o] = __float2bfloat16(v - __bfloat162float(h));
    }
}

// ---------------- fused LayerNorm + top-2 router ----------------
template <int E>
__global__ __launch_bounds__(256)
void ln_gate_kernel(const float* __restrict__ x,
                    const float* __restrict__ w,
                    const float* __restrict__ bvec,
                    const float* __restrict__ gw,   // [D, E] row-major
                    float* __restrict__ xn,
                    int* __restrict__ cnt,
                    int* __restrict__ list,
                    float* __restrict__ gates,
                    int cap, int perBatch)
{
    __shared__ __align__(16) float xs[kD];
    __shared__ float red1[8], red2[8];
    __shared__ float logits[E];
    __shared__ float s_mu, s_rstd;

    int t    = blockIdx.x;
    int tid  = threadIdx.x;
    int lane = tid & 31, wid = tid >> 5;

    const float4* xin = (const float4*)(x + (size_t)t * kD);
    float4* xs4 = (float4*)xs;
    float s = 0.f, ss = 0.f;
    for (int i = tid; i < kD / 4; i += 256) {
        float4 v = xin[i];
        xs4[i] = v;
        s  += v.x + v.y + v.z + v.w;
        ss += v.x * v.x + v.y * v.y + v.z * v.z + v.w * v.w;
    }
    #pragma unroll
    for (int o = 16; o; o >>= 1) {
        s  += __shfl_xor_sync(~0u, s, o);
        ss += __shfl_xor_sync(~0u, ss, o);
    }
    if (lane == 0) { red1[wid] = s; red2[wid] = ss; }
    __syncthreads();
    if (tid == 0) {
        float S1 = 0.f, S2 = 0.f;
        #pragma unroll
        for (int i = 0; i < 8; i++) { S1 += red1[i]; S2 += red2[i]; }
        float mu  = S1 / kD;
        float var = S2 / kD - mu * mu;
        s_mu = mu; s_rstd = rsqrtf(var + kEPS);
    }
    __syncthreads();
    float mu = s_mu, rstd = s_rstd;
    for (int i = tid; i < kD; i += 256) {
        float v = (xs[i] - mu) * rstd * w[i] + bvec[i];
        xs[i] = v;
        xn[(size_t)t * kD + i] = v;
    }
    __syncthreads();

    for (int e = wid; e < E; e += 8) {
        float acc = 0.f;
        for (int d = lane; d < kD; d += 32) acc += xs[d] * gw[d * E + e];
        #pragma unroll
        for (int o = 16; o; o >>= 1) acc += __shfl_xor_sync(~0u, acc, o);
        if (lane == 0) logits[e] = acc;
    }
    __syncthreads();

    if (tid == 0) {
        int e0 = 0; float v0 = logits[0];
        #pragma unroll
        for (int e = 1; e < E; e++) if (logits[e] > v0) { v0 = logits[e]; e0 = e; }
        int e1 = -1; float v1 = -3.4e38f;
        #pragma unroll
        for (int e = 0; e < E; e++) {
            if (e == e0) continue;
            if (logits[e] > v1) { v1 = logits[e]; e1 = e; }
        }
        float a1  = __expf(v1 - v0);
        float inv = 1.f / (1.f + a1);
        float g0 = inv, g1 = a1 * inv;
        int bb = perBatch ? (t / kS) : 0;
        int grp0 = bb * E + e0;
        int p0 = atomicAdd(&cnt[grp0], 1);
        list[grp0 * cap + p0] = t; gates[grp0 * cap + p0] = g0;
        int grp1 = bb * E + e1;
        int p1 = atomicAdd(&cnt[grp1], 1);
        list[grp1 * cap + p1] = t; gates[grp1 * cap + p1] = g1;
    }
}

// ---------------- packed f32x2 helpers ----------------
__device__ __forceinline__ void fma2(ull& d, ull a, ull b) {
    asm("fma.rn.f32x2 %0, %1, %2, %0;" : "+l"(d) : "l"(a), "l"(b));
}
__device__ __forceinline__ void mul2(ull& d, ull a, ull b) {
    asm("mul.rn.f32x2 %0, %1, %2;" : "=l"(d) : "l"(a), "l"(b));
}
__device__ __forceinline__ ull pack_dup(float a) {
    ull r;
    asm("mov.b64 %0, {%1, %1};" : "=l"(r) : "f"(a));
    return r;
}
__device__ __forceinline__ float2 unpack2(ull v) {
    float2 r;
    asm("mov.b64 {%0, %1}, %2;" : "=f"(r.x), "=f"(r.y) : "l"(v));
    return r;
}

// ---------------- warp-MMA (HMMA bf16) ----------------
__device__ __forceinline__ void mma16816(float* c, const unsigned* a, const unsigned* b) {
    asm volatile(
        "mma.sync.aligned.m16n8k16.row.col.f32.bf16.bf16.f32 "
        "{%0,%1,%2,%3}, {%4,%5,%6,%7}, {%8,%9}, {%0,%1,%2,%3};"
        : "+f"(c[0]), "+f"(c[1]), "+f"(c[2]), "+f"(c[3])
        : "r"(a[0]), "r"(a[1]), "r"(a[2]), "r"(a[3]), "r"(b[0]), "r"(b[1]));
}

// ---------------- generic grouped HMMA GEMM ----------------
// CTA tile 128x128, BK=32, 8 warps (2m x 4n -> 64x32 warp tiles).
// bf16 hi/lo split: acc += Ah*Bh + Ah*Bl + Al*Bh.
// OMODE 0: out f32 at grouped (or dense) rows, val = (acc+bias)*alpha
// OMODE 1: relu(acc+bias) -> bf16 hi/lo to outH/outL at grouped rows
// OMODE 2: atomicAdd(outF[token], gate*(acc+bias))
// DENSE: cnt ignored, M=Mfixed, A row = global row index.
template <int OMODE, bool GATHER_A, bool DENSE>
__global__ __launch_bounds__(256)
void wmma_gemm_kernel(const __nv_bfloat16* __restrict__ Ah,
                      const __nv_bfloat16* __restrict__ Al,
                      const __nv_bfloat16* __restrict__ Bh,   // [E][N][K]
                      const __nv_bfloat16* __restrict__ Bl,
                      const float* __restrict__ bias,         // [E][N]
                      float* __restrict__ outF,
                      __nv_bfloat16* __restrict__ outH,
                      __nv_bfloat16* __restrict__ outL,
                      const int* __restrict__ list,
                      const float* __restrict__ gates,
                      const int* __restrict__ cnt,
                      int Mfixed, int N, int K, int cap, int wMod, float alpha)
{
    int g = blockIdx.z;
    int M = DENSE ? Mfixed : cnt[g];
    int e = DENSE ? 0 : (g % wMod);
    int row0 = blockIdx.x * 128;
    if (row0 >= M) return;
    int col0 = blockIdx.y * 128;

    extern __shared__ __align__(16) __nv_bfloat16 sm[];
    __shared__ int   rowTok[128];
    __shared__ float rowG[128];

    int tid  = threadIdx.x;
    int wid  = tid >> 5;
    int lane = tid & 31;
    int gq   = lane >> 2;
    int tq   = lane & 3;

    if (!DENSE && tid < 128) {
        int r = row0 + tid;
        rowTok[tid] = (r < M) ? list[(size_t)g * cap + r] : 0;
        rowG[tid]   = (r < M) ? gates[(size_t)g * cap + r] : 0.f;
    }
    __syncthreads();

    auto tilep = [&](int buf, int t) -> __nv_bfloat16* {
        return sm + ((size_t)(buf * 4 + t)) * (128 * kPAD);
    };

    auto loadChunk = [&](int c, int buf) {
        int k0 = c * 32;
        #pragma unroll
        for (int i = 0; i < 2; i++) {
            int idx = tid + 256 * i;
            int r   = idx >> 2;
            int u   = idx & 3;
            uint4 vh = make_uint4(0, 0, 0, 0), vl = make_uint4(0, 0, 0, 0);
            int gr = row0 + r;
            if (gr < M) {
                size_t ar;
                if (GATHER_A)   ar = (size_t)rowTok[r];
                else if (DENSE) ar = (size_t)gr;
                else            ar = (size_t)g * cap + gr;
                vh = *(const uint4*)(Ah + ar * K + k0 + u * 8);
                vl = *(const uint4*)(Al + ar * K + k0 + u * 8);
            }
            *(uint4*)(tilep(buf, 0) + r * kPAD + u * 8) = vh;
            *(uint4*)(tilep(buf, 1) + r * kPAD + u * 8) = vl;
            size_t br = (size_t)e * N + col0 + r;
            uint4 bh = *(const uint4*)(Bh + br * K + k0 + u * 8);
            uint4 bl = *(const uint4*)(Bl + br * K + k0 + u * 8);
            *(uint4*)(tilep(buf, 2) + r * kPAD + u * 8) = bh;
            *(uint4*)(tilep(buf, 3) + r * kPAD + u * 8) = bl;
        }
    };

    float acc[4][4][4];
    #pragma unroll
    for (int mf = 0; mf < 4; mf++)
        #pragma unroll
        for (int nf = 0; nf < 4; nf++)
            #pragma unroll
            for (int q = 0; q < 4; q++) acc[mf][nf][q] = 0.f;

    int warpM = (wid & 1) * 64;
    int warpN = (wid >> 1) * 32;
    int T = K >> 5;

    loadChunk(0, 0);
    __syncthreads();

    for (int c = 0; c < T; c++) {
        int buf = c & 1;
        if (c + 1 < T) loadChunk(c + 1, buf ^ 1);

        const __nv_bfloat16* sAh = tilep(buf, 0);
        const __nv_bfloat16* sAl = tilep(buf, 1);
        const __nv_bfloat16* sBh = tilep(buf, 2);
        const __nv_bfloat16* sBl = tilep(buf, 3);

        #pragma unroll
        for (int ks = 0; ks < 2; ks++) {
            int k0 = ks * 16;
            unsigned ah[4][4], al[4][4], bh[4][2], bl[4][2];
            #pragma unroll
            for (int mf = 0; mf < 4; mf++) {
                int rb = warpM + mf * 16 + gq;
                ah[mf][0] = *(const unsigned*)(sAh + rb * kPAD + k0 + 2 * tq);
                ah[mf][1] = *(const unsigned*)(sAh + (rb + 8) * kPAD + k0 + 2 * tq);
                ah[mf][2] = *(const unsigned*)(sAh + rb * kPAD + k0 + 2 * tq + 8);
                ah[mf][3] = *(const unsigned*)(sAh + (rb + 8) * kPAD + k0 + 2 * tq + 8);
                al[mf][0] = *(const unsigned*)(sAl + rb * kPAD + k0 + 2 * tq);
                al[mf][1] = *(const unsigned*)(sAl + (rb + 8) * kPAD + k0 + 2 * tq);
                al[mf][2] = *(const unsigned*)(sAl + rb * kPAD + k0 + 2 * tq + 8);
                al[mf][3] = *(const unsigned*)(sAl + (rb + 8) * kPAD + k0 + 2 * tq + 8);
            }
            #pragma unroll
            for (int nf = 0; nf < 4; nf++) {
                int nb = warpN + nf * 8 + gq;
                bh[nf][0] = *(const unsigned*)(sBh + nb * kPAD + k0 + 2 * tq);
                bh[nf][1] = *(const unsigned*)(sBh + nb * kPAD + k0 + 2 * tq + 8);
                bl[nf][0] = *(const unsigned*)(sBl + nb * kPAD + k0 + 2 * tq);
                bl[nf][1] = *(const unsigned*)(sBl + nb * kPAD + k0 + 2 * tq + 8);
            }
            #pragma unroll
            for (int mf = 0; mf < 4; mf++)
                #pragma unroll
                for (int nf = 0; nf < 4; nf++) {
                    mma16816(acc[mf][nf], ah[mf], bh[nf]);
                    mma16816(acc[mf][nf], ah[mf], bl[nf]);
                    mma16816(acc[mf][nf], al[mf], bh[nf]);
                }
        }
        __syncthreads();
    }

    // ---- epilogue ----
    const float* bg = bias + (size_t)e * N;
    #pragma unroll
    for (int mf = 0; mf < 4; mf++) {
        #pragma unroll
        for (int half = 0; half < 2; half++) {
            int rloc = warpM + mf * 16 + gq + half * 8;
            int gr   = row0 + rloc;
            if (gr >= M) continue;
            #pragma unroll
            for (int nf = 0; nf < 4; nf++) {
                int ncol = col0 + warpN + nf * 8 + 2 * tq;
                float v0 = acc[mf][nf][half * 2 + 0] + bg[ncol];
                float v1 = acc[mf][nf][half * 2 + 1] + bg[ncol + 1];
                if (OMODE == 0) {
                    size_t orow = DENSE ? (size_t)gr : (size_t)g * cap + gr;
                    float2 v; v.x = v0 * alpha; v.y = v1 * alpha;
                    *(float2*)(outF + orow * N + ncol) = v;
                } else if (OMODE == 1) {
                    v0 = fmaxf(v0, 0.f);
                    v1 = fmaxf(v1, 0.f);
                    __nv_bfloat16 h0 = __float2bfloat16(v0);
                    __nv_bfloat16 h1 = __float2bfloat16(v1);
                    __nv_bfloat162 H; H.x = h0; H.y = h1;
                    __nv_bfloat162 L;
                    L.x = __float2bfloat16(v0 - __bfloat162float(h0));
                    L.y = __float2bfloat16(v1 - __bfloat162float(h1));
                    size_t off = ((size_t)g * cap + gr) * N + ncol;
                    *(__nv_bfloat162*)(outH + off) = H;
                    *(__nv_bfloat162*)(outL + off) = L;
                } else {
                    int tok = rowTok[rloc];
                    float gt = rowG[rloc];
                    float* dst = outF + (size_t)tok * N + ncol;
                    atomicAdd(dst,     gt * v0);
                    atomicAdd(dst + 1, gt * v1);
                }
            }
        }
    }
}

// ---------------- routed attention core (QT=32, 512 threads, f32x2) ----------------
// smem float offsets
namespace {
constexpr int QT    = 32;
constexpr int KT    = 16;
constexpr int KPADF = 132;
constexpr int OFF_QS   = 0;                       // 32*128
constexpr int OFF_RELQ = OFF_QS + QT * kHD;       // 32*132
constexpr int OFF_KS   = OFF_RELQ + QT * KPADF;   // 16*132
constexpr int OFF_VS   = OFF_KS + KT * KPADF;     // 16*132
constexpr int OFF_PS   = OFF_VS + KT * KPADF;     // 32*16
constexpr int OFF_QPOS = OFF_PS + QT * KT;        // 32 ints
constexpr int ATTN_SMEM_BYTES = (OFF_QPOS + QT) * 4;
}

__global__ __launch_bounds__(512)
void attn_kernel(const float* __restrict__ rel_table)
{
    extern __shared__ __align__(16) float smf[];
    float* qs   = smf + OFF_QS;     // [QT][kHD]
    float* relq = smf + OFF_RELQ;   // [QT][KPADF]
    float* ks   = smf + OFF_KS;     // [KT][KPADF]
    float* vs   = smf + OFF_VS;     // [KT][KPADF]
    float* ps   = smf + OFF_PS;     // [QT][KT]
    int*   qpos = (int*)(smf + OFF_QPOS);

    int g  = blockIdx.x;            // b*EA + e
    int b  = g / kEA;
    int qt = blockIdx.y;
    int cnt  = g_cntA[g];
    int base = qt * QT;
    if (base >= cnt) return;

    int tid = threadIdx.x;

    // load Q tile (zero-padded)
    for (int i = tid; i < QT * kHD / 4; i += 512) {
        int qi = i >> 5, h4 = i & 31;
        float4 v = make_float4(0.f, 0.f, 0.f, 0.f);
        if (base + qi < cnt)
            v = ((const float4*)&g_qg[((size_t)g * kS + base + qi) * kHD])[h4];
        ((float4*)(qs + qi * kHD))[h4] = v;
    }
    if (tid < QT) {
        int t = (base + tid < cnt) ? g_listA[g * kS + base + tid] : 0;
        qpos[tid] = t & (kS - 1);
    }
    __syncthreads();

    // rel bias per query: relq[qi][r] = q . rel_table[r]
    for (int idx = tid; idx < QT * kR; idx += 512) {
        int qi = idx / kR, r = idx % kR;
        const float4* q4 = (const float4*)(qs + qi * kHD);
        const float4* t4 = (const float4*)&rel_table[(size_t)r * kHD];
        float s = 0.f;
        #pragma unroll
        for (int h = 0; h < kHD / 4; h++) {
            float4 a = q4[h], c = t4[h];
            s += a.x * c.x + a.y * c.y + a.z * c.z + a.w * c.w;
        }
        relq[qi * KPADF + r] = s;
    }
    __syncthreads();

    int qi = tid >> 4;              // 0..31
    int li = tid & 15;
    float m = -1e30f, l = 0.f;
    ull acc2[4];
    #pragma unroll
    for (int t = 0; t < 4; t++) acc2[t] = 0ull;
    int myq = qpos[qi];
    const float4* q4 = (const float4*)(qs + qi * kHD);

    for (int c0 = 0; c0 < kS; c0 += KT) {
        // load packed kv rows: 16 tokens x 256 floats
        for (int i = tid; i < KT * 64; i += 512) {
            int kk = i >> 6, h4 = i & 63;
            float4 v = ((const float4*)&g_kvbuf[((size_t)b * kS + c0 + kk) * 256])[h4];
            if (h4 < 32) ((float4*)(ks + kk * KPADF))[h4] = v;
            else         ((float4*)(vs + kk * KPADF))[h4 - 32] = v;
        }
        __syncthreads();

        // score via f32x2
        const float4* k4 = (const float4*)(ks + li * KPADF);
        ull s2a = 0ull, s2b = 0ull;
        #pragma unroll
        for (int h = 0; h < kHD / 4; h++) {
            float4 a = q4[h], kv = k4[h];
            fma2(s2a, ((const ull*)&a)[0], ((const ull*)&kv)[0]);
            fma2(s2b, ((const ull*)&a)[1], ((const ull*)&kv)[1]);
        }
        float2 r1 = unpack2(s2a), r2 = unpack2(s2b);
        float s = r1.x + r1.y + r2.x + r2.y;
        int rel = c0 + li - myq;
        rel = min(max(rel, -kMAXP), kMAXP) + kMAXP;
        s += relq[qi * KPADF + rel];

        // online softmax within 16-lane group
        float cm = s;
        #pragma unroll
        for (int o = 8; o; o >>= 1) cm = fmaxf(cm, __shfl_xor_sync(~0u, cm, o));
        float mn = fmaxf(m, cm);
        float scale = __expf(m - mn);
        float p = __expf(s - mn);
        float psum = p;
        #pragma unroll
        for (int o = 8; o; o >>= 1) psum += __shfl_xor_sync(~0u, psum, o);
        l = l * scale + psum;
        m = mn;
        ps[qi * KT + li] = p;
        __syncwarp();

        ull sc2 = pack_dup(scale);
        #pragma unroll
        for (int t = 0; t < 4; t++) mul2(acc2[t], acc2[t], sc2);
        #pragma unroll
        for (int kk = 0; kk < KT; kk++) {
            ull pv = pack_dup(ps[qi * KT + kk]);
            const ull* v2 = (const ull*)(vs + kk * KPADF + li * 8);
            fma2(acc2[0], pv, v2[0]);
            fma2(acc2[1], pv, v2[1]);
            fma2(acc2[2], pv, v2[2]);
            fma2(acc2[3], pv, v2[3]);
        }
        __syncthreads();
    }

    if (base + qi < cnt) {
        float inv = 1.f / l;
        float* dst = &g_ctxg[((size_t)g * kS + base + qi) * kHD + li * 8];
        #pragma unroll
        for (int t = 0; t < 4; t++) {
            float2 v = unpack2(acc2[t]);
            dst[2 * t]     = v.x * inv;
            dst[2 * t + 1] = v.y * inv;
        }
    }
}

// ---------------- launch ----------------
extern "C" void kernel_launch(void* const* d_in, const int* in_sizes, int n_in,
                              void* d_out, int out_size)
{
    const float* src   = (const float*)d_in[0];
    const float* ln1_w = (const float*)d_in[1];
    const float* ln1_b = (const float*)d_in[2];
    const float* ln2_w = (const float*)d_in[3];
    const float* ln2_b = (const float*)d_in[4];
    const float* agw   = (const float*)d_in[5];
    const float* q_w   = (const float*)d_in[6];
    const float* q_b   = (const float*)d_in[7];
    const float* k_w   = (const float*)d_in[8];
    const float* k_b   = (const float*)d_in[9];
    const float* v_w   = (const float*)d_in[10];
    const float* v_b   = (const float*)d_in[11];
    const float* o_w   = (const float*)d_in[12];
    const float* o_b   = (const float*)d_in[13];
    const float* rel   = (const float*)d_in[14];
    const float* fgw   = (const float*)d_in[15];
    const float* w1    = (const float*)d_in[16];
    const float* b1    = (const float*)d_in[17];
    const float* w2    = (const float*)d_in[18];
    const float* b2    = (const float*)d_in[19];
    float* out = (float*)d_out;

    float *xn1, *xn2, *xcur, *kvb, *kvbias, *qg, *ctxg, *gateA, *gateF;
    int *cntA, *listA, *cntF, *listF;
    __nv_bfloat16 *xn1h, *xn1l, *xn2h, *xn2l, *ctxh, *ctxl, *hh, *hl;
    __nv_bfloat16 *w1th, *w1tl, *w2th, *w2tl, *qwth, *qwtl, *owth, *owtl, *kvth, *kvtl;
    cudaGetSymbolAddress((void**)&xn1,    g_xn1);
    cudaGetSymbolAddress((void**)&xn2,    g_xn2);
    cudaGetSymbolAddress((void**)&xcur,   g_xcur);
    cudaGetSymbolAddress((void**)&kvb,    g_kvbuf);
    cudaGetSymbolAddress((void**)&kvbias, g_kvbias);
    cudaGetSymbolAddress((void**)&qg,     g_qg);
    cudaGetSymbolAddress((void**)&ctxg,   g_ctxg);
    cudaGetSymbolAddress((void**)&gateA,  g_gateA);
    cudaGetSymbolAddress((void**)&gateF,  g_gateF);
    cudaGetSymbolAddress((void**)&cntA,   g_cntA);
    cudaGetSymbolAddress((void**)&listA,  g_listA);
    cudaGetSymbolAddress((void**)&cntF,   g_cntF);
    cudaGetSymbolAddress((void**)&listF,  g_listF);
    cudaGetSymbolAddress((void**)&xn1h,   g_xn1h);
    cudaGetSymbolAddress((void**)&xn1l,   g_xn1l);
    cudaGetSymbolAddress((void**)&xn2h,   g_xn2h);
    cudaGetSymbolAddress((void**)&xn2l,   g_xn2l);
    cudaGetSymbolAddress((void**)&ctxh,   g_ctxh);
    cudaGetSymbolAddress((void**)&ctxl,   g_ctxl);
    cudaGetSymbolAddress((void**)&hh,     g_hh);
    cudaGetSymbolAddress((void**)&hl,     g_hl);
    cudaGetSymbolAddress((void**)&w1th,   g_w1th);
    cudaGetSymbolAddress((void**)&w1tl,   g_w1tl);
    cudaGetSymbolAddress((void**)&w2th,   g_w2th);
    cudaGetSymbolAddress((void**)&w2tl,   g_w2tl);
    cudaGetSymbolAddress((void**)&qwth,   g_qwth);
    cudaGetSymbolAddress((void**)&qwtl,   g_qwtl);
    cudaGetSymbolAddress((void**)&owth,   g_owth);
    cudaGetSymbolAddress((void**)&owtl,   g_owtl);
    cudaGetSymbolAddress((void**)&kvth,   g_kvth);
    cudaGetSymbolAddress((void**)&kvtl,   g_kvtl);

    constexpr int kWmmaSmem = 2 * 4 * 128 * kPAD * 2;   // 81920
    cudaFuncSetAttribute(wmma_gemm_kernel<0, true,  false>,
                         cudaFuncAttributeMaxDynamicSharedMemorySize, kWmmaSmem);
    cudaFuncSetAttribute(wmma_gemm_kernel<0, false, true>,
                         cudaFuncAttributeMaxDynamicSharedMemorySize, kWmmaSmem);
    cudaFuncSetAttribute(wmma_gemm_kernel<1, true,  false>,
                         cudaFuncAttributeMaxDynamicSharedMemorySize, kWmmaSmem);
    cudaFuncSetAttribute(wmma_gemm_kernel<2, false, false>,
                         cudaFuncAttributeMaxDynamicSharedMemorySize, kWmmaSmem);
    cudaFuncSetAttribute(attn_kernel,
                         cudaFuncAttributeMaxDynamicSharedMemorySize, ATTN_SMEM_BYTES);

    zero_cnts_kernel<<<1, 64>>>();
    pack_kvbias_kernel<<<1, 256>>>(k_b, v_b);

    // ---- weight transposes + splits (activation-independent) ----
    transp_split_kernel<<<dim3(kFH / 32, kD / 32, kEF), dim3(32, 8)>>>(w1, w1th, w1tl, kD, kFH);
    transp_split_kernel<<<dim3(kD / 32, kFH / 32, kEF), dim3(32, 8)>>>(w2, w2th, w2tl, kFH, kD);
    transp_split_kernel<<<dim3(kHD / 32, kD / 32, kEA), dim3(32, 8)>>>(q_w, qwth, qwtl, kD, kHD);
    transp_split_kernel<<<dim3(kD / 32, kHD / 32, kEA), dim3(32, 8)>>>(o_w, owth, owtl, kHD, kD);
    transp_split_kernel<<<dim3(kHD / 32, kD / 32, 1),  dim3(32, 8)>>>(k_w, kvth, kvtl, kD, kHD);
    transp_split_kernel<<<dim3(kHD / 32, kD / 32, 1),  dim3(32, 8)>>>(
        v_w, kvth + (size_t)128 * kD, kvtl + (size_t)128 * kD, kD, kHD);

    // ---- LN1 + attention router; split xn1 ----
    ln_gate_kernel<kEA><<<kBS, 256>>>(src, ln1_w, ln1_b, agw, xn1,
                                      cntA, listA, gateA, kS, 1);
    split_rows_kernel<<<512, 256>>>(xn1, xn1h, xn1l, kBS * kD);

    // ---- fused k+v projection (dense HMMA, N=256) -> packed kv ----
    wmma_gemm_kernel<0, false, true><<<dim3(kBS / 128, 2, 1), 256, kWmmaSmem>>>(
        xn1h, xn1l, kvth, kvtl, kvbias, kvb, nullptr, nullptr,
        nullptr, nullptr, nullptr, kBS, 256, kD, 0, 1, 1.f);

    // ---- routed q projection (HMMA gather, alpha = HD^-0.5) ----
    wmma_gemm_kernel<0, true, false><<<dim3(kS / 128, 1, kB * kEA), 256, kWmmaSmem>>>(
        xn1h, xn1l, qwth, qwtl, q_b, qg, nullptr, nullptr,
        listA, gateA, cntA, 0, kHD, kD, kS, kEA, kQScale);

    // ---- attention core ----
    attn_kernel<<<dim3(kB * kEA, kS / QT), 512, ATTN_SMEM_BYTES>>>(rel);

    // ---- split ctx; o-projection scatter into residual ----
    split_rows_kernel<<<512, 256>>>(ctxg, ctxh, ctxl, kB * kEA * kS * kHD);
    copy_kernel<<<512, 256>>>(src, xcur, kBS * kD);
    wmma_gemm_kernel<2, false, false><<<dim3(kS / 128, kD / 128, kB * kEA), 256, kWmmaSmem>>>(
        ctxh, ctxl, owth, owtl, o_b, xcur, nullptr, nullptr,
        listA, gateA, cntA, 0, kD, kHD, kS, kEA, 1.f);

    // ---- LN2 + FFN router; split xn2 ----
    ln_gate_kernel<kEF><<<kBS, 256>>>(xcur, ln2_w, ln2_b, fgw, xn2,
                                      cntF, listF, gateF, kBS, 0);
    split_rows_kernel<<<512, 256>>>(xn2, xn2h, xn2l, kBS * kD);

    // ---- routed FFN up-proj + relu (HMMA) ----
    wmma_gemm_kernel<1, true, false><<<dim3(kBS / 128, kFH / 128, kEF), 256, kWmmaSmem>>>(
        xn2h, xn2l, w1th, w1tl, b1, nullptr, hh, hl,
        listF, gateF, cntF, 0, kFH, kD, kBS, kEF, 1.f);

    // ---- residual + FFN down-proj scatter (HMMA) ----
    copy_kernel<<<512, 256>>>(xcur, out, kBS * kD);
    wmma_gemm_kernel<2, false, false><<<dim3(kBS / 128, kD / 128, kEF), 256, kWmmaSmem>>>(
        hh, hl, w2th, w2tl, b2, out, nullptr, nullptr,
        listF, gateF, cntF, 0, kD, kFH, kBS, kEF, 1.f);
}

// round 11
// speedup vs baseline: 1.6178x; 1.0866x over previous
#include <cuda_runtime.h>
#include <cuda_bf16.h>

// ---------------- problem constants ----------------
namespace {
constexpr int kD    = 1024;
constexpr int kHD   = 128;
constexpr int kEA   = 8;
constexpr int kEF   = 16;
constexpr int kFH   = 512;
constexpr int kMAXP = 64;
constexpr int kR    = 2 * kMAXP + 1;   // 129
constexpr int kB    = 4;
constexpr int kS    = 1024;
constexpr int kBS   = kB * kS;         // 4096
constexpr float kEPS = 1e-5f;
constexpr float kQScale = 0.08838834764831845f;   // 128^-0.5
constexpr int kPAD = 40;               // smem row pitch in bf16 for wmma tiles
}

typedef unsigned long long ull;

// ---------------- device scratch (allocation-free) ----------------
__device__ float g_xcur[kBS * kD];
__device__ float g_kvbuf[(size_t)kBS * 256];              // packed [token][k(128)|v(128)]
__device__ float g_kvbias[256];
__device__ int   g_cntA [kB * kEA];
__device__ int   g_listA[kB * kEA * kS];
__device__ float g_gateA[kB * kEA * kS];
__device__ float g_qg  [(size_t)kB * kEA * kS * kHD];
__device__ int   g_cntF [kEF];
__device__ int   g_listF[kEF * kBS];
__device__ float g_gateF[kEF * kBS];
// bf16 hi/lo split activation buffers
__device__ __nv_bfloat16 g_xn1h[(size_t)kBS * kD];
__device__ __nv_bfloat16 g_xn1l[(size_t)kBS * kD];
__device__ __nv_bfloat16 g_xn2h[(size_t)kBS * kD];
__device__ __nv_bfloat16 g_xn2l[(size_t)kBS * kD];
__device__ __nv_bfloat16 g_ctxh[(size_t)kB * kEA * kS * kHD];
__device__ __nv_bfloat16 g_ctxl[(size_t)kB * kEA * kS * kHD];
__device__ __nv_bfloat16 g_hh [(size_t)kEF * kBS * kFH];
__device__ __nv_bfloat16 g_hl [(size_t)kEF * kBS * kFH];
// bf16 hi/lo transposed weights
__device__ __nv_bfloat16 g_w1th[(size_t)kEF * kFH * kD];
__device__ __nv_bfloat16 g_w1tl[(size_t)kEF * kFH * kD];
__device__ __nv_bfloat16 g_w2th[(size_t)kEF * kD * kFH];
__device__ __nv_bfloat16 g_w2tl[(size_t)kEF * kD * kFH];
__device__ __nv_bfloat16 g_qwth[(size_t)kEA * kHD * kD];
__device__ __nv_bfloat16 g_qwtl[(size_t)kEA * kHD * kD];
__device__ __nv_bfloat16 g_owth[(size_t)kEA * kD * kHD];
__device__ __nv_bfloat16 g_owtl[(size_t)kEA * kD * kHD];
__device__ __nv_bfloat16 g_kvth[(size_t)256 * kD];
__device__ __nv_bfloat16 g_kvtl[(size_t)256 * kD];

// ---------------- small utility kernels ----------------
__global__ void zero_cnts_kernel() {
    int i = threadIdx.x;
    if (i < kB * kEA) g_cntA[i] = 0;
    if (i < kEF)      g_cntF[i] = 0;
}

__global__ void pack_kvbias_kernel(const float* __restrict__ kb, const float* __restrict__ vb) {
    int i = threadIdx.x;
    g_kvbias[i] = (i < 128) ? kb[i] : vb[i - 128];
}

__global__ void copy_kernel(const float* __restrict__ in, float* __restrict__ out, int n) {
    int n4 = n >> 2;
    for (int i = blockIdx.x * blockDim.x + threadIdx.x; i < n4; i += gridDim.x * blockDim.x)
        ((float4*)out)[i] = ((const float4*)in)[i];
}

// [E][K][N] f32 -> [E][N][K] bf16 hi/lo (transpose + split); E via blockIdx.z
__global__ void transp_split_kernel(const float* __restrict__ in,
                                    __nv_bfloat16* __restrict__ oh,
                                    __nv_bfloat16* __restrict__ ol,
                                    int K, int N)
{
    __shared__ float t[32][33];
    int e  = blockIdx.z;
    int nb = blockIdx.x * 32, kb = blockIdx.y * 32;
    int tx = threadIdx.x, ty = threadIdx.y;
    const float* ie = in + (size_t)e * K * N;
    for (int i = ty; i < 32; i += 8)
        t[i][tx] = ie[(size_t)(kb + i) * N + nb + tx];
    __syncthreads();
    size_t ob = (size_t)e * N * K;
    for (int j = ty; j < 32; j += 8) {
        float v = t[tx][j];
        __nv_bfloat16 h = __float2bfloat16(v);
        size_t o = ob + (size_t)(nb + j) * K + kb + tx;
        oh[o] = h;
        ol[o] = __float2bfloat16(v - __bfloat162float(h));
    }
}

// ---------------- fused LayerNorm + top-2 router, bf16 hi/lo output ----------------
template <int E>
__global__ __launch_bounds__(256)
void ln_gate_kernel(const float* __restrict__ x,
                    const float* __restrict__ w,
                    const float* __restrict__ bvec,
                    const float* __restrict__ gw,   // [D, E] row-major
                    __nv_bfloat16* __restrict__ xnh,
                    __nv_bfloat16* __restrict__ xnl,
                    int* __restrict__ cnt,
                    int* __restrict__ list,
                    float* __restrict__ gates,
                    int cap, int perBatch)
{
    __shared__ __align__(16) float xs[kD];
    __shared__ float red1[8], red2[8];
    __shared__ float logits[E];
    __shared__ float s_mu, s_rstd;

    int t    = blockIdx.x;
    int tid  = threadIdx.x;
    int lane = tid & 31, wid = tid >> 5;

    const float4* xin = (const float4*)(x + (size_t)t * kD);
    float4* xs4 = (float4*)xs;
    float s = 0.f, ss = 0.f;
    for (int i = tid; i < kD / 4; i += 256) {
        float4 v = xin[i];
        xs4[i] = v;
        s  += v.x + v.y + v.z + v.w;
        ss += v.x * v.x + v.y * v.y + v.z * v.z + v.w * v.w;
    }
    #pragma unroll
    for (int o = 16; o; o >>= 1) {
        s  += __shfl_xor_sync(~0u, s, o);
        ss += __shfl_xor_sync(~0u, ss, o);
    }
    if (lane == 0) { red1[wid] = s; red2[wid] = ss; }
    __syncthreads();
    if (tid == 0) {
        float S1 = 0.f, S2 = 0.f;
        #pragma unroll
        for (int i = 0; i < 8; i++) { S1 += red1[i]; S2 += red2[i]; }
        float mu  = S1 / kD;
        float var = S2 / kD - mu * mu;
        s_mu = mu; s_rstd = rsqrtf(var + kEPS);
    }
    __syncthreads();
    float mu = s_mu, rstd = s_rstd;
    for (int i = tid; i < kD / 2; i += 256) {
        float v0 = (xs[2 * i]     - mu) * rstd * w[2 * i]     + bvec[2 * i];
        float v1 = (xs[2 * i + 1] - mu) * rstd * w[2 * i + 1] + bvec[2 * i + 1];
        xs[2 * i] = v0; xs[2 * i + 1] = v1;
        __nv_bfloat16 h0 = __float2bfloat16(v0);
        __nv_bfloat16 h1 = __float2bfloat16(v1);
        __nv_bfloat162 H; H.x = h0; H.y = h1;
        __nv_bfloat162 L;
        L.x = __float2bfloat16(v0 - __bfloat162float(h0));
        L.y = __float2bfloat16(v1 - __bfloat162float(h1));
        ((__nv_bfloat162*)(xnh + (size_t)t * kD))[i] = H;
        ((__nv_bfloat162*)(xnl + (size_t)t * kD))[i] = L;
    }
    __syncthreads();

    for (int e = wid; e < E; e += 8) {
        float acc = 0.f;
        for (int d = lane; d < kD; d += 32) acc += xs[d] * gw[d * E + e];
        #pragma unroll
        for (int o = 16; o; o >>= 1) acc += __shfl_xor_sync(~0u, acc, o);
        if (lane == 0) logits[e] = acc;
    }
    __syncthreads();

    if (tid == 0) {
        int e0 = 0; float v0 = logits[0];
        #pragma unroll
        for (int e = 1; e < E; e++) if (logits[e] > v0) { v0 = logits[e]; e0 = e; }
        int e1 = -1; float v1 = -3.4e38f;
        #pragma unroll
        for (int e = 0; e < E; e++) {
            if (e == e0) continue;
            if (logits[e] > v1) { v1 = logits[e]; e1 = e; }
        }
        float a1  = __expf(v1 - v0);
        float inv = 1.f / (1.f + a1);
        float g0 = inv, g1 = a1 * inv;
        int bb = perBatch ? (t / kS) : 0;
        int grp0 = bb * E + e0;
        int p0 = atomicAdd(&cnt[grp0], 1);
        list[grp0 * cap + p0] = t; gates[grp0 * cap + p0] = g0;
        int grp1 = bb * E + e1;
        int p1 = atomicAdd(&cnt[grp1], 1);
        list[grp1 * cap + p1] = t; gates[grp1 * cap + p1] = g1;
    }
}

// ---------------- packed f32x2 helpers ----------------
__device__ __forceinline__ void fma2(ull& d, ull a, ull b) {
    asm("fma.rn.f32x2 %0, %1, %2, %0;" : "+l"(d) : "l"(a), "l"(b));
}
__device__ __forceinline__ void mul2(ull& d, ull a, ull b) {
    asm("mul.rn.f32x2 %0, %1, %2;" : "=l"(d) : "l"(a), "l"(b));
}
__device__ __forceinline__ ull pack_dup(float a) {
    ull r;
    asm("mov.b64 %0, {%1, %1};" : "=l"(r) : "f"(a));
    return r;
}
__device__ __forceinline__ float2 unpack2(ull v) {
    float2 r;
    asm("mov.b64 {%0, %1}, %2;" : "=f"(r.x), "=f"(r.y) : "l"(v));
    return r;
}

// ---------------- warp-MMA (HMMA bf16) + ldmatrix ----------------
__device__ __forceinline__ void mma16816(float* c, const unsigned* a, const unsigned* b) {
    asm volatile(
        "mma.sync.aligned.m16n8k16.row.col.f32.bf16.bf16.f32 "
        "{%0,%1,%2,%3}, {%4,%5,%6,%7}, {%8,%9}, {%0,%1,%2,%3};"
        : "+f"(c[0]), "+f"(c[1]), "+f"(c[2]), "+f"(c[3])
        : "r"(a[0]), "r"(a[1]), "r"(a[2]), "r"(a[3]), "r"(b[0]), "r"(b[1]));
}
__device__ __forceinline__ void ldmx4(unsigned* r, unsigned addr) {
    asm volatile("ldmatrix.sync.aligned.m8n8.x4.shared.b16 {%0,%1,%2,%3}, [%4];"
                 : "=r"(r[0]), "=r"(r[1]), "=r"(r[2]), "=r"(r[3]) : "r"(addr));
}
__device__ __forceinline__ unsigned smem_u32(const void* p) {
    unsigned a;
    asm("{ .reg .u64 t; cvta.to.shared.u64 t, %1; cvt.u32.u64 %0, t; }" : "=r"(a) : "l"(p));
    return a;
}

// ---------------- generic grouped HMMA GEMM (ldmatrix fragments) ----------------
// CTA tile 128x128, BK=32, 8 warps (2m x 4n -> 64x32 warp tiles).
// bf16 hi/lo split: acc += Ah*Bh + Ah*Bl + Al*Bh.
// OMODE 0: out f32, val=(acc+bias)*alpha; OMODE 1: relu->bf16 hi/lo; OMODE 2: gated atomic scatter
template <int OMODE, bool GATHER_A, bool DENSE>
__global__ __launch_bounds__(256)
void wmma_gemm_kernel(const __nv_bfloat16* __restrict__ Ah,
                      const __nv_bfloat16* __restrict__ Al,
                      const __nv_bfloat16* __restrict__ Bh,   // [E][N][K]
                      const __nv_bfloat16* __restrict__ Bl,
                      const float* __restrict__ bias,         // [E][N]
                      float* __restrict__ outF,
                      __nv_bfloat16* __restrict__ outH,
                      __nv_bfloat16* __restrict__ outL,
                      const int* __restrict__ list,
                      const float* __restrict__ gates,
                      const int* __restrict__ cnt,
                      int Mfixed, int N, int K, int cap, int wMod, float alpha)
{
    int g = blockIdx.z;
    int M = DENSE ? Mfixed : cnt[g];
    int e = DENSE ? 0 : (g % wMod);
    int row0 = blockIdx.x * 128;
    if (row0 >= M) return;
    int col0 = blockIdx.y * 128;

    extern __shared__ __align__(16) __nv_bfloat16 sm[];
    __shared__ int   rowTok[128];
    __shared__ float rowG[128];

    int tid  = threadIdx.x;
    int wid  = tid >> 5;
    int lane = tid & 31;
    int gq   = lane >> 2;
    int tq   = lane & 3;

    if (!DENSE && tid < 128) {
        int r = row0 + tid;
        rowTok[tid] = (r < M) ? list[(size_t)g * cap + r] : 0;
        rowG[tid]   = (r < M) ? gates[(size_t)g * cap + r] : 0.f;
    }
    __syncthreads();

    auto tilep = [&](int buf, int t) -> __nv_bfloat16* {
        return sm + ((size_t)(buf * 4 + t)) * (128 * kPAD);
    };
    unsigned smBase = smem_u32(sm);
    auto tileu = [&](int buf, int t) -> unsigned {
        return smBase + (unsigned)((buf * 4 + t) * (128 * kPAD) * 2);
    };

    auto loadChunk = [&](int c, int buf) {
        int k0 = c * 32;
        #pragma unroll
        for (int i = 0; i < 2; i++) {
            int idx = tid + 256 * i;
            int r   = idx >> 2;
            int u   = idx & 3;
            uint4 vh = make_uint4(0, 0, 0, 0), vl = make_uint4(0, 0, 0, 0);
            int gr = row0 + r;
            if (gr < M) {
                size_t ar;
                if (GATHER_A)   ar = (size_t)rowTok[r];
                else if (DENSE) ar = (size_t)gr;
                else            ar = (size_t)g * cap + gr;
                vh = *(const uint4*)(Ah + ar * K + k0 + u * 8);
                vl = *(const uint4*)(Al + ar * K + k0 + u * 8);
            }
            *(uint4*)(tilep(buf, 0) + r * kPAD + u * 8) = vh;
            *(uint4*)(tilep(buf, 1) + r * kPAD + u * 8) = vl;
            size_t br = (size_t)e * N + col0 + r;
            uint4 bh = *(const uint4*)(Bh + br * K + k0 + u * 8);
            uint4 bl = *(const uint4*)(Bl + br * K + k0 + u * 8);
            *(uint4*)(tilep(buf, 2) + r * kPAD + u * 8) = bh;
            *(uint4*)(tilep(buf, 3) + r * kPAD + u * 8) = bl;
        }
    };

    float acc[4][4][4];
    #pragma unroll
    for (int mf = 0; mf < 4; mf++)
        #pragma unroll
        for (int nf = 0; nf < 4; nf++)
            #pragma unroll
            for (int q = 0; q < 4; q++) acc[mf][nf][q] = 0.f;

    int warpM = (wid & 1) * 64;
    int warpN = (wid >> 1) * 32;
    int T = K >> 5;

    // ldmatrix per-lane row/k offsets
    int rowA = (lane & 7) + ((lane >> 3) & 1) * 8;   // A: m0 rows0-7,k0; m1 rows8-15,k0; m2/m3 k+8
    int kA   = ((lane >> 4) & 1) * 8;
    int rowB = (lane & 7) + ((lane >> 4) & 1) * 8;   // B: m0 n0-7,k0; m1 n0-7,k8; m2/m3 n8-15
    int kB   = ((lane >> 3) & 1) * 8;

    loadChunk(0, 0);
    __syncthreads();

    for (int c = 0; c < T; c++) {
        int buf = c & 1;
        if (c + 1 < T) loadChunk(c + 1, buf ^ 1);

        unsigned uAh = tileu(buf, 0), uAl = tileu(buf, 1);
        unsigned uBh = tileu(buf, 2), uBl = tileu(buf, 3);

        #pragma unroll
        for (int ks = 0; ks < 2; ks++) {
            int k0 = ks * 16;
            unsigned ah[4][4], al[4][4], bh[2][4], bl[2][4];
            #pragma unroll
            for (int mf = 0; mf < 4; mf++) {
                unsigned off = (unsigned)(((warpM + mf * 16 + rowA) * kPAD + k0 + kA) * 2);
                ldmx4(ah[mf], uAh + off);
                ldmx4(al[mf], uAl + off);
            }
            #pragma unroll
            for (int np = 0; np < 2; np++) {
                unsigned off = (unsigned)(((warpN + np * 16 + rowB) * kPAD + k0 + kB) * 2);
                ldmx4(bh[np], uBh + off);
                ldmx4(bl[np], uBl + off);
            }
            #pragma unroll
            for (int mf = 0; mf < 4; mf++)
                #pragma unroll
                for (int nf = 0; nf < 4; nf++) {
                    const unsigned* bhf = &bh[nf >> 1][(nf & 1) * 2];
                    const unsigned* blf = &bl[nf >> 1][(nf & 1) * 2];
                    mma16816(acc[mf][nf], ah[mf], bhf);
                    mma16816(acc[mf][nf], ah[mf], blf);
                    mma16816(acc[mf][nf], al[mf], bhf);
                }
        }
        __syncthreads();
    }

    // ---- epilogue ----
    const float* bg = bias + (size_t)e * N;
    #pragma unroll
    for (int mf = 0; mf < 4; mf++) {
        #pragma unroll
        for (int half = 0; half < 2; half++) {
            int rloc = warpM + mf * 16 + gq + half * 8;
            int gr   = row0 + rloc;
            if (gr >= M) continue;
            #pragma unroll
            for (int nf = 0; nf < 4; nf++) {
                int ncol = col0 + warpN + nf * 8 + 2 * tq;
                float v0 = acc[mf][nf][half * 2 + 0] + bg[ncol];
                float v1 = acc[mf][nf][half * 2 + 1] + bg[ncol + 1];
                if (OMODE == 0) {
                    size_t orow = DENSE ? (size_t)gr : (size_t)g * cap + gr;
                    float2 v; v.x = v0 * alpha; v.y = v1 * alpha;
                    *(float2*)(outF + orow * N + ncol) = v;
                } else if (OMODE == 1) {
                    v0 = fmaxf(v0, 0.f);
                    v1 = fmaxf(v1, 0.f);
                    __nv_bfloat16 h0 = __float2bfloat16(v0);
                    __nv_bfloat16 h1 = __float2bfloat16(v1);
                    __nv_bfloat162 H; H.x = h0; H.y = h1;
                    __nv_bfloat162 L;
                    L.x = __float2bfloat16(v0 - __bfloat162float(h0));
                    L.y = __float2bfloat16(v1 - __bfloat162float(h1));
                    size_t off = ((size_t)g * cap + gr) * N + ncol;
                    *(__nv_bfloat162*)(outH + off) = H;
                    *(__nv_bfloat162*)(outL + off) = L;
                } else {
                    int tok = rowTok[rloc];
                    float gt = rowG[rloc];
                    float* dst = outF + (size_t)tok * N + ncol;
                    atomicAdd(dst,     gt * v0);
                    atomicAdd(dst + 1, gt * v1);
                }
            }
        }
    }
}

// ---------------- routed attention core (QT=32, 512 threads, f32x2) ----------------
namespace {
constexpr int QT    = 32;
constexpr int KT    = 16;
constexpr int KPADF = 132;
constexpr int OFF_QS   = 0;                       // 32*128
constexpr int OFF_RELQ = OFF_QS + QT * kHD;       // 32*132
constexpr int OFF_KS   = OFF_RELQ + QT * KPADF;   // 16*132
constexpr int OFF_VS   = OFF_KS + KT * KPADF;     // 16*132
constexpr int OFF_PS   = OFF_VS + KT * KPADF;     // 32*16
constexpr int OFF_QPOS = OFF_PS + QT * KT;        // 32 ints
constexpr int ATTN_SMEM_BYTES = (OFF_QPOS + QT) * 4;
}

__global__ __launch_bounds__(512)
void attn_kernel(const float* __restrict__ rel_table,
                 __nv_bfloat16* __restrict__ ctxh,
                 __nv_bfloat16* __restrict__ ctxl)
{
    extern __shared__ __align__(16) float smf[];
    float* qs   = smf + OFF_QS;
    float* relq = smf + OFF_RELQ;
    float* ks   = smf + OFF_KS;
    float* vs   = smf + OFF_VS;
    float* ps   = smf + OFF_PS;
    int*   qpos = (int*)(smf + OFF_QPOS);

    int g  = blockIdx.x;            // b*EA + e
    int b  = g / kEA;
    int qt = blockIdx.y;
    int cnt  = g_cntA[g];
    int base = qt * QT;
    if (base >= cnt) return;

    int tid = threadIdx.x;

    for (int i = tid; i < QT * kHD / 4; i += 512) {
        int qi = i >> 5, h4 = i & 31;
        float4 v = make_float4(0.f, 0.f, 0.f, 0.f);
        if (base + qi < cnt)
            v = ((const float4*)&g_qg[((size_t)g * kS + base + qi) * kHD])[h4];
        ((float4*)(qs + qi * kHD))[h4] = v;
    }
    if (tid < QT) {
        int t = (base + tid < cnt) ? g_listA[g * kS + base + tid] : 0;
        qpos[tid] = t & (kS - 1);
    }
    __syncthreads();

    for (int idx = tid; idx < QT * kR; idx += 512) {
        int qi = idx / kR, r = idx % kR;
        const float4* q4 = (const float4*)(qs + qi * kHD);
        const float4* t4 = (const float4*)&rel_table[(size_t)r * kHD];
        float s = 0.f;
        #pragma unroll
        for (int h = 0; h < kHD / 4; h++) {
            float4 a = q4[h], c = t4[h];
            s += a.x * c.x + a.y * c.y + a.z * c.z + a.w * c.w;
        }
        relq[qi * KPADF + r] = s;
    }
    __syncthreads();

    int qi = tid >> 4;
    int li = tid & 15;
    float m = -1e30f, l = 0.f;
    ull acc2[4];
    #pragma unroll
    for (int t = 0; t < 4; t++) acc2[t] = 0ull;
    int myq = qpos[qi];
    const float4* q4 = (const float4*)(qs + qi * kHD);

    for (int c0 = 0; c0 < kS; c0 += KT) {
        for (int i = tid; i < KT * 64; i += 512) {
            int kk = i >> 6, h4 = i & 63;
            float4 v = ((const float4*)&g_kvbuf[((size_t)b * kS + c0 + kk) * 256])[h4];
            if (h4 < 32) ((float4*)(ks + kk * KPADF))[h4] = v;
            else         ((float4*)(vs + kk * KPADF))[h4 - 32] = v;
        }
        __syncthreads();

        const float4* k4 = (const float4*)(ks + li * KPADF);
        ull s2a = 0ull, s2b = 0ull;
        #pragma unroll
        for (int h = 0; h < kHD / 4; h++) {
            float4 a = q4[h], kv = k4[h];
            fma2(s2a, ((const ull*)&a)[0], ((const ull*)&kv)[0]);
            fma2(s2b, ((const ull*)&a)[1], ((const ull*)&kv)[1]);
        }
        float2 r1 = unpack2(s2a), r2 = unpack2(s2b);
        float s = r1.x + r1.y + r2.x + r2.y;
        int rel = c0 + li - myq;
        rel = min(max(rel, -kMAXP), kMAXP) + kMAXP;
        s += relq[qi * KPADF + rel];

        float cm = s;
        #pragma unroll
        for (int o = 8; o; o >>= 1) cm = fmaxf(cm, __shfl_xor_sync(~0u, cm, o));
        float mn = fmaxf(m, cm);
        float scale = __expf(m - mn);
        float p = __expf(s - mn);
        float psum = p;
        #pragma unroll
        for (int o = 8; o; o >>= 1) psum += __shfl_xor_sync(~0u, psum, o);
        l = l * scale + psum;
        m = mn;
        ps[qi * KT + li] = p;
        __syncwarp();

        ull sc2 = pack_dup(scale);
        #pragma unroll
        for (int t = 0; t < 4; t++) mul2(acc2[t], acc2[t], sc2);
        #pragma unroll
        for (int kk = 0; kk < KT; kk++) {
            ull pv = pack_dup(ps[qi * KT + kk]);
            const ull* v2 = (const ull*)(vs + kk * KPADF + li * 8);
            fma2(acc2[0], pv, v2[0]);
            fma2(acc2[1], pv, v2[1]);
            fma2(acc2[2], pv, v2[2]);
            fma2(acc2[3], pv, v2[3]);
        }
        __syncthreads();
    }

    if (base + qi < cnt) {
        float inv = 1.f / l;
        size_t off = ((size_t)g * kS + base + qi) * kHD + li * 8;
        #pragma unroll
        for (int t = 0; t < 4; t++) {
            float2 v = unpack2(acc2[t]);
            float v0 = v.x * inv, v1 = v.y * inv;
            __nv_bfloat16 h0 = __float2bfloat16(v0);
            __nv_bfloat16 h1 = __float2bfloat16(v1);
            __nv_bfloat162 H; H.x = h0; H.y = h1;
            __nv_bfloat162 L;
            L.x = __float2bfloat16(v0 - __bfloat162float(h0));
            L.y = __float2bfloat16(v1 - __bfloat162float(h1));
            *(__nv_bfloat162*)(ctxh + off + 2 * t) = H;
            *(__nv_bfloat162*)(ctxl + off + 2 * t) = L;
        }
    }
}

// ---------------- launch ----------------
extern "C" void kernel_launch(void* const* d_in, const int* in_sizes, int n_in,
                              void* d_out, int out_size)
{
    const float* src   = (const float*)d_in[0];
    const float* ln1_w = (const float*)d_in[1];
    const float* ln1_b = (const float*)d_in[2];
    const float* ln2_w = (const float*)d_in[3];
    const float* ln2_b = (const float*)d_in[4];
    const float* agw   = (const float*)d_in[5];
    const float* q_w   = (const float*)d_in[6];
    const float* q_b   = (const float*)d_in[7];
    const float* k_w   = (const float*)d_in[8];
    const float* k_b   = (const float*)d_in[9];
    const float* v_w   = (const float*)d_in[10];
    const float* v_b   = (const float*)d_in[11];
    const float* o_w   = (const float*)d_in[12];
    const float* o_b   = (const float*)d_in[13];
    const float* rel   = (const float*)d_in[14];
    const float* fgw   = (const float*)d_in[15];
    const float* w1    = (const float*)d_in[16];
    const float* b1    = (const float*)d_in[17];
    const float* w2    = (const float*)d_in[18];
    const float* b2    = (const float*)d_in[19];
    float* out = (float*)d_out;

    float *xcur, *kvb, *kvbias, *qg, *gateA, *gateF;
    int *cntA, *listA, *cntF, *listF;
    __nv_bfloat16 *xn1h, *xn1l, *xn2h, *xn2l, *ctxh, *ctxl, *hh, *hl;
    __nv_bfloat16 *w1th, *w1tl, *w2th, *w2tl, *qwth, *qwtl, *owth, *owtl, *kvth, *kvtl;
    cudaGetSymbolAddress((void**)&xcur,   g_xcur);
    cudaGetSymbolAddress((void**)&kvb,    g_kvbuf);
    cudaGetSymbolAddress((void**)&kvbias, g_kvbias);
    cudaGetSymbolAddress((void**)&qg,     g_qg);
    cudaGetSymbolAddress((void**)&gateA,  g_gateA);
    cudaGetSymbolAddress((void**)&gateF,  g_gateF);
    cudaGetSymbolAddress((void**)&cntA,   g_cntA);
    cudaGetSymbolAddress((void**)&listA,  g_listA);
    cudaGetSymbolAddress((void**)&cntF,   g_cntF);
    cudaGetSymbolAddress((void**)&listF,  g_listF);
    cudaGetSymbolAddress((void**)&xn1h,   g_xn1h);
    cudaGetSymbolAddress((void**)&xn1l,   g_xn1l);
    cudaGetSymbolAddress((void**)&xn2h,   g_xn2h);
    cudaGetSymbolAddress((void**)&xn2l,   g_xn2l);
    cudaGetSymbolAddress((void**)&ctxh,   g_ctxh);
    cudaGetSymbolAddress((void**)&ctxl,   g_ctxl);
    cudaGetSymbolAddress((void**)&hh,     g_hh);
    cudaGetSymbolAddress((void**)&hl,     g_hl);
    cudaGetSymbolAddress((void**)&w1th,   g_w1th);
    cudaGetSymbolAddress((void**)&w1tl,   g_w1tl);
    cudaGetSymbolAddress((void**)&w2th,   g_w2th);
    cudaGetSymbolAddress((void**)&w2tl,   g_w2tl);
    cudaGetSymbolAddress((void**)&qwth,   g_qwth);
    cudaGetSymbolAddress((void**)&qwtl,   g_qwtl);
    cudaGetSymbolAddress((void**)&owth,   g_owth);
    cudaGetSymbolAddress((void**)&owtl,   g_owtl);
    cudaGetSymbolAddress((void**)&kvth,   g_kvth);
    cudaGetSymbolAddress((void**)&kvtl,   g_kvtl);

    constexpr int kWmmaSmem = 2 * 4 * 128 * kPAD * 2;   // 81920
    cudaFuncSetAttribute(wmma_gemm_kernel<0, true,  false>,
                         cudaFuncAttributeMaxDynamicSharedMemorySize, kWmmaSmem);
    cudaFuncSetAttribute(wmma_gemm_kernel<0, false, true>,
                         cudaFuncAttributeMaxDynamicSharedMemorySize, kWmmaSmem);
    cudaFuncSetAttribute(wmma_gemm_kernel<1, true,  false>,
                         cudaFuncAttributeMaxDynamicSharedMemorySize, kWmmaSmem);
    cudaFuncSetAttribute(wmma_gemm_kernel<2, false, false>,
                         cudaFuncAttributeMaxDynamicSharedMemorySize, kWmmaSmem);
    cudaFuncSetAttribute(attn_kernel,
                         cudaFuncAttributeMaxDynamicSharedMemorySize, ATTN_SMEM_BYTES);

    zero_cnts_kernel<<<1, 64>>>();
    pack_kvbias_kernel<<<1, 256>>>(k_b, v_b);

    // ---- weight transposes + splits ----
    transp_split_kernel<<<dim3(kFH / 32, kD / 32, kEF), dim3(32, 8)>>>(w1, w1th, w1tl, kD, kFH);
    transp_split_kernel<<<dim3(kD / 32, kFH / 32, kEF), dim3(32, 8)>>>(w2, w2th, w2tl, kFH, kD);
    transp_split_kernel<<<dim3(kHD / 32, kD / 32, kEA), dim3(32, 8)>>>(q_w, qwth, qwtl, kD, kHD);
    transp_split_kernel<<<dim3(kD / 32, kHD / 32, kEA), dim3(32, 8)>>>(o_w, owth, owtl, kHD, kD);
    transp_split_kernel<<<dim3(kHD / 32, kD / 32, 1),  dim3(32, 8)>>>(k_w, kvth, kvtl, kD, kHD);
    transp_split_kernel<<<dim3(kHD / 32, kD / 32, 1),  dim3(32, 8)>>>(
        v_w, kvth + (size_t)128 * kD, kvtl + (size_t)128 * kD, kD, kHD);

    // ---- LN1 + attention router (emits bf16 hi/lo) ----
    ln_gate_kernel<kEA><<<kBS, 256>>>(src, ln1_w, ln1_b, agw, xn1h, xn1l,
                                      cntA, listA, gateA, kS, 1);

    // ---- fused k+v projection (dense, N=256) -> packed kv ----
    wmma_gemm_kernel<0, false, true><<<dim3(kBS / 128, 2, 1), 256, kWmmaSmem>>>(
        xn1h, xn1l, kvth, kvtl, kvbias, kvb, nullptr, nullptr,
        nullptr, nullptr, nullptr, kBS, 256, kD, 0, 1, 1.f);

    // ---- routed q projection ----
    wmma_gemm_kernel<0, true, false><<<dim3(kS / 128, 1, kB * kEA), 256, kWmmaSmem>>>(
        xn1h, xn1l, qwth, qwtl, q_b, qg, nullptr, nullptr,
        listA, gateA, cntA, 0, kHD, kD, kS, kEA, kQScale);

    // ---- attention core (emits ctx bf16 hi/lo) ----
    attn_kernel<<<dim3(kB * kEA, kS / QT), 512, ATTN_SMEM_BYTES>>>(rel, ctxh, ctxl);

    // ---- o-projection scatter into residual ----
    copy_kernel<<<512, 256>>>(src, xcur, kBS * kD);
    wmma_gemm_kernel<2, false, false><<<dim3(kS / 128, kD / 128, kB * kEA), 256, kWmmaSmem>>>(
        ctxh, ctxl, owth, owtl, o_b, xcur, nullptr, nullptr,
        listA, gateA, cntA, 0, kD, kHD, kS, kEA, 1.f);

    // ---- LN2 + FFN router (emits bf16 hi/lo) ----
    ln_gate_kernel<kEF><<<kBS, 256>>>(xcur, ln2_w, ln2_b, fgw, xn2h, xn2l,
                                      cntF, listF, gateF, kBS, 0);

    // ---- routed FFN up-proj + relu ----
    wmma_gemm_kernel<1, true, false><<<dim3(kBS / 128, kFH / 128, kEF), 256, kWmmaSmem>>>(
        xn2h, xn2l, w1th, w1tl, b1, nullptr, hh, hl,
        listF, gateF, cntF, 0, kFH, kD, kBS, kEF, 1.f);

    // ---- residual + FFN down-proj scatter ----
    copy_kernel<<<512, 256>>>(xcur, out, kBS * kD);
    wmma_gemm_kernel<2, false, false><<<dim3(kBS / 128, kD / 128, kEF), 256, kWmmaSmem>>>(
        hh, hl, w2th, w2tl, b2, out, nullptr, nullptr,
        listF, gateF, cntF, 0, kD, kFH, kBS, kEF, 1.f);
}

// round 12
// speedup vs baseline: 1.6373x; 1.0121x over previous
#include <cuda_runtime.h>
#include <cuda_bf16.h>

// ---------------- problem constants ----------------
namespace {
constexpr int kD    = 1024;
constexpr int kHD   = 128;
constexpr int kEA   = 8;
constexpr int kEF   = 16;
constexpr int kFH   = 512;
constexpr int kMAXP = 64;
constexpr int kR    = 2 * kMAXP + 1;   // 129
constexpr int kB    = 4;
constexpr int kS    = 1024;
constexpr int kBS   = kB * kS;         // 4096
constexpr float kEPS = 1e-5f;
constexpr float kQScale = 0.08838834764831845f;   // 128^-0.5
constexpr int kPAD = 40;               // smem row pitch in bf16 for wmma tiles
}

typedef unsigned long long ull;

// ---------------- device scratch (allocation-free) ----------------
__device__ float g_xcur[kBS * kD];
__device__ float g_kvbuf[(size_t)kBS * 256];              // packed [token][k(128)|v(128)]
__device__ float g_kvbias[256];
__device__ int   g_cntA [kB * kEA];
__device__ int   g_listA[kB * kEA * kS];
__device__ float g_gateA[kB * kEA * kS];
__device__ float g_qg  [(size_t)kB * kEA * kS * kHD];
__device__ int   g_cntF [kEF];
__device__ int   g_listF[kEF * kBS];
__device__ float g_gateF[kEF * kBS];
// bf16 hi/lo split activation buffers
__device__ __nv_bfloat16 g_xn1h[(size_t)kBS * kD];
__device__ __nv_bfloat16 g_xn1l[(size_t)kBS * kD];
__device__ __nv_bfloat16 g_xn2h[(size_t)kBS * kD];
__device__ __nv_bfloat16 g_xn2l[(size_t)kBS * kD];
__device__ __nv_bfloat16 g_ctxh[(size_t)kB * kEA * kS * kHD];
__device__ __nv_bfloat16 g_ctxl[(size_t)kB * kEA * kS * kHD];
__device__ __nv_bfloat16 g_hh [(size_t)kEF * kBS * kFH];
__device__ __nv_bfloat16 g_hl [(size_t)kEF * kBS * kFH];
// bf16 hi/lo transposed weights
__device__ __nv_bfloat16 g_w1th[(size_t)kEF * kFH * kD];
__device__ __nv_bfloat16 g_w1tl[(size_t)kEF * kFH * kD];
__device__ __nv_bfloat16 g_w2th[(size_t)kEF * kD * kFH];
__device__ __nv_bfloat16 g_w2tl[(size_t)kEF * kD * kFH];
__device__ __nv_bfloat16 g_qwth[(size_t)kEA * kHD * kD];
__device__ __nv_bfloat16 g_qwtl[(size_t)kEA * kHD * kD];
__device__ __nv_bfloat16 g_owth[(size_t)kEA * kD * kHD];
__device__ __nv_bfloat16 g_owtl[(size_t)kEA * kD * kHD];
__device__ __nv_bfloat16 g_kvth[(size_t)256 * kD];
__device__ __nv_bfloat16 g_kvtl[(size_t)256 * kD];

// ---------------- small utility kernels ----------------
__global__ void zero_cnts_kernel() {
    int i = threadIdx.x;
    if (i < kB * kEA) g_cntA[i] = 0;
    if (i < kEF)      g_cntF[i] = 0;
}

__global__ void pack_kvbias_kernel(const float* __restrict__ kb, const float* __restrict__ vb) {
    int i = threadIdx.x;
    g_kvbias[i] = (i < 128) ? kb[i] : vb[i - 128];
}

__global__ void copy_kernel(const float* __restrict__ in, float* __restrict__ out, int n) {
    int n4 = n >> 2;
    for (int i = blockIdx.x * blockDim.x + threadIdx.x; i < n4; i += gridDim.x * blockDim.x)
        ((float4*)out)[i] = ((const float4*)in)[i];
}

// ---------------- merged weight transpose+split (one launch) ----------------
// segments: w1(8192) w2(8192) qw(1024) ow(1024) kw(128) vw(128) -> 18688 blocks
__global__ __launch_bounds__(256)
void transp_all_kernel(const float* __restrict__ w1, const float* __restrict__ w2,
                       const float* __restrict__ qw, const float* __restrict__ ow,
                       const float* __restrict__ kw, const float* __restrict__ vw)
{
    int bid = blockIdx.x;
    const float* in; __nv_bfloat16* oh; __nv_bfloat16* ol;
    int K, N, e, r;
    if (bid < 8192)       { in = w1; oh = g_w1th; ol = g_w1tl; K = kD;  N = kFH; e = bid >> 9; r = bid & 511; }
    else if (bid < 16384) { bid -= 8192;  in = w2; oh = g_w2th; ol = g_w2tl; K = kFH; N = kD;  e = bid >> 9; r = bid & 511; }
    else if (bid < 17408) { bid -= 16384; in = qw; oh = g_qwth; ol = g_qwtl; K = kD;  N = kHD; e = bid >> 7; r = bid & 127; }
    else if (bid < 18432) { bid -= 17408; in = ow; oh = g_owth; ol = g_owtl; K = kHD; N = kD;  e = bid >> 7; r = bid & 127; }
    else if (bid < 18560) { bid -= 18432; in = kw; oh = g_kvth; ol = g_kvtl; K = kD;  N = kHD; e = 0; r = bid; }
    else                  { bid -= 18560; in = vw; oh = g_kvth + (size_t)128 * kD;
                            ol = g_kvtl + (size_t)128 * kD; K = kD; N = kHD; e = 0; r = bid; }
    int nT = N >> 5;
    int nb = (r % nT) * 32, kb = (r / nT) * 32;

    __shared__ float t[32][33];
    int tx = threadIdx.x & 31, ty = threadIdx.x >> 5;
    const float* ie = in + (size_t)e * K * N;
    for (int i = ty; i < 32; i += 8)
        t[i][tx] = ie[(size_t)(kb + i) * N + nb + tx];
    __syncthreads();
    size_t ob = (size_t)e * N * K;
    for (int j = ty; j < 32; j += 8) {
        float v = t[tx][j];
        __nv_bfloat16 h = __float2bfloat16(v);
        size_t o = ob + (size_t)(nb + j) * K + kb + tx;
        oh[o] = h;
        ol[o] = __float2bfloat16(v - __bfloat162float(h));
    }
}

// ---------------- fused LayerNorm + top-2 router, bf16 hi/lo output ----------------
template <int E>
__global__ __launch_bounds__(256)
void ln_gate_kernel(const float* __restrict__ x,
                    const float* __restrict__ w,
                    const float* __restrict__ bvec,
                    const float* __restrict__ gw,   // [D, E] row-major
                    __nv_bfloat16* __restrict__ xnh,
                    __nv_bfloat16* __restrict__ xnl,
                    int* __restrict__ cnt,
                    int* __restrict__ list,
                    float* __restrict__ gates,
                    int cap, int perBatch)
{
    __shared__ __align__(16) float xs[kD];
    __shared__ float red1[8], red2[8];
    __shared__ float logits[E];
    __shared__ float s_mu, s_rstd;

    int t    = blockIdx.x;
    int tid  = threadIdx.x;
    int lane = tid & 31, wid = tid >> 5;

    const float4* xin = (const float4*)(x + (size_t)t * kD);
    float4* xs4 = (float4*)xs;
    float s = 0.f, ss = 0.f;
    for (int i = tid; i < kD / 4; i += 256) {
        float4 v = xin[i];
        xs4[i] = v;
        s  += v.x + v.y + v.z + v.w;
        ss += v.x * v.x + v.y * v.y + v.z * v.z + v.w * v.w;
    }
    #pragma unroll
    for (int o = 16; o; o >>= 1) {
        s  += __shfl_xor_sync(~0u, s, o);
        ss += __shfl_xor_sync(~0u, ss, o);
    }
    if (lane == 0) { red1[wid] = s; red2[wid] = ss; }
    __syncthreads();
    if (tid == 0) {
        float S1 = 0.f, S2 = 0.f;
        #pragma unroll
        for (int i = 0; i < 8; i++) { S1 += red1[i]; S2 += red2[i]; }
        float mu  = S1 / kD;
        float var = S2 / kD - mu * mu;
        s_mu = mu; s_rstd = rsqrtf(var + kEPS);
    }
    __syncthreads();
    float mu = s_mu, rstd = s_rstd;
    for (int i = tid; i < kD / 2; i += 256) {
        float v0 = (xs[2 * i]     - mu) * rstd * w[2 * i]     + bvec[2 * i];
        float v1 = (xs[2 * i + 1] - mu) * rstd * w[2 * i + 1] + bvec[2 * i + 1];
        xs[2 * i] = v0; xs[2 * i + 1] = v1;
        __nv_bfloat16 h0 = __float2bfloat16(v0);
        __nv_bfloat16 h1 = __float2bfloat16(v1);
        __nv_bfloat162 H; H.x = h0; H.y = h1;
        __nv_bfloat162 L;
        L.x = __float2bfloat16(v0 - __bfloat162float(h0));
        L.y = __float2bfloat16(v1 - __bfloat162float(h1));
        ((__nv_bfloat162*)(xnh + (size_t)t * kD))[i] = H;
        ((__nv_bfloat162*)(xnl + (size_t)t * kD))[i] = L;
    }
    __syncthreads();

    for (int e = wid; e < E; e += 8) {
        float acc = 0.f;
        for (int d = lane; d < kD; d += 32) acc += xs[d] * gw[d * E + e];
        #pragma unroll
        for (int o = 16; o; o >>= 1) acc += __shfl_xor_sync(~0u, acc, o);
        if (lane == 0) logits[e] = acc;
    }
    __syncthreads();

    if (tid == 0) {
        int e0 = 0; float v0 = logits[0];
        #pragma unroll
        for (int e = 1; e < E; e++) if (logits[e] > v0) { v0 = logits[e]; e0 = e; }
        int e1 = -1; float v1 = -3.4e38f;
        #pragma unroll
        for (int e = 0; e < E; e++) {
            if (e == e0) continue;
            if (logits[e] > v1) { v1 = logits[e]; e1 = e; }
        }
        float a1  = __expf(v1 - v0);
        float inv = 1.f / (1.f + a1);
        float g0 = inv, g1 = a1 * inv;
        int bb = perBatch ? (t / kS) : 0;
        int grp0 = bb * E + e0;
        int p0 = atomicAdd(&cnt[grp0], 1);
        list[grp0 * cap + p0] = t; gates[grp0 * cap + p0] = g0;
        int grp1 = bb * E + e1;
        int p1 = atomicAdd(&cnt[grp1], 1);
        list[grp1 * cap + p1] = t; gates[grp1 * cap + p1] = g1;
    }
}

// ---------------- packed f32x2 helpers ----------------
__device__ __forceinline__ void fma2(ull& d, ull a, ull b) {
    asm("fma.rn.f32x2 %0, %1, %2, %0;" : "+l"(d) : "l"(a), "l"(b));
}
__device__ __forceinline__ void mul2(ull& d, ull a, ull b) {
    asm("mul.rn.f32x2 %0, %1, %2;" : "=l"(d) : "l"(a), "l"(b));
}
__device__ __forceinline__ ull pack_dup(float a) {
    ull r;
    asm("mov.b64 %0, {%1, %1};" : "=l"(r) : "f"(a));
    return r;
}
__device__ __forceinline__ float2 unpack2(ull v) {
    float2 r;
    asm("mov.b64 {%0, %1}, %2;" : "=f"(r.x), "=f"(r.y) : "l"(v));
    return r;
}

// ---------------- warp-MMA (HMMA bf16) + ldmatrix ----------------
__device__ __forceinline__ void mma16816(float* c, const unsigned* a, const unsigned* b) {
    asm volatile(
        "mma.sync.aligned.m16n8k16.row.col.f32.bf16.bf16.f32 "
        "{%0,%1,%2,%3}, {%4,%5,%6,%7}, {%8,%9}, {%0,%1,%2,%3};"
        : "+f"(c[0]), "+f"(c[1]), "+f"(c[2]), "+f"(c[3])
        : "r"(a[0]), "r"(a[1]), "r"(a[2]), "r"(a[3]), "r"(b[0]), "r"(b[1]));
}
__device__ __forceinline__ void ldmx4(unsigned* r, unsigned addr) {
    asm volatile("ldmatrix.sync.aligned.m8n8.x4.shared.b16 {%0,%1,%2,%3}, [%4];"
                 : "=r"(r[0]), "=r"(r[1]), "=r"(r[2]), "=r"(r[3]) : "r"(addr));
}
__device__ __forceinline__ unsigned smem_u32(const void* p) {
    unsigned a;
    asm("{ .reg .u64 t; cvta.to.shared.u64 t, %1; cvt.u32.u64 %0, t; }" : "=r"(a) : "l"(p));
    return a;
}

// ---------------- generic grouped HMMA GEMM (ldmatrix fragments) ----------------
// CTA tile 128x128, BK=32, 8 warps (2m x 4n -> 64x32 warp tiles).
// bf16 hi/lo split: acc += Ah*Bh + Ah*Bl + Al*Bh.
// OMODE 0: out f32, val=(acc+bias)*alpha; OMODE 1: relu->bf16 hi/lo; OMODE 2: gated atomic scatter
template <int OMODE, bool GATHER_A, bool DENSE>
__global__ __launch_bounds__(256)
void wmma_gemm_kernel(const __nv_bfloat16* __restrict__ Ah,
                      const __nv_bfloat16* __restrict__ Al,
                      const __nv_bfloat16* __restrict__ Bh,   // [E][N][K]
                      const __nv_bfloat16* __restrict__ Bl,
                      const float* __restrict__ bias,         // [E][N]
                      float* __restrict__ outF,
                      __nv_bfloat16* __restrict__ outH,
                      __nv_bfloat16* __restrict__ outL,
                      const int* __restrict__ list,
                      const float* __restrict__ gates,
                      const int* __restrict__ cnt,
                      int Mfixed, int N, int K, int cap, int wMod, float alpha)
{
    int g = blockIdx.z;
    int M = DENSE ? Mfixed : cnt[g];
    int e = DENSE ? 0 : (g % wMod);
    int row0 = blockIdx.x * 128;
    if (row0 >= M) return;
    int col0 = blockIdx.y * 128;

    extern __shared__ __align__(16) __nv_bfloat16 sm[];
    __shared__ int   rowTok[128];
    __shared__ float rowG[128];

    int tid  = threadIdx.x;
    int wid  = tid >> 5;
    int lane = tid & 31;
    int gq   = lane >> 2;
    int tq   = lane & 3;

    if (!DENSE && tid < 128) {
        int r = row0 + tid;
        rowTok[tid] = (r < M) ? list[(size_t)g * cap + r] : 0;
        rowG[tid]   = (r < M) ? gates[(size_t)g * cap + r] : 0.f;
    }
    __syncthreads();

    auto tilep = [&](int buf, int t) -> __nv_bfloat16* {
        return sm + ((size_t)(buf * 4 + t)) * (128 * kPAD);
    };
    unsigned smBase = smem_u32(sm);
    auto tileu = [&](int buf, int t) -> unsigned {
        return smBase + (unsigned)((buf * 4 + t) * (128 * kPAD) * 2);
    };

    auto loadChunk = [&](int c, int buf) {
        int k0 = c * 32;
        #pragma unroll
        for (int i = 0; i < 2; i++) {
            int idx = tid + 256 * i;
            int r   = idx >> 2;
            int u   = idx & 3;
            uint4 vh = make_uint4(0, 0, 0, 0), vl = make_uint4(0, 0, 0, 0);
            int gr = row0 + r;
            if (gr < M) {
                size_t ar;
                if (GATHER_A)   ar = (size_t)rowTok[r];
                else if (DENSE) ar = (size_t)gr;
                else            ar = (size_t)g * cap + gr;
                vh = *(const uint4*)(Ah + ar * K + k0 + u * 8);
                vl = *(const uint4*)(Al + ar * K + k0 + u * 8);
            }
            *(uint4*)(tilep(buf, 0) + r * kPAD + u * 8) = vh;
            *(uint4*)(tilep(buf, 1) + r * kPAD + u * 8) = vl;
            size_t br = (size_t)e * N + col0 + r;
            uint4 bh = *(const uint4*)(Bh + br * K + k0 + u * 8);
            uint4 bl = *(const uint4*)(Bl + br * K + k0 + u * 8);
            *(uint4*)(tilep(buf, 2) + r * kPAD + u * 8) = bh;
            *(uint4*)(tilep(buf, 3) + r * kPAD + u * 8) = bl;
        }
    };

    float acc[4][4][4];
    #pragma unroll
    for (int mf = 0; mf < 4; mf++)
        #pragma unroll
        for (int nf = 0; nf < 4; nf++)
            #pragma unroll
            for (int q = 0; q < 4; q++) acc[mf][nf][q] = 0.f;

    int warpM = (wid & 1) * 64;
    int warpN = (wid >> 1) * 32;
    int T = K >> 5;

    int rowA = (lane & 7) + ((lane >> 3) & 1) * 8;
    int kA   = ((lane >> 4) & 1) * 8;
    int rowB = (lane & 7) + ((lane >> 4) & 1) * 8;
    int kB   = ((lane >> 3) & 1) * 8;

    loadChunk(0, 0);
    __syncthreads();

    for (int c = 0; c < T; c++) {
        int buf = c & 1;
        if (c + 1 < T) loadChunk(c + 1, buf ^ 1);

        unsigned uAh = tileu(buf, 0), uAl = tileu(buf, 1);
        unsigned uBh = tileu(buf, 2), uBl = tileu(buf, 3);

        #pragma unroll
        for (int ks = 0; ks < 2; ks++) {
            int k0 = ks * 16;
            unsigned ah[4][4], al[4][4], bh[2][4], bl[2][4];
            #pragma unroll
            for (int mf = 0; mf < 4; mf++) {
                unsigned off = (unsigned)(((warpM + mf * 16 + rowA) * kPAD + k0 + kA) * 2);
                ldmx4(ah[mf], uAh + off);
                ldmx4(al[mf], uAl + off);
            }
            #pragma unroll
            for (int np = 0; np < 2; np++) {
                unsigned off = (unsigned)(((warpN + np * 16 + rowB) * kPAD + k0 + kB) * 2);
                ldmx4(bh[np], uBh + off);
                ldmx4(bl[np], uBl + off);
            }
            #pragma unroll
            for (int mf = 0; mf < 4; mf++)
                #pragma unroll
                for (int nf = 0; nf < 4; nf++) {
                    const unsigned* bhf = &bh[nf >> 1][(nf & 1) * 2];
                    const unsigned* blf = &bl[nf >> 1][(nf & 1) * 2];
                    mma16816(acc[mf][nf], ah[mf], bhf);
                    mma16816(acc[mf][nf], ah[mf], blf);
                    mma16816(acc[mf][nf], al[mf], bhf);
                }
        }
        __syncthreads();
    }

    // ---- epilogue ----
    const float* bg = bias + (size_t)e * N;
    #pragma unroll
    for (int mf = 0; mf < 4; mf++) {
        #pragma unroll
        for (int half = 0; half < 2; half++) {
            int rloc = warpM + mf * 16 + gq + half * 8;
            int gr   = row0 + rloc;
            if (gr >= M) continue;
            #pragma unroll
            for (int nf = 0; nf < 4; nf++) {
                int ncol = col0 + warpN + nf * 8 + 2 * tq;
                float v0 = acc[mf][nf][half * 2 + 0] + bg[ncol];
                float v1 = acc[mf][nf][half * 2 + 1] + bg[ncol + 1];
                if (OMODE == 0) {
                    size_t orow = DENSE ? (size_t)gr : (size_t)g * cap + gr;
                    float2 v; v.x = v0 * alpha; v.y = v1 * alpha;
                    *(float2*)(outF + orow * N + ncol) = v;
                } else if (OMODE == 1) {
                    v0 = fmaxf(v0, 0.f);
                    v1 = fmaxf(v1, 0.f);
                    __nv_bfloat16 h0 = __float2bfloat16(v0);
                    __nv_bfloat16 h1 = __float2bfloat16(v1);
                    __nv_bfloat162 H; H.x = h0; H.y = h1;
                    __nv_bfloat162 L;
                    L.x = __float2bfloat16(v0 - __bfloat162float(h0));
                    L.y = __float2bfloat16(v1 - __bfloat162float(h1));
                    size_t off = ((size_t)g * cap + gr) * N + ncol;
                    *(__nv_bfloat162*)(outH + off) = H;
                    *(__nv_bfloat162*)(outL + off) = L;
                } else {
                    int tok = rowTok[rloc];
                    float gt = rowG[rloc];
                    float* dst = outF + (size_t)tok * N + ncol;
                    atomicAdd(dst,     gt * v0);
                    atomicAdd(dst + 1, gt * v1);
                }
            }
        }
    }
}

// ---------------- routed attention core (QT=32, KT=64, 512 threads, f32x2) ----------------
namespace {
constexpr int QT    = 32;
constexpr int KT2   = 64;
constexpr int KPADF = 132;
constexpr int OFF_QS   = 0;                        // 32*128
constexpr int OFF_RELQ = OFF_QS + QT * kHD;        // 32*132
constexpr int OFF_KS   = OFF_RELQ + QT * KPADF;    // 64*132
constexpr int OFF_VS   = OFF_KS + KT2 * KPADF;     // 64*132
constexpr int OFF_PS   = OFF_VS + KT2 * KPADF;     // 32*64
constexpr int OFF_QPOS = OFF_PS + QT * KT2;        // 32 ints
constexpr int ATTN_SMEM_BYTES = (OFF_QPOS + QT) * 4;   // 109,184 B
}

__global__ __launch_bounds__(512)
void attn_kernel(const float* __restrict__ rel_table,
                 __nv_bfloat16* __restrict__ ctxh,
                 __nv_bfloat16* __restrict__ ctxl)
{
    extern __shared__ __align__(16) float smf[];
    float* qs   = smf + OFF_QS;
    float* relq = smf + OFF_RELQ;
    float* ks   = smf + OFF_KS;
    float* vs   = smf + OFF_VS;
    float* ps   = smf + OFF_PS;
    int*   qpos = (int*)(smf + OFF_QPOS);

    int g  = blockIdx.x;            // b*EA + e
    int b  = g / kEA;
    int qt = blockIdx.y;
    int cnt  = g_cntA[g];
    int base = qt * QT;
    if (base >= cnt) return;

    int tid = threadIdx.x;

    for (int i = tid; i < QT * kHD / 4; i += 512) {
        int qi = i >> 5, h4 = i & 31;
        float4 v = make_float4(0.f, 0.f, 0.f, 0.f);
        if (base + qi < cnt)
            v = ((const float4*)&g_qg[((size_t)g * kS + base + qi) * kHD])[h4];
        ((float4*)(qs + qi * kHD))[h4] = v;
    }
    if (tid < QT) {
        int t = (base + tid < cnt) ? g_listA[g * kS + base + tid] : 0;
        qpos[tid] = t & (kS - 1);
    }
    __syncthreads();

    for (int idx = tid; idx < QT * kR; idx += 512) {
        int qi = idx / kR, r = idx % kR;
        const float4* q4 = (const float4*)(qs + qi * kHD);
        const float4* t4 = (const float4*)&rel_table[(size_t)r * kHD];
        float s = 0.f;
        #pragma unroll
        for (int h = 0; h < kHD / 4; h++) {
            float4 a = q4[h], c = t4[h];
            s += a.x * c.x + a.y * c.y + a.z * c.z + a.w * c.w;
        }
        relq[qi * KPADF + r] = s;
    }
    __syncthreads();

    int qi = tid >> 4;
    int li = tid & 15;
    float m = -1e30f, l = 0.f;
    ull acc2[4];
    #pragma unroll
    for (int t = 0; t < 4; t++) acc2[t] = 0ull;
    int myq = qpos[qi];
    const float4* q4 = (const float4*)(qs + qi * kHD);

    for (int c0 = 0; c0 < kS; c0 += KT2) {
        // load packed kv rows: 64 tokens x 256 floats
        for (int i = tid; i < KT2 * 64; i += 512) {
            int kk = i >> 6, h4 = i & 63;
            float4 v = ((const float4*)&g_kvbuf[((size_t)b * kS + c0 + kk) * 256])[h4];
            if (h4 < 32) ((float4*)(ks + kk * KPADF))[h4] = v;
            else         ((float4*)(vs + kk * KPADF))[h4 - 32] = v;
        }
        __syncthreads();

        // scores for 4 keys per lane
        float sv[4];
        #pragma unroll
        for (int t4 = 0; t4 < 4; t4++) {
            int key = li + 16 * t4;
            const float4* k4 = (const float4*)(ks + key * KPADF);
            ull s2a = 0ull, s2b = 0ull;
            #pragma unroll
            for (int h = 0; h < kHD / 4; h++) {
                float4 a = q4[h], kv = k4[h];
                fma2(s2a, ((const ull*)&a)[0], ((const ull*)&kv)[0]);
                fma2(s2b, ((const ull*)&a)[1], ((const ull*)&kv)[1]);
            }
            float2 r1 = unpack2(s2a), r2 = unpack2(s2b);
            float s = r1.x + r1.y + r2.x + r2.y;
            int rel = c0 + key - myq;
            rel = min(max(rel, -kMAXP), kMAXP) + kMAXP;
            sv[t4] = s + relq[qi * KPADF + rel];
        }

        // online softmax within 16-lane group
        float cm = fmaxf(fmaxf(sv[0], sv[1]), fmaxf(sv[2], sv[3]));
        #pragma unroll
        for (int o = 8; o; o >>= 1) cm = fmaxf(cm, __shfl_xor_sync(~0u, cm, o));
        float mn = fmaxf(m, cm);
        float scale = __expf(m - mn);
        float p0 = __expf(sv[0] - mn), p1 = __expf(sv[1] - mn);
        float p2 = __expf(sv[2] - mn), p3 = __expf(sv[3] - mn);
        float psum = p0 + p1 + p2 + p3;
        #pragma unroll
        for (int o = 8; o; o >>= 1) psum += __shfl_xor_sync(~0u, psum, o);
        l = l * scale + psum;
        m = mn;
        ps[qi * KT2 + li]      = p0;
        ps[qi * KT2 + li + 16] = p1;
        ps[qi * KT2 + li + 32] = p2;
        ps[qi * KT2 + li + 48] = p3;
        __syncwarp();

        ull sc2 = pack_dup(scale);
        #pragma unroll
        for (int t = 0; t < 4; t++) mul2(acc2[t], acc2[t], sc2);
        #pragma unroll
        for (int kk = 0; kk < KT2; kk++) {
            ull pv = pack_dup(ps[qi * KT2 + kk]);
            const ull* v2 = (const ull*)(vs + kk * KPADF + li * 8);
            fma2(acc2[0], pv, v2[0]);
            fma2(acc2[1], pv, v2[1]);
            fma2(acc2[2], pv, v2[2]);
            fma2(acc2[3], pv, v2[3]);
        }
        __syncthreads();
    }

    if (base + qi < cnt) {
        float inv = 1.f / l;
        size_t off = ((size_t)g * kS + base + qi) * kHD + li * 8;
        #pragma unroll
        for (int t = 0; t < 4; t++) {
            float2 v = unpack2(acc2[t]);
            float v0 = v.x * inv, v1 = v.y * inv;
            __nv_bfloat16 h0 = __float2bfloat16(v0);
            __nv_bfloat16 h1 = __float2bfloat16(v1);
            __nv_bfloat162 H; H.x = h0; H.y = h1;
            __nv_bfloat162 L;
            L.x = __float2bfloat16(v0 - __bfloat162float(h0));
            L.y = __float2bfloat16(v1 - __bfloat162float(h1));
            *(__nv_bfloat162*)(ctxh + off + 2 * t) = H;
            *(__nv_bfloat162*)(ctxl + off + 2 * t) = L;
        }
    }
}

// ---------------- launch ----------------
extern "C" void kernel_launch(void* const* d_in, const int* in_sizes, int n_in,
                              void* d_out, int out_size)
{
    const float* src   = (const float*)d_in[0];
    const float* ln1_w = (const float*)d_in[1];
    const float* ln1_b = (const float*)d_in[2];
    const float* ln2_w = (const float*)d_in[3];
    const float* ln2_b = (const float*)d_in[4];
    const float* agw   = (const float*)d_in[5];
    const float* q_w   = (const float*)d_in[6];
    const float* q_b   = (const float*)d_in[7];
    const float* k_w   = (const float*)d_in[8];
    const float* k_b   = (const float*)d_in[9];
    const float* v_w   = (const float*)d_in[10];
    const float* v_b   = (const float*)d_in[11];
    const float* o_w   = (const float*)d_in[12];
    const float* o_b   = (const float*)d_in[13];
    const float* rel   = (const float*)d_in[14];
    const float* fgw   = (const float*)d_in[15];
    const float* w1    = (const float*)d_in[16];
    const float* b1    = (const float*)d_in[17];
    const float* w2    = (const float*)d_in[18];
    const float* b2    = (const float*)d_in[19];
    float* out = (float*)d_out;

    float *xcur, *kvb, *kvbias, *qg, *gateA, *gateF;
    int *cntA, *listA, *cntF, *listF;
    __nv_bfloat16 *xn1h, *xn1l, *xn2h, *xn2l, *ctxh, *ctxl, *hh, *hl;
    __nv_bfloat16 *w1th, *w1tl, *w2th, *w2tl, *qwth, *qwtl, *owth, *owtl, *kvth, *kvtl;
    cudaGetSymbolAddress((void**)&xcur,   g_xcur);
    cudaGetSymbolAddress((void**)&kvb,    g_kvbuf);
    cudaGetSymbolAddress((void**)&kvbias, g_kvbias);
    cudaGetSymbolAddress((void**)&qg,     g_qg);
    cudaGetSymbolAddress((void**)&gateA,  g_gateA);
    cudaGetSymbolAddress((void**)&gateF,  g_gateF);
    cudaGetSymbolAddress((void**)&cntA,   g_cntA);
    cudaGetSymbolAddress((void**)&listA,  g_listA);
    cudaGetSymbolAddress((void**)&cntF,   g_cntF);
    cudaGetSymbolAddress((void**)&listF,  g_listF);
    cudaGetSymbolAddress((void**)&xn1h,   g_xn1h);
    cudaGetSymbolAddress((void**)&xn1l,   g_xn1l);
    cudaGetSymbolAddress((void**)&xn2h,   g_xn2h);
    cudaGetSymbolAddress((void**)&xn2l,   g_xn2l);
    cudaGetSymbolAddress((void**)&ctxh,   g_ctxh);
    cudaGetSymbolAddress((void**)&ctxl,   g_ctxl);
    cudaGetSymbolAddress((void**)&hh,     g_hh);
    cudaGetSymbolAddress((void**)&hl,     g_hl);
    cudaGetSymbolAddress((void**)&w1th,   g_w1th);
    cudaGetSymbolAddress((void**)&w1tl,   g_w1tl);
    cudaGetSymbolAddress((void**)&w2th,   g_w2th);
    cudaGetSymbolAddress((void**)&w2tl,   g_w2tl);
    cudaGetSymbolAddress((void**)&qwth,   g_qwth);
    cudaGetSymbolAddress((void**)&qwtl,   g_qwtl);
    cudaGetSymbolAddress((void**)&owth,   g_owth);
    cudaGetSymbolAddress((void**)&owtl,   g_owtl);
    cudaGetSymbolAddress((void**)&kvth,   g_kvth);
    cudaGetSymbolAddress((void**)&kvtl,   g_kvtl);

    constexpr int kWmmaSmem = 2 * 4 * 128 * kPAD * 2;   // 81920
    cudaFuncSetAttribute(wmma_gemm_kernel<0, true,  false>,
                         cudaFuncAttributeMaxDynamicSharedMemorySize, kWmmaSmem);
    cudaFuncSetAttribute(wmma_gemm_kernel<0, false, true>,
                         cudaFuncAttributeMaxDynamicSharedMemorySize, kWmmaSmem);
    cudaFuncSetAttribute(wmma_gemm_kernel<1, true,  false>,
                         cudaFuncAttributeMaxDynamicSharedMemorySize, kWmmaSmem);
    cudaFuncSetAttribute(wmma_gemm_kernel<2, false, false>,
                         cudaFuncAttributeMaxDynamicSharedMemorySize, kWmmaSmem);
    cudaFuncSetAttribute(attn_kernel,
                         cudaFuncAttributeMaxDynamicSharedMemorySize, ATTN_SMEM_BYTES);

    zero_cnts_kernel<<<1, 64>>>();
    pack_kvbias_kernel<<<1, 256>>>(k_b, v_b);

    // ---- all weight transposes + splits in ONE launch ----
    transp_all_kernel<<<18688, 256>>>(w1, w2, q_w, o_w, k_w, v_w);

    // ---- LN1 + attention router (emits bf16 hi/lo) ----
    ln_gate_kernel<kEA><<<kBS, 256>>>(src, ln1_w, ln1_b, agw, xn1h, xn1l,
                                      cntA, listA, gateA, kS, 1);

    // ---- fused k+v projection (dense, N=256) -> packed kv ----
    wmma_gemm_kernel<0, false, true><<<dim3(kBS / 128, 2, 1), 256, kWmmaSmem>>>(
        xn1h, xn1l, kvth, kvtl, kvbias, kvb, nullptr, nullptr,
        nullptr, nullptr, nullptr, kBS, 256, kD, 0, 1, 1.f);

    // ---- routed q projection (launch #6 -> ncu capture target) ----
    wmma_gemm_kernel<0, true, false><<<dim3(kS / 128, 1, kB * kEA), 256, kWmmaSmem>>>(
        xn1h, xn1l, qwth, qwtl, q_b, qg, nullptr, nullptr,
        listA, gateA, cntA, 0, kHD, kD, kS, kEA, kQScale);

    // ---- attention core (emits ctx bf16 hi/lo) ----
    attn_kernel<<<dim3(kB * kEA, kS / QT), 512, ATTN_SMEM_BYTES>>>(rel, ctxh, ctxl);

    // ---- o-projection scatter into residual ----
    copy_kernel<<<512, 256>>>(src, xcur, kBS * kD);
    wmma_gemm_kernel<2, false, false><<<dim3(kS / 128, kD / 128, kB * kEA), 256, kWmmaSmem>>>(
        ctxh, ctxl, owth, owtl, o_b, xcur, nullptr, nullptr,
        listA, gateA, cntA, 0, kD, kHD, kS, kEA, 1.f);

    // ---- LN2 + FFN router (emits bf16 hi/lo) ----
    ln_gate_kernel<kEF><<<kBS, 256>>>(xcur, ln2_w, ln2_b, fgw, xn2h, xn2l,
                                      cntF, listF, gateF, kBS, 0);

    // ---- routed FFN up-proj + relu ----
    wmma_gemm_kernel<1, true, false><<<dim3(kBS / 128, kFH / 128, kEF), 256, kWmmaSmem>>>(
        xn2h, xn2l, w1th, w1tl, b1, nullptr, hh, hl,
        listF, gateF, cntF, 0, kFH, kD, kBS, kEF, 1.f);

    // ---- residual + FFN down-proj scatter ----
    copy_kernel<<<512, 256>>>(xcur, out, kBS * kD);
    wmma_gemm_kernel<2, false, false><<<dim3(kBS / 128, kD / 128, kEF), 256, kWmmaSmem>>>(
        hh, hl, w2th, w2tl, b2, out, nullptr, nullptr,
        listF, gateF, cntF, 0, kD, kFH, kBS, kEF, 1.f);
}

// round 13
// speedup vs baseline: 1.8004x; 1.0996x over previous
#include <cuda_runtime.h>
#include <cuda_bf16.h>

// ---------------- problem constants ----------------
namespace {
constexpr int kD    = 1024;
constexpr int kHD   = 128;
constexpr int kEA   = 8;
constexpr int kEF   = 16;
constexpr int kFH   = 512;
constexpr int kMAXP = 64;
constexpr int kR    = 2 * kMAXP + 1;   // 129
constexpr int kB    = 4;
constexpr int kS    = 1024;
constexpr int kBS   = kB * kS;         // 4096
constexpr float kEPS = 1e-5f;
constexpr float kQScale = 0.08838834764831845f;   // 128^-0.5
constexpr int kPAD = 40;               // smem row pitch in bf16 for wmma tiles
}

typedef unsigned long long ull;

// ---------------- device scratch (allocation-free) ----------------
__device__ float g_xcur[kBS * kD];
__device__ float g_kvbuf[(size_t)kBS * 256];              // packed [token][k(128)|v(128)]
__device__ float g_kvbias[256];
__device__ int   g_cntA [kB * kEA];
__device__ int   g_listA[kB * kEA * kS];
__device__ float g_gateA[kB * kEA * kS];
__device__ float g_qg  [(size_t)kB * kEA * kS * kHD];
__device__ int   g_cntF [kEF];
__device__ int   g_listF[kEF * kBS];
__device__ float g_gateF[kEF * kBS];
// bf16 hi/lo split activation buffers
__device__ __nv_bfloat16 g_xn1h[(size_t)kBS * kD];
__device__ __nv_bfloat16 g_xn1l[(size_t)kBS * kD];
__device__ __nv_bfloat16 g_xn2h[(size_t)kBS * kD];
__device__ __nv_bfloat16 g_xn2l[(size_t)kBS * kD];
__device__ __nv_bfloat16 g_ctxh[(size_t)kB * kEA * kS * kHD];
__device__ __nv_bfloat16 g_ctxl[(size_t)kB * kEA * kS * kHD];
__device__ __nv_bfloat16 g_hh [(size_t)kEF * kBS * kFH];
__device__ __nv_bfloat16 g_hl [(size_t)kEF * kBS * kFH];
// bf16 hi/lo transposed weights
__device__ __nv_bfloat16 g_w1th[(size_t)kEF * kFH * kD];
__device__ __nv_bfloat16 g_w1tl[(size_t)kEF * kFH * kD];
__device__ __nv_bfloat16 g_w2th[(size_t)kEF * kD * kFH];
__device__ __nv_bfloat16 g_w2tl[(size_t)kEF * kD * kFH];
__device__ __nv_bfloat16 g_qwth[(size_t)kEA * kHD * kD];
__device__ __nv_bfloat16 g_qwtl[(size_t)kEA * kHD * kD];
__device__ __nv_bfloat16 g_owth[(size_t)kEA * kD * kHD];
__device__ __nv_bfloat16 g_owtl[(size_t)kEA * kD * kHD];
__device__ __nv_bfloat16 g_kvth[(size_t)256 * kD];
__device__ __nv_bfloat16 g_kvtl[(size_t)256 * kD];

// ---------------- small utility kernels ----------------
__global__ void zero_cnts_kernel() {
    int i = threadIdx.x;
    if (i < kB * kEA) g_cntA[i] = 0;
    if (i < kEF)      g_cntF[i] = 0;
}

__global__ void pack_kvbias_kernel(const float* __restrict__ kb, const float* __restrict__ vb) {
    int i = threadIdx.x;
    g_kvbias[i] = (i < 128) ? kb[i] : vb[i - 128];
}

// ---------------- merged weight transpose+split (one launch) ----------------
__global__ __launch_bounds__(256)
void transp_all_kernel(const float* __restrict__ w1, const float* __restrict__ w2,
                       const float* __restrict__ qw, const float* __restrict__ ow,
                       const float* __restrict__ kw, const float* __restrict__ vw)
{
    int bid = blockIdx.x;
    const float* in; __nv_bfloat16* oh; __nv_bfloat16* ol;
    int K, N, e, r;
    if (bid < 8192)       { in = w1; oh = g_w1th; ol = g_w1tl; K = kD;  N = kFH; e = bid >> 9; r = bid & 511; }
    else if (bid < 16384) { bid -= 8192;  in = w2; oh = g_w2th; ol = g_w2tl; K = kFH; N = kD;  e = bid >> 9; r = bid & 511; }
    else if (bid < 17408) { bid -= 16384; in = qw; oh = g_qwth; ol = g_qwtl; K = kD;  N = kHD; e = bid >> 7; r = bid & 127; }
    else if (bid < 18432) { bid -= 17408; in = ow; oh = g_owth; ol = g_owtl; K = kHD; N = kD;  e = bid >> 7; r = bid & 127; }
    else if (bid < 18560) { bid -= 18432; in = kw; oh = g_kvth; ol = g_kvtl; K = kD;  N = kHD; e = 0; r = bid; }
    else                  { bid -= 18560; in = vw; oh = g_kvth + (size_t)128 * kD;
                            ol = g_kvtl + (size_t)128 * kD; K = kD; N = kHD; e = 0; r = bid; }
    int nT = N >> 5;
    int nb = (r % nT) * 32, kb = (r / nT) * 32;

    __shared__ float t[32][33];
    int tx = threadIdx.x & 31, ty = threadIdx.x >> 5;
    const float* ie = in + (size_t)e * K * N;
    for (int i = ty; i < 32; i += 8)
        t[i][tx] = ie[(size_t)(kb + i) * N + nb + tx];
    __syncthreads();
    size_t ob = (size_t)e * N * K;
    for (int j = ty; j < 32; j += 8) {
        float v = t[tx][j];
        __nv_bfloat16 h = __float2bfloat16(v);
        size_t o = ob + (size_t)(nb + j) * K + kb + tx;
        oh[o] = h;
        ol[o] = __float2bfloat16(v - __bfloat162float(h));
    }
}

// ---------------- fused LayerNorm + residual-copy + top-2 router ----------------
// Router logits: thread owns rows d = tid + 256j, gw row loads fully coalesced.
template <int E>
__global__ __launch_bounds__(256)
void ln_gate_kernel(const float* __restrict__ x,
                    const float* __restrict__ w,
                    const float* __restrict__ bvec,
                    const float* __restrict__ gw,   // [D, E] row-major
                    __nv_bfloat16* __restrict__ xnh,
                    __nv_bfloat16* __restrict__ xnl,
                    float* __restrict__ resid,      // copy of x (residual base), may be null
                    int* __restrict__ cnt,
                    int* __restrict__ list,
                    float* __restrict__ gates,
                    int cap, int perBatch)
{
    __shared__ __align__(16) float xs[kD];
    __shared__ float red1[8], red2[8];
    __shared__ float lred[8][E];
    __shared__ float s_mu, s_rstd;

    int t    = blockIdx.x;
    int tid  = threadIdx.x;
    int lane = tid & 31, wid = tid >> 5;

    const float4* xin = (const float4*)(x + (size_t)t * kD);
    float4* xs4 = (float4*)xs;
    float4* rout = resid ? (float4*)(resid + (size_t)t * kD) : nullptr;
    float s = 0.f, ss = 0.f;
    for (int i = tid; i < kD / 4; i += 256) {
        float4 v = xin[i];
        xs4[i] = v;
        if (rout) rout[i] = v;
        s  += v.x + v.y + v.z + v.w;
        ss += v.x * v.x + v.y * v.y + v.z * v.z + v.w * v.w;
    }
    #pragma unroll
    for (int o = 16; o; o >>= 1) {
        s  += __shfl_xor_sync(~0u, s, o);
        ss += __shfl_xor_sync(~0u, ss, o);
    }
    if (lane == 0) { red1[wid] = s; red2[wid] = ss; }
    __syncthreads();
    if (tid == 0) {
        float S1 = 0.f, S2 = 0.f;
        #pragma unroll
        for (int i = 0; i < 8; i++) { S1 += red1[i]; S2 += red2[i]; }
        float mu  = S1 / kD;
        float var = S2 / kD - mu * mu;
        s_mu = mu; s_rstd = rsqrtf(var + kEPS);
    }
    __syncthreads();
    float mu = s_mu, rstd = s_rstd;
    for (int i = tid; i < kD / 2; i += 256) {
        float v0 = (xs[2 * i]     - mu) * rstd * w[2 * i]     + bvec[2 * i];
        float v1 = (xs[2 * i + 1] - mu) * rstd * w[2 * i + 1] + bvec[2 * i + 1];
        xs[2 * i] = v0; xs[2 * i + 1] = v1;
        __nv_bfloat16 h0 = __float2bfloat16(v0);
        __nv_bfloat16 h1 = __float2bfloat16(v1);
        __nv_bfloat162 H; H.x = h0; H.y = h1;
        __nv_bfloat162 L;
        L.x = __float2bfloat16(v0 - __bfloat162float(h0));
        L.y = __float2bfloat16(v1 - __bfloat162float(h1));
        ((__nv_bfloat162*)(xnh + (size_t)t * kD))[i] = H;
        ((__nv_bfloat162*)(xnl + (size_t)t * kD))[i] = L;
    }
    __syncthreads();

    // ---- router logits: coalesced gw rows, register accumulators ----
    float accE[E];
    #pragma unroll
    for (int e = 0; e < E; e++) accE[e] = 0.f;
    #pragma unroll
    for (int j = 0; j < 4; j++) {
        int d = tid + 256 * j;
        float xv = xs[d];
        const float4* gp = (const float4*)(gw + (size_t)d * E);
        #pragma unroll
        for (int q = 0; q < E / 4; q++) {
            float4 gv = gp[q];
            accE[4 * q + 0] += xv * gv.x;
            accE[4 * q + 1] += xv * gv.y;
            accE[4 * q + 2] += xv * gv.z;
            accE[4 * q + 3] += xv * gv.w;
        }
    }
    #pragma unroll
    for (int e = 0; e < E; e++)
        #pragma unroll
        for (int o = 16; o; o >>= 1) accE[e] += __shfl_xor_sync(~0u, accE[e], o);
    if (lane == 0) {
        #pragma unroll
        for (int e = 0; e < E; e++) lred[wid][e] = accE[e];
    }
    __syncthreads();

    if (tid == 0) {
        float logits[E];
        #pragma unroll
        for (int e = 0; e < E; e++) {
            float a = 0.f;
            #pragma unroll
            for (int i = 0; i < 8; i++) a += lred[i][e];
            logits[e] = a;
        }
        int e0 = 0; float v0 = logits[0];
        #pragma unroll
        for (int e = 1; e < E; e++) if (logits[e] > v0) { v0 = logits[e]; e0 = e; }
        int e1 = -1; float v1 = -3.4e38f;
        #pragma unroll
        for (int e = 0; e < E; e++) {
            if (e == e0) continue;
            if (logits[e] > v1) { v1 = logits[e]; e1 = e; }
        }
        float a1  = __expf(v1 - v0);
        float inv = 1.f / (1.f + a1);
        float g0 = inv, g1 = a1 * inv;
        int bb = perBatch ? (t / kS) : 0;
        int grp0 = bb * E + e0;
        int p0 = atomicAdd(&cnt[grp0], 1);
        list[grp0 * cap + p0] = t; gates[grp0 * cap + p0] = g0;
        int grp1 = bb * E + e1;
        int p1 = atomicAdd(&cnt[grp1], 1);
        list[grp1 * cap + p1] = t; gates[grp1 * cap + p1] = g1;
    }
}

// ---------------- packed f32x2 helpers ----------------
__device__ __forceinline__ void fma2(ull& d, ull a, ull b) {
    asm("fma.rn.f32x2 %0, %1, %2, %0;" : "+l"(d) : "l"(a), "l"(b));
}
__device__ __forceinline__ void mul2(ull& d, ull a, ull b) {
    asm("mul.rn.f32x2 %0, %1, %2;" : "=l"(d) : "l"(a), "l"(b));
}
__device__ __forceinline__ ull pack_dup(float a) {
    ull r;
    asm("mov.b64 %0, {%1, %1};" : "=l"(r) : "f"(a));
    return r;
}
__device__ __forceinline__ float2 unpack2(ull v) {
    float2 r;
    asm("mov.b64 {%0, %1}, %2;" : "=f"(r.x), "=f"(r.y) : "l"(v));
    return r;
}

// ---------------- warp-MMA (HMMA bf16) + ldmatrix ----------------
__device__ __forceinline__ void mma16816(float* c, const unsigned* a, const unsigned* b) {
    asm volatile(
        "mma.sync.aligned.m16n8k16.row.col.f32.bf16.bf16.f32 "
        "{%0,%1,%2,%3}, {%4,%5,%6,%7}, {%8,%9}, {%0,%1,%2,%3};"
        : "+f"(c[0]), "+f"(c[1]), "+f"(c[2]), "+f"(c[3])
        : "r"(a[0]), "r"(a[1]), "r"(a[2]), "r"(a[3]), "r"(b[0]), "r"(b[1]));
}
__device__ __forceinline__ void ldmx4(unsigned* r, unsigned addr) {
    asm volatile("ldmatrix.sync.aligned.m8n8.x4.shared.b16 {%0,%1,%2,%3}, [%4];"
                 : "=r"(r[0]), "=r"(r[1]), "=r"(r[2]), "=r"(r[3]) : "r"(addr));
}
__device__ __forceinline__ unsigned smem_u32(const void* p) {
    unsigned a;
    asm("{ .reg .u64 t; cvta.to.shared.u64 t, %1; cvt.u32.u64 %0, t; }" : "=r"(a) : "l"(p));
    return a;
}

// ---------------- generic grouped HMMA GEMM (ldmatrix fragments) ----------------
template <int OMODE, bool GATHER_A, bool DENSE>
__global__ __launch_bounds__(256)
void wmma_gemm_kernel(const __nv_bfloat16* __restrict__ Ah,
                      const __nv_bfloat16* __restrict__ Al,
                      const __nv_bfloat16* __restrict__ Bh,   // [E][N][K]
                      const __nv_bfloat16* __restrict__ Bl,
                      const float* __restrict__ bias,         // [E][N]
                      float* __restrict__ outF,
                      __nv_bfloat16* __restrict__ outH,
                      __nv_bfloat16* __restrict__ outL,
                      const int* __restrict__ list,
                      const float* __restrict__ gates,
                      const int* __restrict__ cnt,
                      int Mfixed, int N, int K, int cap, int wMod, float alpha)
{
    int g = blockIdx.z;
    int M = DENSE ? Mfixed : cnt[g];
    int e = DENSE ? 0 : (g % wMod);
    int row0 = blockIdx.x * 128;
    if (row0 >= M) return;
    int col0 = blockIdx.y * 128;

    extern __shared__ __align__(16) __nv_bfloat16 sm[];
    __shared__ int   rowTok[128];
    __shared__ float rowG[128];

    int tid  = threadIdx.x;
    int wid  = tid >> 5;
    int lane = tid & 31;
    int gq   = lane >> 2;
    int tq   = lane & 3;

    if (!DENSE && tid < 128) {
        int r = row0 + tid;
        rowTok[tid] = (r < M) ? list[(size_t)g * cap + r] : 0;
        rowG[tid]   = (r < M) ? gates[(size_t)g * cap + r] : 0.f;
    }
    __syncthreads();

    auto tilep = [&](int buf, int t) -> __nv_bfloat16* {
        return sm + ((size_t)(buf * 4 + t)) * (128 * kPAD);
    };
    unsigned smBase = smem_u32(sm);
    auto tileu = [&](int buf, int t) -> unsigned {
        return smBase + (unsigned)((buf * 4 + t) * (128 * kPAD) * 2);
    };

    auto loadChunk = [&](int c, int buf) {
        int k0 = c * 32;
        #pragma unroll
        for (int i = 0; i < 2; i++) {
            int idx = tid + 256 * i;
            int r   = idx >> 2;
            int u   = idx & 3;
            uint4 vh = make_uint4(0, 0, 0, 0), vl = make_uint4(0, 0, 0, 0);
            int gr = row0 + r;
            if (gr < M) {
                size_t ar;
                if (GATHER_A)   ar = (size_t)rowTok[r];
                else if (DENSE) ar = (size_t)gr;
                else            ar = (size_t)g * cap + gr;
                vh = *(const uint4*)(Ah + ar * K + k0 + u * 8);
                vl = *(const uint4*)(Al + ar * K + k0 + u * 8);
            }
            *(uint4*)(tilep(buf, 0) + r * kPAD + u * 8) = vh;
            *(uint4*)(tilep(buf, 1) + r * kPAD + u * 8) = vl;
            size_t br = (size_t)e * N + col0 + r;
            uint4 bh = *(const uint4*)(Bh + br * K + k0 + u * 8);
            uint4 bl = *(const uint4*)(Bl + br * K + k0 + u * 8);
            *(uint4*)(tilep(buf, 2) + r * kPAD + u * 8) = bh;
            *(uint4*)(tilep(buf, 3) + r * kPAD + u * 8) = bl;
        }
    };

    float acc[4][4][4];
    #pragma unroll
    for (int mf = 0; mf < 4; mf++)
        #pragma unroll
        for (int nf = 0; nf < 4; nf++)
            #pragma unroll
            for (int q = 0; q < 4; q++) acc[mf][nf][q] = 0.f;

    int warpM = (wid & 1) * 64;
    int warpN = (wid >> 1) * 32;
    int T = K >> 5;

    int rowA = (lane & 7) + ((lane >> 3) & 1) * 8;
    int kA   = ((lane >> 4) & 1) * 8;
    int rowB = (lane & 7) + ((lane >> 4) & 1) * 8;
    int kB   = ((lane >> 3) & 1) * 8;

    loadChunk(0, 0);
    __syncthreads();

    for (int c = 0; c < T; c++) {
        int buf = c & 1;
        if (c + 1 < T) loadChunk(c + 1, buf ^ 1);

        unsigned uAh = tileu(buf, 0), uAl = tileu(buf, 1);
        unsigned uBh = tileu(buf, 2), uBl = tileu(buf, 3);

        #pragma unroll
        for (int ks = 0; ks < 2; ks++) {
            int k0 = ks * 16;
            unsigned ah[4][4], al[4][4], bh[2][4], bl[2][4];
            #pragma unroll
            for (int mf = 0; mf < 4; mf++) {
                unsigned off = (unsigned)(((warpM + mf * 16 + rowA) * kPAD + k0 + kA) * 2);
                ldmx4(ah[mf], uAh + off);
                ldmx4(al[mf], uAl + off);
            }
            #pragma unroll
            for (int np = 0; np < 2; np++) {
                unsigned off = (unsigned)(((warpN + np * 16 + rowB) * kPAD + k0 + kB) * 2);
                ldmx4(bh[np], uBh + off);
                ldmx4(bl[np], uBl + off);
            }
            #pragma unroll
            for (int mf = 0; mf < 4; mf++)
                #pragma unroll
                for (int nf = 0; nf < 4; nf++) {
                    const unsigned* bhf = &bh[nf >> 1][(nf & 1) * 2];
                    const unsigned* blf = &bl[nf >> 1][(nf & 1) * 2];
                    mma16816(acc[mf][nf], ah[mf], bhf);
                    mma16816(acc[mf][nf], ah[mf], blf);
                    mma16816(acc[mf][nf], al[mf], bhf);
                }
        }
        __syncthreads();
    }

    // ---- epilogue ----
    const float* bg = bias + (size_t)e * N;
    #pragma unroll
    for (int mf = 0; mf < 4; mf++) {
        #pragma unroll
        for (int half = 0; half < 2; half++) {
            int rloc = warpM + mf * 16 + gq + half * 8;
            int gr   = row0 + rloc;
            if (gr >= M) continue;
            #pragma unroll
            for (int nf = 0; nf < 4; nf++) {
                int ncol = col0 + warpN + nf * 8 + 2 * tq;
                float v0 = acc[mf][nf][half * 2 + 0] + bg[ncol];
                float v1 = acc[mf][nf][half * 2 + 1] + bg[ncol + 1];
                if (OMODE == 0) {
                    size_t orow = DENSE ? (size_t)gr : (size_t)g * cap + gr;
                    float2 v; v.x = v0 * alpha; v.y = v1 * alpha;
                    *(float2*)(outF + orow * N + ncol) = v;
                } else if (OMODE == 1) {
                    v0 = fmaxf(v0, 0.f);
                    v1 = fmaxf(v1, 0.f);
                    __nv_bfloat16 h0 = __float2bfloat16(v0);
                    __nv_bfloat16 h1 = __float2bfloat16(v1);
                    __nv_bfloat162 H; H.x = h0; H.y = h1;
                    __nv_bfloat162 L;
                    L.x = __float2bfloat16(v0 - __bfloat162float(h0));
                    L.y = __float2bfloat16(v1 - __bfloat162float(h1));
                    size_t off = ((size_t)g * cap + gr) * N + ncol;
                    *(__nv_bfloat162*)(outH + off) = H;
                    *(__nv_bfloat162*)(outL + off) = L;
                } else {
                    int tok = rowTok[rloc];
                    float gt = rowG[rloc];
                    float* dst = outF + (size_t)tok * N + ncol;
                    atomicAdd(dst,     gt * v0);
                    atomicAdd(dst + 1, gt * v1);
                }
            }
        }
    }
}

// ---------------- routed attention core (QT=32, KT=64, 512 threads, f32x2) ----------------
namespace {
constexpr int QT    = 32;
constexpr int KT2   = 64;
constexpr int KPADF = 132;
constexpr int OFF_QS   = 0;
constexpr int OFF_RELQ = OFF_QS + QT * kHD;
constexpr int OFF_KS   = OFF_RELQ + QT * KPADF;
constexpr int OFF_VS   = OFF_KS + KT2 * KPADF;
constexpr int OFF_PS   = OFF_VS + KT2 * KPADF;
constexpr int OFF_QPOS = OFF_PS + QT * KT2;
constexpr int ATTN_SMEM_BYTES = (OFF_QPOS + QT) * 4;   // ~109 KB
}

__global__ __launch_bounds__(512)
void attn_kernel(const float* __restrict__ rel_table,
                 __nv_bfloat16* __restrict__ ctxh,
                 __nv_bfloat16* __restrict__ ctxl)
{
    extern __shared__ __align__(16) float smf[];
    float* qs   = smf + OFF_QS;
    float* relq = smf + OFF_RELQ;
    float* ks   = smf + OFF_KS;
    float* vs   = smf + OFF_VS;
    float* ps   = smf + OFF_PS;
    int*   qpos = (int*)(smf + OFF_QPOS);

    int g  = blockIdx.x;
    int b  = g / kEA;
    int qt = blockIdx.y;
    int cnt  = g_cntA[g];
    int base = qt * QT;
    if (base >= cnt) return;

    int tid = threadIdx.x;

    for (int i = tid; i < QT * kHD / 4; i += 512) {
        int qi = i >> 5, h4 = i & 31;
        float4 v = make_float4(0.f, 0.f, 0.f, 0.f);
        if (base + qi < cnt)
            v = ((const float4*)&g_qg[((size_t)g * kS + base + qi) * kHD])[h4];
        ((float4*)(qs + qi * kHD))[h4] = v;
    }
    if (tid < QT) {
        int t = (base + tid < cnt) ? g_listA[g * kS + base + tid] : 0;
        qpos[tid] = t & (kS - 1);
    }
    __syncthreads();

    for (int idx = tid; idx < QT * kR; idx += 512) {
        int qi = idx / kR, r = idx % kR;
        const float4* q4 = (const float4*)(qs + qi * kHD);
        const float4* t4 = (const float4*)&rel_table[(size_t)r * kHD];
        float s = 0.f;
        #pragma unroll
        for (int h = 0; h < kHD / 4; h++) {
            float4 a = q4[h], c = t4[h];
            s += a.x * c.x + a.y * c.y + a.z * c.z + a.w * c.w;
        }
        relq[qi * KPADF + r] = s;
    }
    __syncthreads();

    int qi = tid >> 4;
    int li = tid & 15;
    float m = -1e30f, l = 0.f;
    ull acc2[4];
    #pragma unroll
    for (int t = 0; t < 4; t++) acc2[t] = 0ull;
    int myq = qpos[qi];
    const float4* q4 = (const float4*)(qs + qi * kHD);

    for (int c0 = 0; c0 < kS; c0 += KT2) {
        for (int i = tid; i < KT2 * 64; i += 512) {
            int kk = i >> 6, h4 = i & 63;
            float4 v = ((const float4*)&g_kvbuf[((size_t)b * kS + c0 + kk) * 256])[h4];
            if (h4 < 32) ((float4*)(ks + kk * KPADF))[h4] = v;
            else         ((float4*)(vs + kk * KPADF))[h4 - 32] = v;
        }
        __syncthreads();

        float sv[4];
        #pragma unroll
        for (int t4 = 0; t4 < 4; t4++) {
            int key = li + 16 * t4;
            const float4* k4 = (const float4*)(ks + key * KPADF);
            ull s2a = 0ull, s2b = 0ull;
            #pragma unroll
            for (int h = 0; h < kHD / 4; h++) {
                float4 a = q4[h], kv = k4[h];
                fma2(s2a, ((const ull*)&a)[0], ((const ull*)&kv)[0]);
                fma2(s2b, ((const ull*)&a)[1], ((const ull*)&kv)[1]);
            }
            float2 r1 = unpack2(s2a), r2 = unpack2(s2b);
            float s = r1.x + r1.y + r2.x + r2.y;
            int rel = c0 + key - myq;
            rel = min(max(rel, -kMAXP), kMAXP) + kMAXP;
            sv[t4] = s + relq[qi * KPADF + rel];
        }

        float cm = fmaxf(fmaxf(sv[0], sv[1]), fmaxf(sv[2], sv[3]));
        #pragma unroll
        for (int o = 8; o; o >>= 1) cm = fmaxf(cm, __shfl_xor_sync(~0u, cm, o));
        float mn = fmaxf(m, cm);
        float scale = __expf(m - mn);
        float p0 = __expf(sv[0] - mn), p1 = __expf(sv[1] - mn);
        float p2 = __expf(sv[2] - mn), p3 = __expf(sv[3] - mn);
        float psum = p0 + p1 + p2 + p3;
        #pragma unroll
        for (int o = 8; o; o >>= 1) psum += __shfl_xor_sync(~0u, psum, o);
        l = l * scale + psum;
        m = mn;
        ps[qi * KT2 + li]      = p0;
        ps[qi * KT2 + li + 16] = p1;
        ps[qi * KT2 + li + 32] = p2;
        ps[qi * KT2 + li + 48] = p3;
        __syncwarp();

        ull sc2 = pack_dup(scale);
        #pragma unroll
        for (int t = 0; t < 4; t++) mul2(acc2[t], acc2[t], sc2);
        #pragma unroll
        for (int kk = 0; kk < KT2; kk++) {
            ull pv = pack_dup(ps[qi * KT2 + kk]);
            const ull* v2 = (const ull*)(vs + kk * KPADF + li * 8);
            fma2(acc2[0], pv, v2[0]);
            fma2(acc2[1], pv, v2[1]);
            fma2(acc2[2], pv, v2[2]);
            fma2(acc2[3], pv, v2[3]);
        }
        __syncthreads();
    }

    if (base + qi < cnt) {
        float inv = 1.f / l;
        size_t off = ((size_t)g * kS + base + qi) * kHD + li * 8;
        #pragma unroll
        for (int t = 0; t < 4; t++) {
            float2 v = unpack2(acc2[t]);
            float v0 = v.x * inv, v1 = v.y * inv;
            __nv_bfloat16 h0 = __float2bfloat16(v0);
            __nv_bfloat16 h1 = __float2bfloat16(v1);
            __nv_bfloat162 H; H.x = h0; H.y = h1;
            __nv_bfloat162 L;
            L.x = __float2bfloat16(v0 - __bfloat162float(h0));
            L.y = __float2bfloat16(v1 - __bfloat162float(h1));
            *(__nv_bfloat162*)(ctxh + off + 2 * t) = H;
            *(__nv_bfloat162*)(ctxl + off + 2 * t) = L;
        }
    }
}

// ---------------- launch ----------------
extern "C" void kernel_launch(void* const* d_in, const int* in_sizes, int n_in,
                              void* d_out, int out_size)
{
    const float* src   = (const float*)d_in[0];
    const float* ln1_w = (const float*)d_in[1];
    const float* ln1_b = (const float*)d_in[2];
    const float* ln2_w = (const float*)d_in[3];
    const float* ln2_b = (const float*)d_in[4];
    const float* agw   = (const float*)d_in[5];
    const float* q_w   = (const float*)d_in[6];
    const float* q_b   = (const float*)d_in[7];
    const float* k_w   = (const float*)d_in[8];
    const float* k_b   = (const float*)d_in[9];
    const float* v_w   = (const float*)d_in[10];
    const float* v_b   = (const float*)d_in[11];
    const float* o_w   = (const float*)d_in[12];
    const float* o_b   = (const float*)d_in[13];
    const float* rel   = (const float*)d_in[14];
    const float* fgw   = (const float*)d_in[15];
    const float* w1    = (const float*)d_in[16];
    const float* b1    = (const float*)d_in[17];
    const float* w2    = (const float*)d_in[18];
    const float* b2    = (const float*)d_in[19];
    float* out = (float*)d_out;

    float *xcur, *kvb, *kvbias, *qg, *gateA, *gateF;
    int *cntA, *listA, *cntF, *listF;
    __nv_bfloat16 *xn1h, *xn1l, *xn2h, *xn2l, *ctxh, *ctxl, *hh, *hl;
    __nv_bfloat16 *w1th, *w1tl, *w2th, *w2tl, *qwth, *qwtl, *owth, *owtl, *kvth, *kvtl;
    cudaGetSymbolAddress((void**)&xcur,   g_xcur);
    cudaGetSymbolAddress((void**)&kvb,    g_kvbuf);
    cudaGetSymbolAddress((void**)&kvbias, g_kvbias);
    cudaGetSymbolAddress((void**)&qg,     g_qg);
    cudaGetSymbolAddress((void**)&gateA,  g_gateA);
    cudaGetSymbolAddress((void**)&gateF,  g_gateF);
    cudaGetSymbolAddress((void**)&cntA,   g_cntA);
    cudaGetSymbolAddress((void**)&listA,  g_listA);
    cudaGetSymbolAddress((void**)&cntF,   g_cntF);
    cudaGetSymbolAddress((void**)&listF,  g_listF);
    cudaGetSymbolAddress((void**)&xn1h,   g_xn1h);
    cudaGetSymbolAddress((void**)&xn1l,   g_xn1l);
    cudaGetSymbolAddress((void**)&xn2h,   g_xn2h);
    cudaGetSymbolAddress((void**)&xn2l,   g_xn2l);
    cudaGetSymbolAddress((void**)&ctxh,   g_ctxh);
    cudaGetSymbolAddress((void**)&ctxl,   g_ctxl);
    cudaGetSymbolAddress((void**)&hh,     g_hh);
    cudaGetSymbolAddress((void**)&hl,     g_hl);
    cudaGetSymbolAddress((void**)&w1th,   g_w1th);
    cudaGetSymbolAddress((void**)&w1tl,   g_w1tl);
    cudaGetSymbolAddress((void**)&w2th,   g_w2th);
    cudaGetSymbolAddress((void**)&w2tl,   g_w2tl);
    cudaGetSymbolAddress((void**)&qwth,   g_qwth);
    cudaGetSymbolAddress((void**)&qwtl,   g_qwtl);
    cudaGetSymbolAddress((void**)&owth,   g_owth);
    cudaGetSymbolAddress((void**)&owtl,   g_owtl);
    cudaGetSymbolAddress((void**)&kvth,   g_kvth);
    cudaGetSymbolAddress((void**)&kvtl,   g_kvtl);

    constexpr int kWmmaSmem = 2 * 4 * 128 * kPAD * 2;   // 81920
    cudaFuncSetAttribute(wmma_gemm_kernel<0, true,  false>,
                         cudaFuncAttributeMaxDynamicSharedMemorySize, kWmmaSmem);
    cudaFuncSetAttribute(wmma_gemm_kernel<0, false, true>,
                         cudaFuncAttributeMaxDynamicSharedMemorySize, kWmmaSmem);
    cudaFuncSetAttribute(wmma_gemm_kernel<1, true,  false>,
                         cudaFuncAttributeMaxDynamicSharedMemorySize, kWmmaSmem);
    cudaFuncSetAttribute(wmma_gemm_kernel<2, false, false>,
                         cudaFuncAttributeMaxDynamicSharedMemorySize, kWmmaSmem);
    cudaFuncSetAttribute(attn_kernel,
                         cudaFuncAttributeMaxDynamicSharedMemorySize, ATTN_SMEM_BYTES);

    zero_cnts_kernel<<<1, 64>>>();
    pack_kvbias_kernel<<<1, 256>>>(k_b, v_b);

    // ---- all weight transposes + splits in ONE launch ----
    transp_all_kernel<<<18688, 256>>>(w1, w2, q_w, o_w, k_w, v_w);

    // ---- LN1 + residual copy (src -> xcur) + attention router ----
    ln_gate_kernel<kEA><<<kBS, 256>>>(src, ln1_w, ln1_b, agw, xn1h, xn1l, xcur,
                                      cntA, listA, gateA, kS, 1);

    // ---- fused k+v projection (dense, N=256) -> packed kv ----
    wmma_gemm_kernel<0, false, true><<<dim3(kBS / 128, 2, 1), 256, kWmmaSmem>>>(
        xn1h, xn1l, kvth, kvtl, kvbias, kvb, nullptr, nullptr,
        nullptr, nullptr, nullptr, kBS, 256, kD, 0, 1, 1.f);

    // ---- routed q projection ----
    wmma_gemm_kernel<0, true, false><<<dim3(kS / 128, 1, kB * kEA), 256, kWmmaSmem>>>(
        xn1h, xn1l, qwth, qwtl, q_b, qg, nullptr, nullptr,
        listA, gateA, cntA, 0, kHD, kD, kS, kEA, kQScale);

    // ---- attention core (emits ctx bf16 hi/lo) ----
    attn_kernel<<<dim3(kB * kEA, kS / QT), 512, ATTN_SMEM_BYTES>>>(rel, ctxh, ctxl);

    // ---- o-projection scatter into residual (xcur pre-filled by LN1) ----
    wmma_gemm_kernel<2, false, false><<<dim3(kS / 128, kD / 128, kB * kEA), 256, kWmmaSmem>>>(
        ctxh, ctxl, owth, owtl, o_b, xcur, nullptr, nullptr,
        listA, gateA, cntA, 0, kD, kHD, kS, kEA, 1.f);

    // ---- LN2 + residual copy (xcur -> out) + FFN router ----
    ln_gate_kernel<kEF><<<kBS, 256>>>(xcur, ln2_w, ln2_b, fgw, xn2h, xn2l, out,
                                      cntF, listF, gateF, kBS, 0);

    // ---- routed FFN up-proj + relu ----
    wmma_gemm_kernel<1, true, false><<<dim3(kBS / 128, kFH / 128, kEF), 256, kWmmaSmem>>>(
        xn2h, xn2l, w1th, w1tl, b1, nullptr, hh, hl,
        listF, gateF, cntF, 0, kFH, kD, kBS, kEF, 1.f);

    // ---- FFN down-proj scatter into out (pre-filled by LN2) ----
    wmma_gemm_kernel<2, false, false><<<dim3(kBS / 128, kD / 128, kEF), 256, kWmmaSmem>>>(
        hh, hl, w2th, w2tl, b2, out, nullptr, nullptr,
        listF, gateF, cntF, 0, kD, kFH, kBS, kEF, 1.f);
}